// round 2
// baseline (speedup 1.0000x reference)
#include <cuda_runtime.h>

#define T_STEPS 2048
#define OBS 512
#define MLPD 1024
#define HD 1024
#define ACTD 16
#define SCAN_BLOCKS 128

// ---------------- device scratch (no allocations allowed) ----------------
__device__ float g_preW[MLPD * OBS];
__device__ float g_preB[MLPD];
__device__ float g_p1W[MLPD * HD];
__device__ float g_p1B[MLPD];
__device__ float g_p2W[MLPD * MLPD];
__device__ float g_p2B[MLPD];
__device__ float g_p3W[ACTD * MLPD];
__device__ float g_p3B[ACTD];
__device__ float g_z[T_STEPS * MLPD];
__device__ float g_ig[(size_t)T_STEPS * 3 * HD];
__device__ float g_states[(size_t)T_STEPS * HD];
__device__ float g_hbuf[2][HD];
__device__ float g_y1[T_STEPS * MLPD];
__device__ float g_y2[T_STEPS * MLPD];
__device__ unsigned g_bar;

// ---------------- threefry2x32 (matches JAX) ----------------
#define TF_ROUND(x0, x1, R) { x0 += x1; x1 = (x1 << R) | (x1 >> (32 - R)); x1 ^= x0; }

__host__ __device__ inline void tf_block(unsigned k0, unsigned k1, unsigned &x0, unsigned &x1) {
    unsigned ks2 = k0 ^ k1 ^ 0x1BD11BDAu;
    x0 += k0; x1 += k1;
    TF_ROUND(x0, x1, 13) TF_ROUND(x0, x1, 15) TF_ROUND(x0, x1, 26) TF_ROUND(x0, x1, 6)
    x0 += k1; x1 += ks2 + 1u;
    TF_ROUND(x0, x1, 17) TF_ROUND(x0, x1, 29) TF_ROUND(x0, x1, 16) TF_ROUND(x0, x1, 24)
    x0 += ks2; x1 += k0 + 2u;
    TF_ROUND(x0, x1, 13) TF_ROUND(x0, x1, 15) TF_ROUND(x0, x1, 26) TF_ROUND(x0, x1, 6)
    x0 += k0; x1 += k1 + 3u;
    TF_ROUND(x0, x1, 17) TF_ROUND(x0, x1, 29) TF_ROUND(x0, x1, 16) TF_ROUND(x0, x1, 24)
    x0 += k1; x1 += ks2 + 4u;
    TF_ROUND(x0, x1, 13) TF_ROUND(x0, x1, 15) TF_ROUND(x0, x1, 26) TF_ROUND(x0, x1, 6)
    x0 += ks2; x1 += k0 + 5u;
}

// XLA f32 erf_inv (Giles), exact coefficient match
__device__ inline float xla_erfinv(float x) {
    float w = -log1pf(-x * x);
    float p;
    if (w < 5.0f) {
        w -= 2.5f;
        p = 2.81022636e-08f;
        p = fmaf(p, w, 3.43273939e-07f);
        p = fmaf(p, w, -3.5233877e-06f);
        p = fmaf(p, w, -4.39150654e-06f);
        p = fmaf(p, w, 0.00021858087f);
        p = fmaf(p, w, -0.00125372503f);
        p = fmaf(p, w, -0.00417768164f);
        p = fmaf(p, w, 0.246640727f);
        p = fmaf(p, w, 1.50140941f);
    } else {
        w = sqrtf(w) - 3.0f;
        p = -0.000200214257f;
        p = fmaf(p, w, 0.000100950558f);
        p = fmaf(p, w, 0.00134934322f);
        p = fmaf(p, w, -0.00367342844f);
        p = fmaf(p, w, 0.00573950773f);
        p = fmaf(p, w, -0.0076224613f);
        p = fmaf(p, w, 0.00943887047f);
        p = fmaf(p, w, 1.00167406f);
        p = fmaf(p, w, 2.83297682f);
    }
    return p * x;
}

__device__ inline float bits_to_normal(unsigned b) {
    float u1 = __uint_as_float((b >> 9) | 0x3f800000u) - 1.0f;  // [0,1)
    float v = fmaf(u1, 1.99999994f, -0.99999994f);              // uniform(-0.99999994, 1)
    v = fmaxf(v, -0.99999994f);
    return 1.41421356f * xla_erfinv(v);
}

// Partitionable threefry (JAX >= 0.4.36 default):
// bits[i] = x0out ^ x1out of threefry block with counter (hi=0, lo=i).
__global__ void gen_noisy_kernel(const float* __restrict__ wm, const float* __restrict__ ws,
                                 float* __restrict__ dst, int n, unsigned k0, unsigned k1) {
    int i = blockIdx.x * blockDim.x + threadIdx.x;
    if (i >= n) return;
    unsigned x0 = 0u, x1 = (unsigned)i;
    tf_block(k0, k1, x0, x1);
    dst[i] = fmaf(ws[i], bits_to_normal(x0 ^ x1), wm[i]);
}

// ---------------- activations ----------------
__device__ inline float mishf(float x) {
    float sp = fmaxf(x, 0.0f) + log1pf(expf(-fabsf(x)));  // stable softplus
    return x * tanhf(sp);
}

// ---------------- SGEMM: C[M,N] = A[M,K] @ B[N,K]^T + bias, optional mish ----------------
// M multiple of 64, K multiple of 16; N guarded.
__global__ __launch_bounds__(256) void sgemm_kernel(
    const float* __restrict__ A, const float* __restrict__ B,
    const float* __restrict__ bias, float* __restrict__ C,
    int M, int N, int K, int act) {
    __shared__ float As[16][64];
    __shared__ float Bs[16][64];
    const int m0 = blockIdx.y * 64;
    const int n0 = blockIdx.x * 64;
    const int tid = threadIdx.x;
    const int tx = tid & 15, ty = tid >> 4;
    const int lr = tid >> 2, lq = tid & 3;
    float acc[4][4] = {};
    for (int k0 = 0; k0 < K; k0 += 16) {
        float4 a4 = *(const float4*)(A + (size_t)(m0 + lr) * K + k0 + lq * 4);
        As[lq * 4 + 0][lr] = a4.x; As[lq * 4 + 1][lr] = a4.y;
        As[lq * 4 + 2][lr] = a4.z; As[lq * 4 + 3][lr] = a4.w;
        float4 b4 = make_float4(0.f, 0.f, 0.f, 0.f);
        if (n0 + lr < N) b4 = *(const float4*)(B + (size_t)(n0 + lr) * K + k0 + lq * 4);
        Bs[lq * 4 + 0][lr] = b4.x; Bs[lq * 4 + 1][lr] = b4.y;
        Bs[lq * 4 + 2][lr] = b4.z; Bs[lq * 4 + 3][lr] = b4.w;
        __syncthreads();
#pragma unroll
        for (int k = 0; k < 16; k++) {
            float4 av = *(const float4*)(&As[k][ty * 4]);
            float4 bv = *(const float4*)(&Bs[k][tx * 4]);
            acc[0][0] = fmaf(av.x, bv.x, acc[0][0]); acc[0][1] = fmaf(av.x, bv.y, acc[0][1]);
            acc[0][2] = fmaf(av.x, bv.z, acc[0][2]); acc[0][3] = fmaf(av.x, bv.w, acc[0][3]);
            acc[1][0] = fmaf(av.y, bv.x, acc[1][0]); acc[1][1] = fmaf(av.y, bv.y, acc[1][1]);
            acc[1][2] = fmaf(av.y, bv.z, acc[1][2]); acc[1][3] = fmaf(av.y, bv.w, acc[1][3]);
            acc[2][0] = fmaf(av.z, bv.x, acc[2][0]); acc[2][1] = fmaf(av.z, bv.y, acc[2][1]);
            acc[2][2] = fmaf(av.z, bv.z, acc[2][2]); acc[2][3] = fmaf(av.z, bv.w, acc[2][3]);
            acc[3][0] = fmaf(av.w, bv.x, acc[3][0]); acc[3][1] = fmaf(av.w, bv.y, acc[3][1]);
            acc[3][2] = fmaf(av.w, bv.z, acc[3][2]); acc[3][3] = fmaf(av.w, bv.w, acc[3][3]);
        }
        __syncthreads();
    }
#pragma unroll
    for (int i = 0; i < 4; i++) {
        int m = m0 + ty * 4 + i;
#pragma unroll
        for (int jj = 0; jj < 4; jj++) {
            int n = n0 + tx * 4 + jj;
            if (n < N) {
                float v = acc[i][jj] + (bias ? bias[n] : 0.0f);
                if (act) v = mishf(v);
                C[(size_t)m * N + n] = v;
            }
        }
    }
}

// ---------------- init + final-state copy ----------------
__global__ void init_kernel(const float* __restrict__ state) {
    int i = blockIdx.x * blockDim.x + threadIdx.x;
    if (i == 0) g_bar = 0u;
    if (i < HD) g_hbuf[0][i] = state[i];
}

__global__ void copy_final_kernel(float* __restrict__ out) {
    int i = blockIdx.x * blockDim.x + threadIdx.x;
    if (i < HD) out[i] = g_states[(size_t)(T_STEPS - 1) * HD + i];
}

// ---------------- persistent GRU scan ----------------
// 128 blocks x 256 threads, 1 block/SM (~100KB dyn smem) -> all co-resident.
// Block b owns h indices j0..j0+7 (j0 = 8*b); warp w owns j0+w fully
// (rows j, 1024+j, 2048+j of whh live in SMEM).
__global__ __launch_bounds__(256) void scan_kernel(
    const float* __restrict__ whh, const float* __restrict__ gbn,
    const int* __restrict__ start) {
    extern __shared__ float smem[];
    float* sW = smem;              // 24 * 1024
    float* sH = smem + 24 * 1024;  // 1024
    const int tid = threadIdx.x;
    const int j0 = blockIdx.x * 8;
    const int w = tid >> 5, lane = tid & 31;

    // stage whh rows into SMEM (once per launch)
    for (int idx = tid; idx < 24 * 256; idx += 256) {
        int rr = idx >> 8, c4 = idx & 255;
        int gate = rr >> 3, ww = rr & 7;
        ((float4*)sW)[idx] = ((const float4*)(whh + (size_t)(gate * HD + j0 + ww) * HD))[c4];
    }

    const float4* wR = (const float4*)(sW + (size_t)(0 + w) * 1024);
    const float4* wZ = (const float4*)(sW + (size_t)(8 + w) * 1024);
    const float4* wN = (const float4*)(sW + (size_t)(16 + w) * 1024);
    const float4* sH4 = (const float4*)sH;
    const int j = j0 + w;
    const float bnj = gbn[j];
    volatile unsigned* barp = &g_bar;

    for (int t = 0; t < T_STEPS; t++) {
        float keep = start[t] ? 0.0f : 1.0f;
        const float* hsrc = g_hbuf[t & 1];
        for (int idx = tid; idx < HD; idx += 256) sH[idx] = __ldcg(hsrc + idx) * keep;
        __syncthreads();

        float ir = 0.f, iz = 0.f, inn = 0.f;
        if (lane == 0) {
            const float* igt = g_ig + (size_t)t * (3 * HD);
            ir = igt[j]; iz = igt[HD + j]; inn = igt[2 * HD + j];
        }

        float aR = 0.f, aZ = 0.f, aN = 0.f;
#pragma unroll
        for (int q = 0; q < 8; q++) {
            int c = lane + q * 32;
            float4 h4 = sH4[c];
            float4 r4 = wR[c]; float4 z4 = wZ[c]; float4 n4 = wN[c];
            aR = fmaf(h4.x, r4.x, fmaf(h4.y, r4.y, fmaf(h4.z, r4.z, fmaf(h4.w, r4.w, aR))));
            aZ = fmaf(h4.x, z4.x, fmaf(h4.y, z4.y, fmaf(h4.z, z4.z, fmaf(h4.w, z4.w, aZ))));
            aN = fmaf(h4.x, n4.x, fmaf(h4.y, n4.y, fmaf(h4.z, n4.z, fmaf(h4.w, n4.w, aN))));
        }
#pragma unroll
        for (int off = 16; off; off >>= 1) {
            aR += __shfl_xor_sync(0xffffffffu, aR, off);
            aZ += __shfl_xor_sync(0xffffffffu, aZ, off);
            aN += __shfl_xor_sync(0xffffffffu, aN, off);
        }
        if (lane == 0) {
            float rv = 1.0f / (1.0f + expf(-(ir + aR)));
            float uv = 1.0f / (1.0f + expf(-(iz + aZ)));
            float nv = tanhf(inn + rv * (aN + bnj));
            float hin = sH[j];
            float hnew = nv + uv * (hin - nv);
            g_hbuf[(t + 1) & 1][j] = hnew;
            g_states[(size_t)t * HD + j] = hnew;
            __threadfence();
        }
        __syncthreads();
        if (tid == 0) {
            atomicAdd(&g_bar, 1u);
            unsigned target = (unsigned)(t + 1) * (unsigned)gridDim.x;
            while (*barp < target) {}
        }
        __syncthreads();
    }
}

// ---------------- launch ----------------
extern "C" void kernel_launch(void* const* d_in, const int* in_sizes, int n_in,
                              void* d_out, int out_size) {
    (void)in_sizes; (void)n_in;
    const float* x      = (const float*)d_in[0];
    const float* state  = (const float*)d_in[1];
    const int*   start  = (const int*)d_in[2];
    // d_in[3] = done (unused)
    const float* pre_wm = (const float*)d_in[4];
    const float* pre_ws = (const float*)d_in[5];
    const float* pre_bm = (const float*)d_in[6];
    const float* pre_bs = (const float*)d_in[7];
    const float* wih    = (const float*)d_in[8];
    const float* whh    = (const float*)d_in[9];
    const float* gru_b  = (const float*)d_in[10];
    const float* gru_bn = (const float*)d_in[11];
    const float* p1_wm  = (const float*)d_in[12];
    const float* p1_ws  = (const float*)d_in[13];
    const float* p1_bm  = (const float*)d_in[14];
    const float* p1_bs  = (const float*)d_in[15];
    const float* p2_wm  = (const float*)d_in[16];
    const float* p2_ws  = (const float*)d_in[17];
    const float* p2_bm  = (const float*)d_in[18];
    const float* p2_bs  = (const float*)d_in[19];
    const float* p3_wm  = (const float*)d_in[20];
    const float* p3_ws  = (const float*)d_in[21];
    const float* p3_bm  = (const float*)d_in[22];
    const float* p3_bs  = (const float*)d_in[23];
    float* out = (float*)d_out;
    (void)out_size;

    // nk = jax.random.split(jax.random.key(7), 8), partitionable ("foldlike"):
    // key_i = threefry block output (x0, x1) with counter (hi=0, lo=i).
    unsigned nk[8][2];
    for (int i = 0; i < 8; i++) {
        unsigned a = 0u, b = (unsigned)i;
        tf_block(0u, 7u, a, b);
        nk[i][0] = a; nk[i][1] = b;
    }

    float *preW, *preB, *p1W, *p1B, *p2W, *p2B, *p3W, *p3B, *z, *ig, *states, *y1, *y2;
    cudaGetSymbolAddress((void**)&preW, g_preW);
    cudaGetSymbolAddress((void**)&preB, g_preB);
    cudaGetSymbolAddress((void**)&p1W, g_p1W);
    cudaGetSymbolAddress((void**)&p1B, g_p1B);
    cudaGetSymbolAddress((void**)&p2W, g_p2W);
    cudaGetSymbolAddress((void**)&p2B, g_p2B);
    cudaGetSymbolAddress((void**)&p3W, g_p3W);
    cudaGetSymbolAddress((void**)&p3B, g_p3B);
    cudaGetSymbolAddress((void**)&z, g_z);
    cudaGetSymbolAddress((void**)&ig, g_ig);
    cudaGetSymbolAddress((void**)&states, g_states);
    cudaGetSymbolAddress((void**)&y1, g_y1);
    cudaGetSymbolAddress((void**)&y2, g_y2);

    cudaFuncSetAttribute(scan_kernel, cudaFuncAttributeMaxDynamicSharedMemorySize,
                         (24 * 1024 + 1024) * (int)sizeof(float));

    init_kernel<<<(HD + 255) / 256, 256>>>(state);

    // noisy weights/biases: nk order = pre(w,b), p1(w,b), p2(w,b), p3(w,b)
    {
        int n;
        n = MLPD * OBS;  gen_noisy_kernel<<<(n + 255) / 256, 256>>>(pre_wm, pre_ws, preW, n, nk[0][0], nk[0][1]);
        n = MLPD;        gen_noisy_kernel<<<(n + 255) / 256, 256>>>(pre_bm, pre_bs, preB, n, nk[1][0], nk[1][1]);
        n = MLPD * HD;   gen_noisy_kernel<<<(n + 255) / 256, 256>>>(p1_wm, p1_ws, p1W, n, nk[2][0], nk[2][1]);
        n = MLPD;        gen_noisy_kernel<<<(n + 255) / 256, 256>>>(p1_bm, p1_bs, p1B, n, nk[3][0], nk[3][1]);
        n = MLPD * MLPD; gen_noisy_kernel<<<(n + 255) / 256, 256>>>(p2_wm, p2_ws, p2W, n, nk[4][0], nk[4][1]);
        n = MLPD;        gen_noisy_kernel<<<(n + 255) / 256, 256>>>(p2_bm, p2_bs, p2B, n, nk[5][0], nk[5][1]);
        n = ACTD * MLPD; gen_noisy_kernel<<<(n + 255) / 256, 256>>>(p3_wm, p3_ws, p3W, n, nk[6][0], nk[6][1]);
        n = ACTD;        gen_noisy_kernel<<<(n + 255) / 256, 256>>>(p3_bm, p3_bs, p3B, n, nk[7][0], nk[7][1]);
    }

    // z = mish(x @ preW^T + preB)   [2048,1024], K=512
    sgemm_kernel<<<dim3(MLPD / 64, T_STEPS / 64), 256>>>(x, preW, preB, z, T_STEPS, MLPD, OBS, 1);
    // igates = z @ wih^T + gru_b    [2048,3072], K=1024
    sgemm_kernel<<<dim3(3 * HD / 64, T_STEPS / 64), 256>>>(z, wih, gru_b, ig, T_STEPS, 3 * HD, MLPD, 0);
    // sequential GRU scan
    scan_kernel<<<SCAN_BLOCKS, 256, (24 * 1024 + 1024) * (int)sizeof(float)>>>(whh, gru_bn, start);
    // post MLP
    sgemm_kernel<<<dim3(MLPD / 64, T_STEPS / 64), 256>>>(states, p1W, p1B, y1, T_STEPS, MLPD, HD, 1);
    sgemm_kernel<<<dim3(MLPD / 64, T_STEPS / 64), 256>>>(y1, p2W, p2B, y2, T_STEPS, MLPD, MLPD, 1);
    // final layer -> d_out[0 : 2048*16]
    sgemm_kernel<<<dim3(1, T_STEPS / 64), 256>>>(y2, p3W, p3B, out, T_STEPS, ACTD, MLPD, 0);
    // final hidden state -> d_out[2048*16 : +1024]
    copy_final_kernel<<<(HD + 255) / 256, 256>>>(out + (size_t)T_STEPS * ACTD);
}

// round 3
// speedup vs baseline: 1.6102x; 1.6102x over previous
#include <cuda_runtime.h>

#define T_STEPS 2048
#define OBS 512
#define MLPD 1024
#define HD 1024
#define ACTD 16
#define SCAN_BLOCKS 128

// ---------------- device scratch (no allocations allowed) ----------------
__device__ float g_preW[MLPD * OBS];
__device__ float g_preB[MLPD];
__device__ float g_p1W[MLPD * HD];
__device__ float g_p1B[MLPD];
__device__ float g_p2W[MLPD * MLPD];
__device__ float g_p2B[MLPD];
__device__ float g_p3W[ACTD * MLPD];
__device__ float g_p3B[ACTD];
__device__ float g_z[T_STEPS * MLPD];
__device__ float g_ig[(size_t)T_STEPS * 3 * HD];
__device__ float g_states[(size_t)T_STEPS * HD];
__device__ float g_hbuf[2][HD];
__device__ float g_y1[T_STEPS * MLPD];
__device__ float g_y2[T_STEPS * MLPD];
__device__ unsigned g_bar;

// ---------------- threefry2x32 (matches JAX) ----------------
#define TF_ROUND(x0, x1, R) { x0 += x1; x1 = (x1 << R) | (x1 >> (32 - R)); x1 ^= x0; }

__host__ __device__ inline void tf_block(unsigned k0, unsigned k1, unsigned &x0, unsigned &x1) {
    unsigned ks2 = k0 ^ k1 ^ 0x1BD11BDAu;
    x0 += k0; x1 += k1;
    TF_ROUND(x0, x1, 13) TF_ROUND(x0, x1, 15) TF_ROUND(x0, x1, 26) TF_ROUND(x0, x1, 6)
    x0 += k1; x1 += ks2 + 1u;
    TF_ROUND(x0, x1, 17) TF_ROUND(x0, x1, 29) TF_ROUND(x0, x1, 16) TF_ROUND(x0, x1, 24)
    x0 += ks2; x1 += k0 + 2u;
    TF_ROUND(x0, x1, 13) TF_ROUND(x0, x1, 15) TF_ROUND(x0, x1, 26) TF_ROUND(x0, x1, 6)
    x0 += k0; x1 += k1 + 3u;
    TF_ROUND(x0, x1, 17) TF_ROUND(x0, x1, 29) TF_ROUND(x0, x1, 16) TF_ROUND(x0, x1, 24)
    x0 += k1; x1 += ks2 + 4u;
    TF_ROUND(x0, x1, 13) TF_ROUND(x0, x1, 15) TF_ROUND(x0, x1, 26) TF_ROUND(x0, x1, 6)
    x0 += ks2; x1 += k0 + 5u;
}

// XLA f32 erf_inv (Giles), exact coefficient match
__device__ inline float xla_erfinv(float x) {
    float w = -log1pf(-x * x);
    float p;
    if (w < 5.0f) {
        w -= 2.5f;
        p = 2.81022636e-08f;
        p = fmaf(p, w, 3.43273939e-07f);
        p = fmaf(p, w, -3.5233877e-06f);
        p = fmaf(p, w, -4.39150654e-06f);
        p = fmaf(p, w, 0.00021858087f);
        p = fmaf(p, w, -0.00125372503f);
        p = fmaf(p, w, -0.00417768164f);
        p = fmaf(p, w, 0.246640727f);
        p = fmaf(p, w, 1.50140941f);
    } else {
        w = sqrtf(w) - 3.0f;
        p = -0.000200214257f;
        p = fmaf(p, w, 0.000100950558f);
        p = fmaf(p, w, 0.00134934322f);
        p = fmaf(p, w, -0.00367342844f);
        p = fmaf(p, w, 0.00573950773f);
        p = fmaf(p, w, -0.0076224613f);
        p = fmaf(p, w, 0.00943887047f);
        p = fmaf(p, w, 1.00167406f);
        p = fmaf(p, w, 2.83297682f);
    }
    return p * x;
}

__device__ inline float bits_to_normal(unsigned b) {
    float u1 = __uint_as_float((b >> 9) | 0x3f800000u) - 1.0f;  // [0,1)
    float v = fmaf(u1, 1.99999994f, -0.99999994f);              // uniform(-0.99999994, 1)
    v = fmaxf(v, -0.99999994f);
    return 1.41421356f * xla_erfinv(v);
}

// Partitionable threefry: bits[i] = x0^x1 of block with counter (0, i)
__global__ void gen_noisy_kernel(const float* __restrict__ wm, const float* __restrict__ ws,
                                 float* __restrict__ dst, int n, unsigned k0, unsigned k1) {
    int i = blockIdx.x * blockDim.x + threadIdx.x;
    if (i >= n) return;
    unsigned x0 = 0u, x1 = (unsigned)i;
    tf_block(k0, k1, x0, x1);
    dst[i] = fmaf(ws[i], bits_to_normal(x0 ^ x1), wm[i]);
}

// ---------------- activations ----------------
__device__ inline float mishf(float x) {
    float sp = fmaxf(x, 0.0f) + log1pf(expf(-fabsf(x)));  // stable softplus
    return x * tanhf(sp);
}

// ---------------- SGEMM 128x128x16, 8x8 microtile: C = A[M,K] @ B[N,K]^T + bias ----------------
// M, N multiples of 128; K multiple of 16.
__global__ __launch_bounds__(256, 2) void sgemm128_kernel(
    const float* __restrict__ A, const float* __restrict__ B,
    const float* __restrict__ bias, float* __restrict__ C,
    int M, int N, int K, int act) {
    __shared__ float As[16][128];
    __shared__ float Bs[16][128];
    const int tid = threadIdx.x;
    const int m0 = blockIdx.y * 128, n0 = blockIdx.x * 128;
    const int tx = tid & 15, ty = tid >> 4;
    const int r0 = tid >> 2;       // 0..63
    const int c4 = tid & 3;        // float4 column within 16-k tile
    const int rs = r0 ^ (c4 * 8);  // xor-swizzled row for conflict-free STS

    const float* Aptr  = A + (size_t)(m0 + r0) * K + c4 * 4;
    const float* Aptr2 = Aptr + (size_t)64 * K;
    const float* Bptr  = B + (size_t)(n0 + r0) * K + c4 * 4;
    const float* Bptr2 = Bptr + (size_t)64 * K;

    float4 a0 = *(const float4*)Aptr;
    float4 a1 = *(const float4*)Aptr2;
    float4 b0 = *(const float4*)Bptr;
    float4 b1 = *(const float4*)Bptr2;

    float acc[8][8] = {};
    const int aBase = ty * 8, bBase = tx * 8;

    for (int k0 = 0; k0 < K; k0 += 16) {
        As[c4 * 4 + 0][rs] = a0.x; As[c4 * 4 + 1][rs] = a0.y;
        As[c4 * 4 + 2][rs] = a0.z; As[c4 * 4 + 3][rs] = a0.w;
        As[c4 * 4 + 0][rs + 64] = a1.x; As[c4 * 4 + 1][rs + 64] = a1.y;
        As[c4 * 4 + 2][rs + 64] = a1.z; As[c4 * 4 + 3][rs + 64] = a1.w;
        Bs[c4 * 4 + 0][rs] = b0.x; Bs[c4 * 4 + 1][rs] = b0.y;
        Bs[c4 * 4 + 2][rs] = b0.z; Bs[c4 * 4 + 3][rs] = b0.w;
        Bs[c4 * 4 + 0][rs + 64] = b1.x; Bs[c4 * 4 + 1][rs + 64] = b1.y;
        Bs[c4 * 4 + 2][rs + 64] = b1.z; Bs[c4 * 4 + 3][rs + 64] = b1.w;
        __syncthreads();
        if (k0 + 16 < K) {
            Aptr += 16; Aptr2 += 16; Bptr += 16; Bptr2 += 16;
            a0 = *(const float4*)Aptr;  a1 = *(const float4*)Aptr2;
            b0 = *(const float4*)Bptr;  b1 = *(const float4*)Bptr2;
        }
#pragma unroll
        for (int k = 0; k < 16; k++) {
            const int off = (k >> 2) * 8;
            const int sa = aBase ^ off, sb = bBase ^ off;
            float4 av0 = *(const float4*)&As[k][sa];
            float4 av1 = *(const float4*)&As[k][sa + 4];
            float4 bv0 = *(const float4*)&Bs[k][sb];
            float4 bv1 = *(const float4*)&Bs[k][sb + 4];
            float av[8] = {av0.x, av0.y, av0.z, av0.w, av1.x, av1.y, av1.z, av1.w};
            float bv[8] = {bv0.x, bv0.y, bv0.z, bv0.w, bv1.x, bv1.y, bv1.z, bv1.w};
#pragma unroll
            for (int i = 0; i < 8; i++)
#pragma unroll
                for (int jj = 0; jj < 8; jj++)
                    acc[i][jj] = fmaf(av[i], bv[jj], acc[i][jj]);
        }
        __syncthreads();
    }

    float bs0[8];
#pragma unroll
    for (int jj = 0; jj < 8; jj++) bs0[jj] = bias ? bias[n0 + bBase + jj] : 0.0f;
#pragma unroll
    for (int i = 0; i < 8; i++) {
        const int m = m0 + aBase + i;
        float v[8];
#pragma unroll
        for (int jj = 0; jj < 8; jj++) {
            v[jj] = acc[i][jj] + bs0[jj];
            if (act) v[jj] = mishf(v[jj]);
        }
        *(float4*)&C[(size_t)m * N + n0 + bBase]     = make_float4(v[0], v[1], v[2], v[3]);
        *(float4*)&C[(size_t)m * N + n0 + bBase + 4] = make_float4(v[4], v[5], v[6], v[7]);
    }
}

// ---------------- small SGEMM (p3, N=16): C[M,N] = A @ B^T + bias ----------------
__global__ __launch_bounds__(256) void sgemm64_kernel(
    const float* __restrict__ A, const float* __restrict__ B,
    const float* __restrict__ bias, float* __restrict__ C,
    int M, int N, int K) {
    __shared__ float As[16][64];
    __shared__ float Bs[16][64];
    const int m0 = blockIdx.y * 64;
    const int n0 = blockIdx.x * 64;
    const int tid = threadIdx.x;
    const int tx = tid & 15, ty = tid >> 4;
    const int lr = tid >> 2, lq = tid & 3;
    float acc[4][4] = {};
    for (int k0 = 0; k0 < K; k0 += 16) {
        float4 a4 = *(const float4*)(A + (size_t)(m0 + lr) * K + k0 + lq * 4);
        As[lq * 4 + 0][lr] = a4.x; As[lq * 4 + 1][lr] = a4.y;
        As[lq * 4 + 2][lr] = a4.z; As[lq * 4 + 3][lr] = a4.w;
        float4 b4 = make_float4(0.f, 0.f, 0.f, 0.f);
        if (n0 + lr < N) b4 = *(const float4*)(B + (size_t)(n0 + lr) * K + k0 + lq * 4);
        Bs[lq * 4 + 0][lr] = b4.x; Bs[lq * 4 + 1][lr] = b4.y;
        Bs[lq * 4 + 2][lr] = b4.z; Bs[lq * 4 + 3][lr] = b4.w;
        __syncthreads();
#pragma unroll
        for (int k = 0; k < 16; k++) {
            float4 av = *(const float4*)(&As[k][ty * 4]);
            float4 bv = *(const float4*)(&Bs[k][tx * 4]);
            float avs[4] = {av.x, av.y, av.z, av.w};
            float bvs[4] = {bv.x, bv.y, bv.z, bv.w};
#pragma unroll
            for (int i = 0; i < 4; i++)
#pragma unroll
                for (int jj = 0; jj < 4; jj++)
                    acc[i][jj] = fmaf(avs[i], bvs[jj], acc[i][jj]);
        }
        __syncthreads();
    }
#pragma unroll
    for (int i = 0; i < 4; i++) {
        int m = m0 + ty * 4 + i;
#pragma unroll
        for (int jj = 0; jj < 4; jj++) {
            int n = n0 + tx * 4 + jj;
            if (n < N) C[(size_t)m * N + n] = acc[i][jj] + (bias ? bias[n] : 0.0f);
        }
    }
}

// ---------------- init ----------------
__global__ void init_kernel(const float* __restrict__ state) {
    int i = blockIdx.x * blockDim.x + threadIdx.x;
    if (i == 0) g_bar = 0u;
    if (i < HD) g_hbuf[0][i] = state[i];
}

// ---------------- persistent GRU scan, register-resident whh ----------------
// 128 blocks x 256 threads. Warp w of block b owns h-index j = 8b + w.
// Each lane holds 96 weight floats (3 gates x 32) in registers.
__global__ __launch_bounds__(256, 1) void scan_kernel(
    const float* __restrict__ whh, const float* __restrict__ gbn,
    const int* __restrict__ start, float* __restrict__ out) {
    __shared__ float sH[HD];
    const int tid = threadIdx.x;
    const int w = tid >> 5, lane = tid & 31;
    const int j = blockIdx.x * 8 + w;

    // weights -> registers (once)
    const float4* w4 = (const float4*)whh;
    float4 wr[8], wz[8], wn[8];
#pragma unroll
    for (int q = 0; q < 8; q++) {
        wr[q] = w4[(size_t)(0 * HD + j) * 256 + lane + 32 * q];
        wz[q] = w4[(size_t)(1 * HD + j) * 256 + lane + 32 * q];
        wn[q] = w4[(size_t)(2 * HD + j) * 256 + lane + 32 * q];
    }
    const float bnj = gbn[j];
    float4* sH4s = (float4*)sH;
    const float4* sH4 = (const float4*)sH;
    unsigned* barp = &g_bar;

    for (int t = 0; t < T_STEPS; t++) {
        const int st = start[t];  // uniform across grid

        // prefetch input gates early (lane 0 only)
        float ir = 0.f, iz = 0.f, inn = 0.f;
        if (lane == 0) {
            const float* igt = g_ig + (size_t)t * (3 * HD);
            ir = igt[j]; iz = igt[HD + j]; inn = igt[2 * HD + j];
        }

        float aR = 0.f, aZ = 0.f, aN = 0.f;
        float hin = 0.f;
        if (!st) {
            const float4* hsrc = (const float4*)g_hbuf[t & 1];
            sH4s[tid] = __ldcg(hsrc + tid);
            __syncthreads();
#pragma unroll
            for (int q = 0; q < 8; q++) {
                float4 h4 = sH4[lane + 32 * q];
                aR = fmaf(h4.x, wr[q].x, fmaf(h4.y, wr[q].y, fmaf(h4.z, wr[q].z, fmaf(h4.w, wr[q].w, aR))));
                aZ = fmaf(h4.x, wz[q].x, fmaf(h4.y, wz[q].y, fmaf(h4.z, wz[q].z, fmaf(h4.w, wz[q].w, aZ))));
                aN = fmaf(h4.x, wn[q].x, fmaf(h4.y, wn[q].y, fmaf(h4.z, wn[q].z, fmaf(h4.w, wn[q].w, aN))));
            }
#pragma unroll
            for (int off = 16; off; off >>= 1) {
                aR += __shfl_xor_sync(0xffffffffu, aR, off);
                aZ += __shfl_xor_sync(0xffffffffu, aZ, off);
                aN += __shfl_xor_sync(0xffffffffu, aN, off);
            }
            if (lane == 0) hin = sH[j];
        }

        if (lane == 0) {
            float rv = 1.0f / (1.0f + expf(-(ir + aR)));
            float uv = 1.0f / (1.0f + expf(-(iz + aZ)));
            float nv = tanhf(inn + rv * (aN + bnj));
            float hnew = nv + uv * (hin - nv);
            g_hbuf[(t + 1) & 1][j] = hnew;
            g_states[(size_t)t * HD + j] = hnew;
            if (t == T_STEPS - 1) out[(size_t)T_STEPS * ACTD + j] = hnew;
        }
        __syncthreads();
        if (tid == 0) {
            asm volatile("red.release.gpu.global.add.u32 [%0], %1;" :: "l"(barp), "r"(1u) : "memory");
            const unsigned target = (unsigned)(t + 1) * (unsigned)SCAN_BLOCKS;
            unsigned v;
            do {
                asm volatile("ld.acquire.gpu.global.u32 %0, [%1];" : "=r"(v) : "l"(barp) : "memory");
            } while (v < target);
        }
        __syncthreads();
    }
}

// ---------------- launch ----------------
extern "C" void kernel_launch(void* const* d_in, const int* in_sizes, int n_in,
                              void* d_out, int out_size) {
    (void)in_sizes; (void)n_in;
    const float* x      = (const float*)d_in[0];
    const float* state  = (const float*)d_in[1];
    const int*   start  = (const int*)d_in[2];
    // d_in[3] = done (unused)
    const float* pre_wm = (const float*)d_in[4];
    const float* pre_ws = (const float*)d_in[5];
    const float* pre_bm = (const float*)d_in[6];
    const float* pre_bs = (const float*)d_in[7];
    const float* wih    = (const float*)d_in[8];
    const float* whh    = (const float*)d_in[9];
    const float* gru_b  = (const float*)d_in[10];
    const float* gru_bn = (const float*)d_in[11];
    const float* p1_wm  = (const float*)d_in[12];
    const float* p1_ws  = (const float*)d_in[13];
    const float* p1_bm  = (const float*)d_in[14];
    const float* p1_bs  = (const float*)d_in[15];
    const float* p2_wm  = (const float*)d_in[16];
    const float* p2_ws  = (const float*)d_in[17];
    const float* p2_bm  = (const float*)d_in[18];
    const float* p2_bs  = (const float*)d_in[19];
    const float* p3_wm  = (const float*)d_in[20];
    const float* p3_ws  = (const float*)d_in[21];
    const float* p3_bm  = (const float*)d_in[22];
    const float* p3_bs  = (const float*)d_in[23];
    float* out = (float*)d_out;
    (void)out_size;

    // nk = jax.random.split(jax.random.key(7), 8) (partitionable):
    // key_i = threefry block output with counter (0, i)
    unsigned nk[8][2];
    for (int i = 0; i < 8; i++) {
        unsigned a = 0u, b = (unsigned)i;
        tf_block(0u, 7u, a, b);
        nk[i][0] = a; nk[i][1] = b;
    }

    float *preW, *preB, *p1W, *p1B, *p2W, *p2B, *p3W, *p3B, *z, *ig, *states, *y1, *y2;
    cudaGetSymbolAddress((void**)&preW, g_preW);
    cudaGetSymbolAddress((void**)&preB, g_preB);
    cudaGetSymbolAddress((void**)&p1W, g_p1W);
    cudaGetSymbolAddress((void**)&p1B, g_p1B);
    cudaGetSymbolAddress((void**)&p2W, g_p2W);
    cudaGetSymbolAddress((void**)&p2B, g_p2B);
    cudaGetSymbolAddress((void**)&p3W, g_p3W);
    cudaGetSymbolAddress((void**)&p3B, g_p3B);
    cudaGetSymbolAddress((void**)&z, g_z);
    cudaGetSymbolAddress((void**)&ig, g_ig);
    cudaGetSymbolAddress((void**)&states, g_states);
    cudaGetSymbolAddress((void**)&y1, g_y1);
    cudaGetSymbolAddress((void**)&y2, g_y2);

    init_kernel<<<(HD + 255) / 256, 256>>>(state);

    // noisy weights/biases: nk order = pre(w,b), p1(w,b), p2(w,b), p3(w,b)
    {
        int n;
        n = MLPD * OBS;  gen_noisy_kernel<<<(n + 255) / 256, 256>>>(pre_wm, pre_ws, preW, n, nk[0][0], nk[0][1]);
        n = MLPD;        gen_noisy_kernel<<<(n + 255) / 256, 256>>>(pre_bm, pre_bs, preB, n, nk[1][0], nk[1][1]);
        n = MLPD * HD;   gen_noisy_kernel<<<(n + 255) / 256, 256>>>(p1_wm, p1_ws, p1W, n, nk[2][0], nk[2][1]);
        n = MLPD;        gen_noisy_kernel<<<(n + 255) / 256, 256>>>(p1_bm, p1_bs, p1B, n, nk[3][0], nk[3][1]);
        n = MLPD * MLPD; gen_noisy_kernel<<<(n + 255) / 256, 256>>>(p2_wm, p2_ws, p2W, n, nk[4][0], nk[4][1]);
        n = MLPD;        gen_noisy_kernel<<<(n + 255) / 256, 256>>>(p2_bm, p2_bs, p2B, n, nk[5][0], nk[5][1]);
        n = ACTD * MLPD; gen_noisy_kernel<<<(n + 255) / 256, 256>>>(p3_wm, p3_ws, p3W, n, nk[6][0], nk[6][1]);
        n = ACTD;        gen_noisy_kernel<<<(n + 255) / 256, 256>>>(p3_bm, p3_bs, p3B, n, nk[7][0], nk[7][1]);
    }

    // z = mish(x @ preW^T + preB)   [2048,1024], K=512
    sgemm128_kernel<<<dim3(MLPD / 128, T_STEPS / 128), 256>>>(x, preW, preB, z, T_STEPS, MLPD, OBS, 1);
    // igates = z @ wih^T + gru_b    [2048,3072], K=1024
    sgemm128_kernel<<<dim3(3 * HD / 128, T_STEPS / 128), 256>>>(z, wih, gru_b, ig, T_STEPS, 3 * HD, MLPD, 0);
    // sequential GRU scan (also writes final state into out tail)
    scan_kernel<<<SCAN_BLOCKS, 256>>>(whh, gru_bn, start, out);
    // post MLP
    sgemm128_kernel<<<dim3(MLPD / 128, T_STEPS / 128), 256>>>(states, p1W, p1B, y1, T_STEPS, MLPD, HD, 1);
    sgemm128_kernel<<<dim3(MLPD / 128, T_STEPS / 128), 256>>>(y1, p2W, p2B, y2, T_STEPS, MLPD, MLPD, 1);
    // final layer -> d_out[0 : 2048*16]
    sgemm64_kernel<<<dim3(1, T_STEPS / 64), 256>>>(y2, p3W, p3B, out, T_STEPS, ACTD, MLPD);
}

// round 4
// speedup vs baseline: 5.5932x; 3.4736x over previous
#include <cuda_runtime.h>

#define T_STEPS 2048
#define OBS 512
#define MLPD 1024
#define HD 1024
#define ACTD 16
#define SCAN_BLOCKS 128

// ---------------- device scratch (no allocations allowed) ----------------
__device__ float g_preW[MLPD * OBS];
__device__ float g_preB[MLPD];
__device__ float g_p1W[MLPD * HD];
__device__ float g_p1B[MLPD];
__device__ float g_p2W[MLPD * MLPD];
__device__ float g_p2B[MLPD];
__device__ float g_p3W[ACTD * MLPD];
__device__ float g_p3B[ACTD];
__device__ float g_z[T_STEPS * MLPD];
__device__ float g_ig[(size_t)T_STEPS * 3 * HD];
__device__ float g_states[(size_t)T_STEPS * HD];
__device__ float g_y1[T_STEPS * MLPD];
__device__ float g_y2[T_STEPS * MLPD];
__device__ unsigned g_bar;
__device__ int g_order[T_STEPS];
__device__ int g_off[T_STEPS + 1];
__device__ int g_kmax;

// ---------------- threefry2x32 (matches JAX) ----------------
#define TF_ROUND(x0, x1, R) { x0 += x1; x1 = (x1 << R) | (x1 >> (32 - R)); x1 ^= x0; }

__host__ __device__ inline void tf_block(unsigned k0, unsigned k1, unsigned &x0, unsigned &x1) {
    unsigned ks2 = k0 ^ k1 ^ 0x1BD11BDAu;
    x0 += k0; x1 += k1;
    TF_ROUND(x0, x1, 13) TF_ROUND(x0, x1, 15) TF_ROUND(x0, x1, 26) TF_ROUND(x0, x1, 6)
    x0 += k1; x1 += ks2 + 1u;
    TF_ROUND(x0, x1, 17) TF_ROUND(x0, x1, 29) TF_ROUND(x0, x1, 16) TF_ROUND(x0, x1, 24)
    x0 += ks2; x1 += k0 + 2u;
    TF_ROUND(x0, x1, 13) TF_ROUND(x0, x1, 15) TF_ROUND(x0, x1, 26) TF_ROUND(x0, x1, 6)
    x0 += k0; x1 += k1 + 3u;
    TF_ROUND(x0, x1, 17) TF_ROUND(x0, x1, 29) TF_ROUND(x0, x1, 16) TF_ROUND(x0, x1, 24)
    x0 += k1; x1 += ks2 + 4u;
    TF_ROUND(x0, x1, 13) TF_ROUND(x0, x1, 15) TF_ROUND(x0, x1, 26) TF_ROUND(x0, x1, 6)
    x0 += ks2; x1 += k0 + 5u;
}

// XLA f32 erf_inv (Giles), exact coefficient match
__device__ inline float xla_erfinv(float x) {
    float w = -log1pf(-x * x);
    float p;
    if (w < 5.0f) {
        w -= 2.5f;
        p = 2.81022636e-08f;
        p = fmaf(p, w, 3.43273939e-07f);
        p = fmaf(p, w, -3.5233877e-06f);
        p = fmaf(p, w, -4.39150654e-06f);
        p = fmaf(p, w, 0.00021858087f);
        p = fmaf(p, w, -0.00125372503f);
        p = fmaf(p, w, -0.00417768164f);
        p = fmaf(p, w, 0.246640727f);
        p = fmaf(p, w, 1.50140941f);
    } else {
        w = sqrtf(w) - 3.0f;
        p = -0.000200214257f;
        p = fmaf(p, w, 0.000100950558f);
        p = fmaf(p, w, 0.00134934322f);
        p = fmaf(p, w, -0.00367342844f);
        p = fmaf(p, w, 0.00573950773f);
        p = fmaf(p, w, -0.0076224613f);
        p = fmaf(p, w, 0.00943887047f);
        p = fmaf(p, w, 1.00167406f);
        p = fmaf(p, w, 2.83297682f);
    }
    return p * x;
}

__device__ inline float bits_to_normal(unsigned b) {
    float u1 = __uint_as_float((b >> 9) | 0x3f800000u) - 1.0f;  // [0,1)
    float v = fmaf(u1, 1.99999994f, -0.99999994f);              // uniform(-0.99999994, 1)
    v = fmaxf(v, -0.99999994f);
    return 1.41421356f * xla_erfinv(v);
}

// Partitionable threefry: bits[i] = x0^x1 of block with counter (0, i)
__global__ void gen_noisy_kernel(const float* __restrict__ wm, const float* __restrict__ ws,
                                 float* __restrict__ dst, int n, unsigned k0, unsigned k1) {
    int i = blockIdx.x * blockDim.x + threadIdx.x;
    if (i >= n) return;
    unsigned x0 = 0u, x1 = (unsigned)i;
    tf_block(k0, k1, x0, x1);
    dst[i] = fmaf(ws[i], bits_to_normal(x0 ^ x1), wm[i]);
}

// ---------------- activations ----------------
__device__ inline float mishf(float x) {
    float sp = fmaxf(x, 0.0f) + log1pf(expf(-fabsf(x)));  // stable softplus
    return x * tanhf(sp);
}

__device__ inline float sigmoidf_(float x) { return 1.0f / (1.0f + expf(-x)); }

// ---------------- SGEMM 128x128x16, 8x8 microtile: C = A[M,K] @ B[N,K]^T + bias ----------------
__global__ __launch_bounds__(256, 2) void sgemm128_kernel(
    const float* __restrict__ A, const float* __restrict__ B,
    const float* __restrict__ bias, float* __restrict__ C,
    int M, int N, int K, int act) {
    __shared__ float As[16][128];
    __shared__ float Bs[16][128];
    const int tid = threadIdx.x;
    const int m0 = blockIdx.y * 128, n0 = blockIdx.x * 128;
    const int tx = tid & 15, ty = tid >> 4;
    const int r0 = tid >> 2;
    const int c4 = tid & 3;
    const int rs = r0 ^ (c4 * 8);

    const float* Aptr  = A + (size_t)(m0 + r0) * K + c4 * 4;
    const float* Aptr2 = Aptr + (size_t)64 * K;
    const float* Bptr  = B + (size_t)(n0 + r0) * K + c4 * 4;
    const float* Bptr2 = Bptr + (size_t)64 * K;

    float4 a0 = *(const float4*)Aptr;
    float4 a1 = *(const float4*)Aptr2;
    float4 b0 = *(const float4*)Bptr;
    float4 b1 = *(const float4*)Bptr2;

    float acc[8][8] = {};
    const int aBase = ty * 8, bBase = tx * 8;

    for (int k0 = 0; k0 < K; k0 += 16) {
        As[c4 * 4 + 0][rs] = a0.x; As[c4 * 4 + 1][rs] = a0.y;
        As[c4 * 4 + 2][rs] = a0.z; As[c4 * 4 + 3][rs] = a0.w;
        As[c4 * 4 + 0][rs + 64] = a1.x; As[c4 * 4 + 1][rs + 64] = a1.y;
        As[c4 * 4 + 2][rs + 64] = a1.z; As[c4 * 4 + 3][rs + 64] = a1.w;
        Bs[c4 * 4 + 0][rs] = b0.x; Bs[c4 * 4 + 1][rs] = b0.y;
        Bs[c4 * 4 + 2][rs] = b0.z; Bs[c4 * 4 + 3][rs] = b0.w;
        Bs[c4 * 4 + 0][rs + 64] = b1.x; Bs[c4 * 4 + 1][rs + 64] = b1.y;
        Bs[c4 * 4 + 2][rs + 64] = b1.z; Bs[c4 * 4 + 3][rs + 64] = b1.w;
        __syncthreads();
        if (k0 + 16 < K) {
            Aptr += 16; Aptr2 += 16; Bptr += 16; Bptr2 += 16;
            a0 = *(const float4*)Aptr;  a1 = *(const float4*)Aptr2;
            b0 = *(const float4*)Bptr;  b1 = *(const float4*)Bptr2;
        }
#pragma unroll
        for (int k = 0; k < 16; k++) {
            const int off = (k >> 2) * 8;
            const int sa = aBase ^ off, sb = bBase ^ off;
            float4 av0 = *(const float4*)&As[k][sa];
            float4 av1 = *(const float4*)&As[k][sa + 4];
            float4 bv0 = *(const float4*)&Bs[k][sb];
            float4 bv1 = *(const float4*)&Bs[k][sb + 4];
            float av[8] = {av0.x, av0.y, av0.z, av0.w, av1.x, av1.y, av1.z, av1.w};
            float bv[8] = {bv0.x, bv0.y, bv0.z, bv0.w, bv1.x, bv1.y, bv1.z, bv1.w};
#pragma unroll
            for (int i = 0; i < 8; i++)
#pragma unroll
                for (int jj = 0; jj < 8; jj++)
                    acc[i][jj] = fmaf(av[i], bv[jj], acc[i][jj]);
        }
        __syncthreads();
    }

    float bs0[8];
#pragma unroll
    for (int jj = 0; jj < 8; jj++) bs0[jj] = bias ? bias[n0 + bBase + jj] : 0.0f;
#pragma unroll
    for (int i = 0; i < 8; i++) {
        const int m = m0 + aBase + i;
        float v[8];
#pragma unroll
        for (int jj = 0; jj < 8; jj++) {
            v[jj] = acc[i][jj] + bs0[jj];
            if (act) v[jj] = mishf(v[jj]);
        }
        *(float4*)&C[(size_t)m * N + n0 + bBase]     = make_float4(v[0], v[1], v[2], v[3]);
        *(float4*)&C[(size_t)m * N + n0 + bBase + 4] = make_float4(v[4], v[5], v[6], v[7]);
    }
}

// ---------------- small SGEMM (p3, N=16) ----------------
__global__ __launch_bounds__(256) void sgemm64_kernel(
    const float* __restrict__ A, const float* __restrict__ B,
    const float* __restrict__ bias, float* __restrict__ C,
    int M, int N, int K) {
    __shared__ float As[16][64];
    __shared__ float Bs[16][64];
    const int m0 = blockIdx.y * 64;
    const int n0 = blockIdx.x * 64;
    const int tid = threadIdx.x;
    const int tx = tid & 15, ty = tid >> 4;
    const int lr = tid >> 2, lq = tid & 3;
    float acc[4][4] = {};
    for (int k0 = 0; k0 < K; k0 += 16) {
        float4 a4 = *(const float4*)(A + (size_t)(m0 + lr) * K + k0 + lq * 4);
        As[lq * 4 + 0][lr] = a4.x; As[lq * 4 + 1][lr] = a4.y;
        As[lq * 4 + 2][lr] = a4.z; As[lq * 4 + 3][lr] = a4.w;
        float4 b4 = make_float4(0.f, 0.f, 0.f, 0.f);
        if (n0 + lr < N) b4 = *(const float4*)(B + (size_t)(n0 + lr) * K + k0 + lq * 4);
        Bs[lq * 4 + 0][lr] = b4.x; Bs[lq * 4 + 1][lr] = b4.y;
        Bs[lq * 4 + 2][lr] = b4.z; Bs[lq * 4 + 3][lr] = b4.w;
        __syncthreads();
#pragma unroll
        for (int k = 0; k < 16; k++) {
            float4 av = *(const float4*)(&As[k][ty * 4]);
            float4 bv = *(const float4*)(&Bs[k][tx * 4]);
            float avs[4] = {av.x, av.y, av.z, av.w};
            float bvs[4] = {bv.x, bv.y, bv.z, bv.w};
#pragma unroll
            for (int i = 0; i < 4; i++)
#pragma unroll
                for (int jj = 0; jj < 4; jj++)
                    acc[i][jj] = fmaf(avs[i], bvs[jj], acc[i][jj]);
        }
        __syncthreads();
    }
#pragma unroll
    for (int i = 0; i < 4; i++) {
        int m = m0 + ty * 4 + i;
#pragma unroll
        for (int jj = 0; jj < 4; jj++) {
            int n = n0 + tx * 4 + jj;
            if (n < N) C[(size_t)m * N + n] = acc[i][jj] + (bias ? bias[n] : 0.0f);
        }
    }
}

// ---------------- prep: bucket timesteps by age within their reset-segment ----------------
// age[t] = t - (last index r <= t with start[r]==1), or t if none.
// Rows with age k form round k; all rows in a round are independent.
__global__ __launch_bounds__(1024) void prep_kernel(const int* __restrict__ start) {
    __shared__ int sa[2048], sb[2048], sc[2048];
    __shared__ int skmax;
    const int tid = threadIdx.x;
    const int t0 = tid, t1 = tid + 1024;
    if (tid == 0) { g_bar = 0u; skmax = 0; }
    sa[t0] = start[t0] ? t0 : -1;
    sa[t1] = start[t1] ? t1 : -1;
    __syncthreads();
    // Hillis-Steele max-scan (11 iters, ping-pong)
    int* src = sa; int* dst = sb;
    for (int d = 1; d < 2048; d <<= 1) {
        int v0 = src[t0]; if (t0 >= d) v0 = max(v0, src[t0 - d]);
        int v1 = src[t1]; if (t1 >= d) v1 = max(v1, src[t1 - d]);
        dst[t0] = v0; dst[t1] = v1;
        __syncthreads();
        int* tmp = src; src = dst; dst = tmp;
    }
    int r0v = src[t0], r1v = src[t1];
    int age0 = (r0v < 0) ? t0 : t0 - r0v;
    int age1 = (r1v < 0) ? t1 : t1 - r1v;
    __syncthreads();
    // counts per age
    sc[t0] = 0; sc[t1] = 0;
    __syncthreads();
    atomicAdd(&sc[age0], 1);
    atomicAdd(&sc[age1], 1);
    atomicMax(&skmax, max(age0, age1) + 1);
    __syncthreads();
    // inclusive prefix sum of counts (ping-pong sa/sb)
    sa[t0] = sc[t0]; sa[t1] = sc[t1];
    __syncthreads();
    src = sa; dst = sb;
    for (int d = 1; d < 2048; d <<= 1) {
        int v0 = src[t0]; if (t0 >= d) v0 += src[t0 - d];
        int v1 = src[t1]; if (t1 >= d) v1 += src[t1 - d];
        dst[t0] = v0; dst[t1] = v1;
        __syncthreads();
        int* tmp = src; src = dst; dst = tmp;
    }
    if (tid == 0) { g_off[0] = 0; g_kmax = skmax; }
    g_off[t0 + 1] = src[t0];
    g_off[t1 + 1] = src[t1];
    // scatter (cursor per age)
    sc[t0] = 0; sc[t1] = 0;
    __syncthreads();
    int base0 = (age0 == 0) ? 0 : src[age0 - 1];
    g_order[base0 + atomicAdd(&sc[age0], 1)] = t0;
    int base1 = (age1 == 0) ? 0 : src[age1 - 1];
    g_order[base1 + atomicAdd(&sc[age1], 1)] = t1;
}

// ---------------- grid barrier ----------------
__device__ inline void grid_bar(unsigned* barp, unsigned target) {
    __syncthreads();
    if (threadIdx.x == 0) {
        asm volatile("red.release.gpu.global.add.u32 [%0], %1;" :: "l"(barp), "r"(1u) : "memory");
        unsigned v;
        do {
            asm volatile("ld.acquire.gpu.global.u32 %0, [%1];" : "=r"(v) : "l"(barp) : "memory");
        } while (v < target);
    }
    __syncthreads();
}

// ---------------- segment-parallel GRU scan, register-resident whh ----------------
// 128 blocks x 256 threads. Warp w of block b owns h-index j = 8b + w.
__global__ __launch_bounds__(256, 1) void scan_kernel(
    const float* __restrict__ whh, const float* __restrict__ gbn,
    const int* __restrict__ start, const float* __restrict__ state,
    float* __restrict__ out) {
    __shared__ float sH[HD];
    const int tid = threadIdx.x;
    const int w = tid >> 5, lane = tid & 31;
    const int j = blockIdx.x * 8 + w;

    // weights -> registers (once)
    const float4* w4 = (const float4*)whh;
    float4 wr[8], wz[8], wn[8];
#pragma unroll
    for (int q = 0; q < 8; q++) {
        wr[q] = w4[(size_t)(0 * HD + j) * 256 + lane + 32 * q];
        wz[q] = w4[(size_t)(1 * HD + j) * 256 + lane + 32 * q];
        wn[q] = w4[(size_t)(2 * HD + j) * 256 + lane + 32 * q];
    }
    const float bnj = gbn[j];
    float4* sH4s = (float4*)sH;
    const float4* sH4 = (const float4*)sH;
    unsigned* barp = &g_bar;
    const int kmax = g_kmax;
    const int s0 = start[0];
    unsigned epoch = 0;

    // ---- round 0 ----
    // t=0 with start[0]==0: h_in = state (general matvec path)
    if (s0 == 0) {
        sH4s[tid] = ((const float4*)state)[tid];
        __syncthreads();
        float ir = 0.f, iz = 0.f, inn = 0.f;
        if (lane == 0) { ir = g_ig[j]; iz = g_ig[HD + j]; inn = g_ig[2 * HD + j]; }
        float aR = 0.f, aZ = 0.f, aN = 0.f;
#pragma unroll
        for (int q = 0; q < 8; q++) {
            float4 h4 = sH4[lane + 32 * q];
            aR = fmaf(h4.x, wr[q].x, fmaf(h4.y, wr[q].y, fmaf(h4.z, wr[q].z, fmaf(h4.w, wr[q].w, aR))));
            aZ = fmaf(h4.x, wz[q].x, fmaf(h4.y, wz[q].y, fmaf(h4.z, wz[q].z, fmaf(h4.w, wz[q].w, aZ))));
            aN = fmaf(h4.x, wn[q].x, fmaf(h4.y, wn[q].y, fmaf(h4.z, wn[q].z, fmaf(h4.w, wn[q].w, aN))));
        }
#pragma unroll
        for (int off = 16; off; off >>= 1) {
            aR += __shfl_xor_sync(0xffffffffu, aR, off);
            aZ += __shfl_xor_sync(0xffffffffu, aZ, off);
            aN += __shfl_xor_sync(0xffffffffu, aN, off);
        }
        if (lane == 0) {
            float rv = sigmoidf_(ir + aR);
            float uv = sigmoidf_(iz + aZ);
            float nv = tanhf(inn + rv * (aN + bnj));
            float hin = sH[j];
            g_states[j] = nv + uv * (hin - nv);
        }
        __syncthreads();
    }
    // remaining round-0 rows: start[t]==1 -> h_in = 0 -> closed form, lane-parallel
    {
        const int beg = g_off[0], end = g_off[1];
        for (int r = beg + lane; r < end; r += 32) {
            const int t = g_order[r];
            if (t == 0 && s0 == 0) continue;
            const float* igt = g_ig + (size_t)t * (3 * HD);
            float rv = sigmoidf_(igt[j]);
            float uv = sigmoidf_(igt[HD + j]);
            float nv = tanhf(igt[2 * HD + j] + rv * bnj);
            float hnew = nv - uv * nv;
            g_states[(size_t)t * HD + j] = hnew;
            if (t == T_STEPS - 1) out[(size_t)T_STEPS * ACTD + j] = hnew;
        }
    }
    grid_bar(barp, (++epoch) * SCAN_BLOCKS);

    // ---- rounds k >= 1: general matvec path with next-row prefetch ----
    for (int k = 1; k < kmax; k++) {
        const int beg = g_off[k], end = g_off[k + 1];
        int t = g_order[beg];
        float4 nxt = __ldcg((const float4*)(g_states + (size_t)(t - 1) * HD) + tid);
        for (int r = beg; r < end; r++) {
            sH4s[tid] = nxt;
            __syncthreads();
            const int tcur = t;
            if (r + 1 < end) {
                t = g_order[r + 1];
                nxt = __ldcg((const float4*)(g_states + (size_t)(t - 1) * HD) + tid);
            }
            float ir = 0.f, iz = 0.f, inn = 0.f;
            if (lane == 0) {
                const float* igt = g_ig + (size_t)tcur * (3 * HD);
                ir = igt[j]; iz = igt[HD + j]; inn = igt[2 * HD + j];
            }
            float aR = 0.f, aZ = 0.f, aN = 0.f;
#pragma unroll
            for (int q = 0; q < 8; q++) {
                float4 h4 = sH4[lane + 32 * q];
                aR = fmaf(h4.x, wr[q].x, fmaf(h4.y, wr[q].y, fmaf(h4.z, wr[q].z, fmaf(h4.w, wr[q].w, aR))));
                aZ = fmaf(h4.x, wz[q].x, fmaf(h4.y, wz[q].y, fmaf(h4.z, wz[q].z, fmaf(h4.w, wz[q].w, aZ))));
                aN = fmaf(h4.x, wn[q].x, fmaf(h4.y, wn[q].y, fmaf(h4.z, wn[q].z, fmaf(h4.w, wn[q].w, aN))));
            }
#pragma unroll
            for (int off = 16; off; off >>= 1) {
                aR += __shfl_xor_sync(0xffffffffu, aR, off);
                aZ += __shfl_xor_sync(0xffffffffu, aZ, off);
                aN += __shfl_xor_sync(0xffffffffu, aN, off);
            }
            if (lane == 0) {
                float rv = sigmoidf_(ir + aR);
                float uv = sigmoidf_(iz + aZ);
                float nv = tanhf(inn + rv * (aN + bnj));
                float hin = sH[j];
                float hnew = nv + uv * (hin - nv);
                g_states[(size_t)tcur * HD + j] = hnew;
                if (tcur == T_STEPS - 1) out[(size_t)T_STEPS * ACTD + j] = hnew;
            }
            __syncthreads();
        }
        grid_bar(barp, (++epoch) * SCAN_BLOCKS);
    }
}

// ---------------- launch ----------------
extern "C" void kernel_launch(void* const* d_in, const int* in_sizes, int n_in,
                              void* d_out, int out_size) {
    (void)in_sizes; (void)n_in;
    const float* x      = (const float*)d_in[0];
    const float* state  = (const float*)d_in[1];
    const int*   start  = (const int*)d_in[2];
    // d_in[3] = done (unused)
    const float* pre_wm = (const float*)d_in[4];
    const float* pre_ws = (const float*)d_in[5];
    const float* pre_bm = (const float*)d_in[6];
    const float* pre_bs = (const float*)d_in[7];
    const float* wih    = (const float*)d_in[8];
    const float* whh    = (const float*)d_in[9];
    const float* gru_b  = (const float*)d_in[10];
    const float* gru_bn = (const float*)d_in[11];
    const float* p1_wm  = (const float*)d_in[12];
    const float* p1_ws  = (const float*)d_in[13];
    const float* p1_bm  = (const float*)d_in[14];
    const float* p1_bs  = (const float*)d_in[15];
    const float* p2_wm  = (const float*)d_in[16];
    const float* p2_ws  = (const float*)d_in[17];
    const float* p2_bm  = (const float*)d_in[18];
    const float* p2_bs  = (const float*)d_in[19];
    const float* p3_wm  = (const float*)d_in[20];
    const float* p3_ws  = (const float*)d_in[21];
    const float* p3_bm  = (const float*)d_in[22];
    const float* p3_bs  = (const float*)d_in[23];
    float* out = (float*)d_out;
    (void)out_size;

    // nk = jax.random.split(jax.random.key(7), 8) (partitionable)
    unsigned nk[8][2];
    for (int i = 0; i < 8; i++) {
        unsigned a = 0u, b = (unsigned)i;
        tf_block(0u, 7u, a, b);
        nk[i][0] = a; nk[i][1] = b;
    }

    float *preW, *preB, *p1W, *p1B, *p2W, *p2B, *p3W, *p3B, *z, *ig, *states, *y1, *y2;
    cudaGetSymbolAddress((void**)&preW, g_preW);
    cudaGetSymbolAddress((void**)&preB, g_preB);
    cudaGetSymbolAddress((void**)&p1W, g_p1W);
    cudaGetSymbolAddress((void**)&p1B, g_p1B);
    cudaGetSymbolAddress((void**)&p2W, g_p2W);
    cudaGetSymbolAddress((void**)&p2B, g_p2B);
    cudaGetSymbolAddress((void**)&p3W, g_p3W);
    cudaGetSymbolAddress((void**)&p3B, g_p3B);
    cudaGetSymbolAddress((void**)&z, g_z);
    cudaGetSymbolAddress((void**)&ig, g_ig);
    cudaGetSymbolAddress((void**)&states, g_states);
    cudaGetSymbolAddress((void**)&y1, g_y1);
    cudaGetSymbolAddress((void**)&y2, g_y2);

    prep_kernel<<<1, 1024>>>(start);

    // noisy weights/biases: nk order = pre(w,b), p1(w,b), p2(w,b), p3(w,b)
    {
        int n;
        n = MLPD * OBS;  gen_noisy_kernel<<<(n + 255) / 256, 256>>>(pre_wm, pre_ws, preW, n, nk[0][0], nk[0][1]);
        n = MLPD;        gen_noisy_kernel<<<(n + 255) / 256, 256>>>(pre_bm, pre_bs, preB, n, nk[1][0], nk[1][1]);
        n = MLPD * HD;   gen_noisy_kernel<<<(n + 255) / 256, 256>>>(p1_wm, p1_ws, p1W, n, nk[2][0], nk[2][1]);
        n = MLPD;        gen_noisy_kernel<<<(n + 255) / 256, 256>>>(p1_bm, p1_bs, p1B, n, nk[3][0], nk[3][1]);
        n = MLPD * MLPD; gen_noisy_kernel<<<(n + 255) / 256, 256>>>(p2_wm, p2_ws, p2W, n, nk[4][0], nk[4][1]);
        n = MLPD;        gen_noisy_kernel<<<(n + 255) / 256, 256>>>(p2_bm, p2_bs, p2B, n, nk[5][0], nk[5][1]);
        n = ACTD * MLPD; gen_noisy_kernel<<<(n + 255) / 256, 256>>>(p3_wm, p3_ws, p3W, n, nk[6][0], nk[6][1]);
        n = ACTD;        gen_noisy_kernel<<<(n + 255) / 256, 256>>>(p3_bm, p3_bs, p3B, n, nk[7][0], nk[7][1]);
    }

    // z = mish(x @ preW^T + preB)   [2048,1024], K=512
    sgemm128_kernel<<<dim3(MLPD / 128, T_STEPS / 128), 256>>>(x, preW, preB, z, T_STEPS, MLPD, OBS, 1);
    // igates = z @ wih^T + gru_b    [2048,3072], K=1024
    sgemm128_kernel<<<dim3(3 * HD / 128, T_STEPS / 128), 256>>>(z, wih, gru_b, ig, T_STEPS, 3 * HD, MLPD, 0);
    // segment-parallel GRU scan (writes final state into out tail)
    scan_kernel<<<SCAN_BLOCKS, 256>>>(whh, gru_bn, start, state, out);
    // post MLP
    sgemm128_kernel<<<dim3(MLPD / 128, T_STEPS / 128), 256>>>(states, p1W, p1B, y1, T_STEPS, MLPD, HD, 1);
    sgemm128_kernel<<<dim3(MLPD / 128, T_STEPS / 128), 256>>>(y1, p2W, p2B, y2, T_STEPS, MLPD, MLPD, 1);
    // final layer -> d_out[0 : 2048*16]
    sgemm64_kernel<<<dim3(1, T_STEPS / 64), 256>>>(y2, p3W, p3B, out, T_STEPS, ACTD, MLPD);
}

// round 7
// speedup vs baseline: 6.8704x; 1.2284x over previous
#include <cuda_runtime.h>
#include <cuda_bf16.h>
#include <cstdint>

#define T_STEPS 2048
#define OBS 512
#define MLPD 1024
#define HD 1024
#define ACTD 16
#define SCAN_BLOCKS 128

// ---------------- device scratch (no allocations allowed) ----------------
__device__ float g_preW[MLPD * OBS];
__device__ float g_preB[MLPD];
__device__ float g_p1W[MLPD * HD];
__device__ float g_p1B[MLPD];
__device__ float g_p2W[MLPD * MLPD];
__device__ float g_p2B[MLPD];
__device__ float g_p3W[ACTD * MLPD];
__device__ float g_p3B[ACTD];
__device__ float g_z[T_STEPS * MLPD];
__device__ float g_ig[(size_t)T_STEPS * 3 * HD];
__device__ float g_states[(size_t)T_STEPS * HD];
__device__ float g_y1[T_STEPS * MLPD];
__device__ float g_y2[T_STEPS * MLPD];
__device__ __nv_bfloat16 g_ah[T_STEPS * MLPD];
__device__ __nv_bfloat16 g_al[T_STEPS * MLPD];
__device__ __nv_bfloat16 g_bh[3 * HD * MLPD];
__device__ __nv_bfloat16 g_bl[3 * HD * MLPD];
__device__ unsigned g_bar;
__device__ int g_order[T_STEPS];
__device__ int g_off[T_STEPS + 1];
__device__ int g_kmax;

// ---------------- threefry2x32 (matches JAX) ----------------
#define TF_ROUND(x0, x1, R) { x0 += x1; x1 = (x1 << R) | (x1 >> (32 - R)); x1 ^= x0; }

__host__ __device__ inline void tf_block(unsigned k0, unsigned k1, unsigned &x0, unsigned &x1) {
    unsigned ks2 = k0 ^ k1 ^ 0x1BD11BDAu;
    x0 += k0; x1 += k1;
    TF_ROUND(x0, x1, 13) TF_ROUND(x0, x1, 15) TF_ROUND(x0, x1, 26) TF_ROUND(x0, x1, 6)
    x0 += k1; x1 += ks2 + 1u;
    TF_ROUND(x0, x1, 17) TF_ROUND(x0, x1, 29) TF_ROUND(x0, x1, 16) TF_ROUND(x0, x1, 24)
    x0 += ks2; x1 += k0 + 2u;
    TF_ROUND(x0, x1, 13) TF_ROUND(x0, x1, 15) TF_ROUND(x0, x1, 26) TF_ROUND(x0, x1, 6)
    x0 += k0; x1 += k1 + 3u;
    TF_ROUND(x0, x1, 17) TF_ROUND(x0, x1, 29) TF_ROUND(x0, x1, 16) TF_ROUND(x0, x1, 24)
    x0 += k1; x1 += ks2 + 4u;
    TF_ROUND(x0, x1, 13) TF_ROUND(x0, x1, 15) TF_ROUND(x0, x1, 26) TF_ROUND(x0, x1, 6)
    x0 += ks2; x1 += k0 + 5u;
}

// XLA f32 erf_inv (Giles)
__device__ inline float xla_erfinv(float x) {
    float w = -log1pf(-x * x);
    float p;
    if (w < 5.0f) {
        w -= 2.5f;
        p = 2.81022636e-08f;
        p = fmaf(p, w, 3.43273939e-07f);
        p = fmaf(p, w, -3.5233877e-06f);
        p = fmaf(p, w, -4.39150654e-06f);
        p = fmaf(p, w, 0.00021858087f);
        p = fmaf(p, w, -0.00125372503f);
        p = fmaf(p, w, -0.00417768164f);
        p = fmaf(p, w, 0.246640727f);
        p = fmaf(p, w, 1.50140941f);
    } else {
        w = sqrtf(w) - 3.0f;
        p = -0.000200214257f;
        p = fmaf(p, w, 0.000100950558f);
        p = fmaf(p, w, 0.00134934322f);
        p = fmaf(p, w, -0.00367342844f);
        p = fmaf(p, w, 0.00573950773f);
        p = fmaf(p, w, -0.0076224613f);
        p = fmaf(p, w, 0.00943887047f);
        p = fmaf(p, w, 1.00167406f);
        p = fmaf(p, w, 2.83297682f);
    }
    return p * x;
}

__device__ inline float bits_to_normal(unsigned b) {
    float u1 = __uint_as_float((b >> 9) | 0x3f800000u) - 1.0f;
    float v = fmaf(u1, 1.99999994f, -0.99999994f);
    v = fmaxf(v, -0.99999994f);
    return 1.41421356f * xla_erfinv(v);
}

// Partitionable threefry: bits[i] = x0^x1 of block with counter (0, i)
__global__ void gen_noisy_kernel(const float* __restrict__ wm, const float* __restrict__ ws,
                                 float* __restrict__ dst, int n, unsigned k0, unsigned k1) {
    int i = blockIdx.x * blockDim.x + threadIdx.x;
    if (i >= n) return;
    unsigned x0 = 0u, x1 = (unsigned)i;
    tf_block(k0, k1, x0, x1);
    dst[i] = fmaf(ws[i], bits_to_normal(x0 ^ x1), wm[i]);
}

// ---------------- activations ----------------
__device__ inline float mishf(float x) {
    float sp = fmaxf(x, 0.0f) + log1pf(expf(-fabsf(x)));
    return x * tanhf(sp);
}
__device__ inline float sigmoidf_(float x) { return 1.0f / (1.0f + expf(-x)); }

__device__ __forceinline__ uint32_t bfu(__nv_bfloat162 v) {
    return *reinterpret_cast<uint32_t*>(&v);
}

// ---------------- fp32 -> bf16 hi/lo split (n4 = n/4) ----------------
__global__ void conv_split_kernel(const float* __restrict__ src,
                                  __nv_bfloat16* __restrict__ hi,
                                  __nv_bfloat16* __restrict__ lo, int n4) {
    int i = blockIdx.x * blockDim.x + threadIdx.x;
    if (i >= n4) return;
    float4 v = ((const float4*)src)[i];
    __nv_bfloat162 h0, h1, l0, l1;
    h0.x = __float2bfloat16_rn(v.x); h0.y = __float2bfloat16_rn(v.y);
    h1.x = __float2bfloat16_rn(v.z); h1.y = __float2bfloat16_rn(v.w);
    l0.x = __float2bfloat16_rn(v.x - __bfloat162float(h0.x));
    l0.y = __float2bfloat16_rn(v.y - __bfloat162float(h0.y));
    l1.x = __float2bfloat16_rn(v.z - __bfloat162float(h1.x));
    l1.y = __float2bfloat16_rn(v.w - __bfloat162float(h1.y));
    ((uint2*)hi)[i] = make_uint2(bfu(h0), bfu(h1));
    ((uint2*)lo)[i] = make_uint2(bfu(l0), bfu(l1));
}

// ---------------- mma.sync m16n8k16 bf16 wrapper ----------------
__device__ __forceinline__ void mma16816(float* c, const uint32_t* a, const uint32_t* b) {
    asm volatile(
        "mma.sync.aligned.m16n8k16.row.col.f32.bf16.bf16.f32 "
        "{%0,%1,%2,%3}, {%4,%5,%6,%7}, {%8,%9}, {%0,%1,%2,%3};\n"
        : "+f"(c[0]), "+f"(c[1]), "+f"(c[2]), "+f"(c[3])
        : "r"(a[0]), "r"(a[1]), "r"(a[2]), "r"(a[3]), "r"(b[0]), "r"(b[1]));
}

// ============ split-bf16 tensor-core GEMM: C[M,N] = A[M,K] @ B[N,K]^T + bias ============
// CTA tile 128x64, warp tile 32x32, k-chunk 32, double-buffered SMEM (pad 40).
#define APAD 40
#define OFF_AH 0
#define OFF_AL (128 * APAD)
#define OFF_BH (2 * 128 * APAD)
#define OFF_BL (2 * 128 * APAD + 64 * APAD)
#define BUFE (2 * 128 * APAD + 2 * 64 * APAD)
#define MMA_SMEM_BYTES (2 * BUFE * 2)

__global__ __launch_bounds__(256) void mma_gemm_kernel(
    const __nv_bfloat16* __restrict__ Ah, const __nv_bfloat16* __restrict__ Al,
    const __nv_bfloat16* __restrict__ Bh, const __nv_bfloat16* __restrict__ Bl,
    const float* __restrict__ bias, float* __restrict__ C,
    int M, int N, int K, int act) {
    extern __shared__ __nv_bfloat16 smb[];
    const int tid = threadIdx.x;
    const int wid = tid >> 5, lane = tid & 31;
    const int r4 = lane >> 2, lq = lane & 3;
    const int m0 = blockIdx.y * 128, n0 = blockIdx.x * 64;
    const int wm = (wid & 3) * 32, wn = (wid >> 2) * 32;

    float acc[2][4][4] = {};
    const int nch = K >> 5;

    // preload chunk 0
    {
#pragma unroll
        for (int q = 0; q < 4; q++) {
            int i = tid + 256 * q; int r = i >> 3, kq = i & 7;
            size_t go = (size_t)(m0 + r) * K + kq * 4;
            int e = r * APAD + kq * 4;
            *(uint2*)(smb + OFF_AH + e) = *(const uint2*)(Ah + go);
            *(uint2*)(smb + OFF_AL + e) = *(const uint2*)(Al + go);
        }
#pragma unroll
        for (int q = 0; q < 2; q++) {
            int i = tid + 256 * q; int r = i >> 3, kq = i & 7;
            size_t go = (size_t)(n0 + r) * K + kq * 4;
            int e = r * APAD + kq * 4;
            *(uint2*)(smb + OFF_BH + e) = *(const uint2*)(Bh + go);
            *(uint2*)(smb + OFF_BL + e) = *(const uint2*)(Bl + go);
        }
    }
    __syncthreads();

    for (int c = 0; c < nch; c++) {
        uint2 pah[4], pal[4], pbh[2], pbl[2];
        const bool pf = (c + 1 < nch);
        if (pf) {
            const int k0 = (c + 1) << 5;
#pragma unroll
            for (int q = 0; q < 4; q++) {
                int i = tid + 256 * q; int r = i >> 3, kq = i & 7;
                size_t go = (size_t)(m0 + r) * K + k0 + kq * 4;
                pah[q] = *(const uint2*)(Ah + go);
                pal[q] = *(const uint2*)(Al + go);
            }
#pragma unroll
            for (int q = 0; q < 2; q++) {
                int i = tid + 256 * q; int r = i >> 3, kq = i & 7;
                size_t go = (size_t)(n0 + r) * K + k0 + kq * 4;
                pbh[q] = *(const uint2*)(Bh + go);
                pbl[q] = *(const uint2*)(Bl + go);
            }
        }
        const __nv_bfloat16* buf = smb + (c & 1) * BUFE;
#pragma unroll
        for (int ks = 0; ks < 2; ks++) {
            const int kk = ks * 16 + 2 * lq;
            uint32_t afr[2][4], alr[2][4], bfr[4][2], blr[4][2];
#pragma unroll
            for (int am = 0; am < 2; am++) {
                int e = (wm + am * 16 + r4) * APAD + kk;
                afr[am][0] = *(const uint32_t*)(buf + OFF_AH + e);
                afr[am][1] = *(const uint32_t*)(buf + OFF_AH + e + 8 * APAD);
                afr[am][2] = *(const uint32_t*)(buf + OFF_AH + e + 8);
                afr[am][3] = *(const uint32_t*)(buf + OFF_AH + e + 8 * APAD + 8);
                alr[am][0] = *(const uint32_t*)(buf + OFF_AL + e);
                alr[am][1] = *(const uint32_t*)(buf + OFF_AL + e + 8 * APAD);
                alr[am][2] = *(const uint32_t*)(buf + OFF_AL + e + 8);
                alr[am][3] = *(const uint32_t*)(buf + OFF_AL + e + 8 * APAD + 8);
            }
#pragma unroll
            for (int bn = 0; bn < 4; bn++) {
                int e = (wn + bn * 8 + r4) * APAD + kk;
                bfr[bn][0] = *(const uint32_t*)(buf + OFF_BH + e);
                bfr[bn][1] = *(const uint32_t*)(buf + OFF_BH + e + 8);
                blr[bn][0] = *(const uint32_t*)(buf + OFF_BL + e);
                blr[bn][1] = *(const uint32_t*)(buf + OFF_BL + e + 8);
            }
#pragma unroll
            for (int am = 0; am < 2; am++)
#pragma unroll
                for (int bn = 0; bn < 4; bn++) {
                    mma16816(acc[am][bn], afr[am], bfr[bn]);
                    mma16816(acc[am][bn], alr[am], bfr[bn]);
                    mma16816(acc[am][bn], afr[am], blr[bn]);
                }
        }
        if (pf) {
            __nv_bfloat16* nb = smb + ((c + 1) & 1) * BUFE;
#pragma unroll
            for (int q = 0; q < 4; q++) {
                int i = tid + 256 * q; int r = i >> 3, kq = i & 7;
                int e = r * APAD + kq * 4;
                *(uint2*)(nb + OFF_AH + e) = pah[q];
                *(uint2*)(nb + OFF_AL + e) = pal[q];
            }
#pragma unroll
            for (int q = 0; q < 2; q++) {
                int i = tid + 256 * q; int r = i >> 3, kq = i & 7;
                int e = r * APAD + kq * 4;
                *(uint2*)(nb + OFF_BH + e) = pbh[q];
                *(uint2*)(nb + OFF_BL + e) = pbl[q];
            }
        }
        __syncthreads();
    }

    // epilogue: bias + optional mish
#pragma unroll
    for (int am = 0; am < 2; am++) {
        const int row = m0 + wm + am * 16 + r4;
#pragma unroll
        for (int bn = 0; bn < 4; bn++) {
            const int col = n0 + wn + bn * 8 + 2 * lq;
            const float b0 = bias[col], b1 = bias[col + 1];
            float v0 = acc[am][bn][0] + b0, v1 = acc[am][bn][1] + b1;
            float v2 = acc[am][bn][2] + b0, v3 = acc[am][bn][3] + b1;
            if (act) { v0 = mishf(v0); v1 = mishf(v1); v2 = mishf(v2); v3 = mishf(v3); }
            *(float2*)(C + (size_t)row * N + col) = make_float2(v0, v1);
            *(float2*)(C + (size_t)(row + 8) * N + col) = make_float2(v2, v3);
        }
    }
}

// ---------------- small SGEMM (p3, N=16) ----------------
__global__ __launch_bounds__(256) void sgemm64_kernel(
    const float* __restrict__ A, const float* __restrict__ B,
    const float* __restrict__ bias, float* __restrict__ C,
    int M, int N, int K) {
    __shared__ float As[16][64];
    __shared__ float Bs[16][64];
    const int m0 = blockIdx.y * 64;
    const int n0 = blockIdx.x * 64;
    const int tid = threadIdx.x;
    const int tx = tid & 15, ty = tid >> 4;
    const int lr = tid >> 2, lq = tid & 3;
    float acc[4][4] = {};
    for (int k0 = 0; k0 < K; k0 += 16) {
        float4 a4 = *(const float4*)(A + (size_t)(m0 + lr) * K + k0 + lq * 4);
        As[lq * 4 + 0][lr] = a4.x; As[lq * 4 + 1][lr] = a4.y;
        As[lq * 4 + 2][lr] = a4.z; As[lq * 4 + 3][lr] = a4.w;
        float4 b4 = make_float4(0.f, 0.f, 0.f, 0.f);
        if (n0 + lr < N) b4 = *(const float4*)(B + (size_t)(n0 + lr) * K + k0 + lq * 4);
        Bs[lq * 4 + 0][lr] = b4.x; Bs[lq * 4 + 1][lr] = b4.y;
        Bs[lq * 4 + 2][lr] = b4.z; Bs[lq * 4 + 3][lr] = b4.w;
        __syncthreads();
#pragma unroll
        for (int k = 0; k < 16; k++) {
            float4 av = *(const float4*)(&As[k][ty * 4]);
            float4 bv = *(const float4*)(&Bs[k][tx * 4]);
            float avs[4] = {av.x, av.y, av.z, av.w};
            float bvs[4] = {bv.x, bv.y, bv.z, bv.w};
#pragma unroll
            for (int i = 0; i < 4; i++)
#pragma unroll
                for (int jj = 0; jj < 4; jj++)
                    acc[i][jj] = fmaf(avs[i], bvs[jj], acc[i][jj]);
        }
        __syncthreads();
    }
#pragma unroll
    for (int i = 0; i < 4; i++) {
        int m = m0 + ty * 4 + i;
#pragma unroll
        for (int jj = 0; jj < 4; jj++) {
            int n = n0 + tx * 4 + jj;
            if (n < N) C[(size_t)m * N + n] = acc[i][jj] + (bias ? bias[n] : 0.0f);
        }
    }
}

// ---------------- prep: bucket timesteps by age within reset-segment ----------------
__global__ __launch_bounds__(1024) void prep_kernel(const int* __restrict__ start) {
    __shared__ int sa[2048], sb_[2048], sc[2048];
    __shared__ int skmax;
    const int tid = threadIdx.x;
    const int t0 = tid, t1 = tid + 1024;
    if (tid == 0) { g_bar = 0u; skmax = 0; }
    sa[t0] = start[t0] ? t0 : -1;
    sa[t1] = start[t1] ? t1 : -1;
    __syncthreads();
    int* src = sa; int* dst = sb_;
    for (int d = 1; d < 2048; d <<= 1) {
        int v0 = src[t0]; if (t0 >= d) v0 = max(v0, src[t0 - d]);
        int v1 = src[t1]; if (t1 >= d) v1 = max(v1, src[t1 - d]);
        dst[t0] = v0; dst[t1] = v1;
        __syncthreads();
        int* tmp = src; src = dst; dst = tmp;
    }
    int r0v = src[t0], r1v = src[t1];
    int age0 = (r0v < 0) ? t0 : t0 - r0v;
    int age1 = (r1v < 0) ? t1 : t1 - r1v;
    __syncthreads();
    sc[t0] = 0; sc[t1] = 0;
    __syncthreads();
    atomicAdd(&sc[age0], 1);
    atomicAdd(&sc[age1], 1);
    atomicMax(&skmax, max(age0, age1) + 1);
    __syncthreads();
    sa[t0] = sc[t0]; sa[t1] = sc[t1];
    __syncthreads();
    src = sa; dst = sb_;
    for (int d = 1; d < 2048; d <<= 1) {
        int v0 = src[t0]; if (t0 >= d) v0 += src[t0 - d];
        int v1 = src[t1]; if (t1 >= d) v1 += src[t1 - d];
        dst[t0] = v0; dst[t1] = v1;
        __syncthreads();
        int* tmp = src; src = dst; dst = tmp;
    }
    if (tid == 0) { g_off[0] = 0; g_kmax = skmax; }
    g_off[t0 + 1] = src[t0];
    g_off[t1 + 1] = src[t1];
    sc[t0] = 0; sc[t1] = 0;
    __syncthreads();
    int base0 = (age0 == 0) ? 0 : src[age0 - 1];
    g_order[base0 + atomicAdd(&sc[age0], 1)] = t0;
    int base1 = (age1 == 0) ? 0 : src[age1 - 1];
    g_order[base1 + atomicAdd(&sc[age1], 1)] = t1;
}

// ---------------- grid barrier ----------------
__device__ inline void grid_bar(unsigned* barp, unsigned target) {
    __syncthreads();
    if (threadIdx.x == 0) {
        asm volatile("red.release.gpu.global.add.u32 [%0], %1;" :: "l"(barp), "r"(1u) : "memory");
        unsigned v;
        do {
            asm volatile("ld.acquire.gpu.global.u32 %0, [%1];" : "=r"(v) : "l"(barp) : "memory");
        } while (v < target);
    }
    __syncthreads();
}

// ---------------- segment-parallel GRU scan, register-resident whh ----------------
__global__ __launch_bounds__(256, 1) void scan_kernel(
    const float* __restrict__ whh, const float* __restrict__ gbn,
    const int* __restrict__ start, const float* __restrict__ state,
    float* __restrict__ out) {
    __shared__ float sH[HD];
    const int tid = threadIdx.x;
    const int w = tid >> 5, lane = tid & 31;
    const int j = blockIdx.x * 8 + w;

    const float4* w4 = (const float4*)whh;
    float4 wr[8], wz[8], wn[8];
#pragma unroll
    for (int q = 0; q < 8; q++) {
        wr[q] = w4[(size_t)(0 * HD + j) * 256 + lane + 32 * q];
        wz[q] = w4[(size_t)(1 * HD + j) * 256 + lane + 32 * q];
        wn[q] = w4[(size_t)(2 * HD + j) * 256 + lane + 32 * q];
    }
    const float bnj = gbn[j];
    float4* sH4s = (float4*)sH;
    const float4* sH4 = (const float4*)sH;
    unsigned* barp = &g_bar;
    const int kmax = g_kmax;
    const int s0 = start[0];
    unsigned epoch = 0;

    if (s0 == 0) {
        sH4s[tid] = ((const float4*)state)[tid];
        __syncthreads();
        float ir = 0.f, iz = 0.f, inn = 0.f;
        if (lane == 0) { ir = g_ig[j]; iz = g_ig[HD + j]; inn = g_ig[2 * HD + j]; }
        float aR = 0.f, aZ = 0.f, aN = 0.f;
#pragma unroll
        for (int q = 0; q < 8; q++) {
            float4 h4 = sH4[lane + 32 * q];
            aR = fmaf(h4.x, wr[q].x, fmaf(h4.y, wr[q].y, fmaf(h4.z, wr[q].z, fmaf(h4.w, wr[q].w, aR))));
            aZ = fmaf(h4.x, wz[q].x, fmaf(h4.y, wz[q].y, fmaf(h4.z, wz[q].z, fmaf(h4.w, wz[q].w, aZ))));
            aN = fmaf(h4.x, wn[q].x, fmaf(h4.y, wn[q].y, fmaf(h4.z, wn[q].z, fmaf(h4.w, wn[q].w, aN))));
        }
#pragma unroll
        for (int off = 16; off; off >>= 1) {
            aR += __shfl_xor_sync(0xffffffffu, aR, off);
            aZ += __shfl_xor_sync(0xffffffffu, aZ, off);
            aN += __shfl_xor_sync(0xffffffffu, aN, off);
        }
        if (lane == 0) {
            float rv = sigmoidf_(ir + aR);
            float uv = sigmoidf_(iz + aZ);
            float nv = tanhf(inn + rv * (aN + bnj));
            float hin = sH[j];
            g_states[j] = nv + uv * (hin - nv);
        }
        __syncthreads();
    }
    {
        const int beg = g_off[0], end = g_off[1];
        for (int r = beg + lane; r < end; r += 32) {
            const int t = g_order[r];
            if (t == 0 && s0 == 0) continue;
            const float* igt = g_ig + (size_t)t * (3 * HD);
            float rv = sigmoidf_(igt[j]);
            float uv = sigmoidf_(igt[HD + j]);
            float nv = tanhf(igt[2 * HD + j] + rv * bnj);
            float hnew = nv - uv * nv;
            g_states[(size_t)t * HD + j] = hnew;
            if (t == T_STEPS - 1) out[(size_t)T_STEPS * ACTD + j] = hnew;
        }
    }
    grid_bar(barp, (++epoch) * SCAN_BLOCKS);

    for (int k = 1; k < kmax; k++) {
        const int beg = g_off[k], end = g_off[k + 1];
        int t = g_order[beg];
        float4 nxt = __ldcg((const float4*)(g_states + (size_t)(t - 1) * HD) + tid);
        for (int r = beg; r < end; r++) {
            sH4s[tid] = nxt;
            __syncthreads();
            const int tcur = t;
            if (r + 1 < end) {
                t = g_order[r + 1];
                nxt = __ldcg((const float4*)(g_states + (size_t)(t - 1) * HD) + tid);
            }
            float ir = 0.f, iz = 0.f, inn = 0.f;
            if (lane == 0) {
                const float* igt = g_ig + (size_t)tcur * (3 * HD);
                ir = igt[j]; iz = igt[HD + j]; inn = igt[2 * HD + j];
            }
            float aR = 0.f, aZ = 0.f, aN = 0.f;
#pragma unroll
            for (int q = 0; q < 8; q++) {
                float4 h4 = sH4[lane + 32 * q];
                aR = fmaf(h4.x, wr[q].x, fmaf(h4.y, wr[q].y, fmaf(h4.z, wr[q].z, fmaf(h4.w, wr[q].w, aR))));
                aZ = fmaf(h4.x, wz[q].x, fmaf(h4.y, wz[q].y, fmaf(h4.z, wz[q].z, fmaf(h4.w, wz[q].w, aZ))));
                aN = fmaf(h4.x, wn[q].x, fmaf(h4.y, wn[q].y, fmaf(h4.z, wn[q].z, fmaf(h4.w, wn[q].w, aN))));
            }
#pragma unroll
            for (int off = 16; off; off >>= 1) {
                aR += __shfl_xor_sync(0xffffffffu, aR, off);
                aZ += __shfl_xor_sync(0xffffffffu, aZ, off);
                aN += __shfl_xor_sync(0xffffffffu, aN, off);
            }
            if (lane == 0) {
                float rv = sigmoidf_(ir + aR);
                float uv = sigmoidf_(iz + aZ);
                float nv = tanhf(inn + rv * (aN + bnj));
                float hin = sH[j];
                float hnew = nv + uv * (hin - nv);
                g_states[(size_t)tcur * HD + j] = hnew;
                if (tcur == T_STEPS - 1) out[(size_t)T_STEPS * ACTD + j] = hnew;
            }
            __syncthreads();
        }
        grid_bar(barp, (++epoch) * SCAN_BLOCKS);
    }
}

// ---------------- launch ----------------
extern "C" void kernel_launch(void* const* d_in, const int* in_sizes, int n_in,
                              void* d_out, int out_size) {
    (void)in_sizes; (void)n_in;
    const float* x      = (const float*)d_in[0];
    const float* state  = (const float*)d_in[1];
    const int*   start  = (const int*)d_in[2];
    const float* pre_wm = (const float*)d_in[4];
    const float* pre_ws = (const float*)d_in[5];
    const float* pre_bm = (const float*)d_in[6];
    const float* pre_bs = (const float*)d_in[7];
    const float* wih    = (const float*)d_in[8];
    const float* whh    = (const float*)d_in[9];
    const float* gru_b  = (const float*)d_in[10];
    const float* gru_bn = (const float*)d_in[11];
    const float* p1_wm  = (const float*)d_in[12];
    const float* p1_ws  = (const float*)d_in[13];
    const float* p1_bm  = (const float*)d_in[14];
    const float* p1_bs  = (const float*)d_in[15];
    const float* p2_wm  = (const float*)d_in[16];
    const float* p2_ws  = (const float*)d_in[17];
    const float* p2_bm  = (const float*)d_in[18];
    const float* p2_bs  = (const float*)d_in[19];
    const float* p3_wm  = (const float*)d_in[20];
    const float* p3_ws  = (const float*)d_in[21];
    const float* p3_bm  = (const float*)d_in[22];
    const float* p3_bs  = (const float*)d_in[23];
    float* out = (float*)d_out;
    (void)out_size;

    unsigned nk[8][2];
    for (int i = 0; i < 8; i++) {
        unsigned a = 0u, b = (unsigned)i;
        tf_block(0u, 7u, a, b);
        nk[i][0] = a; nk[i][1] = b;
    }

    float *preW, *preB, *p1W, *p1B, *p2W, *p2B, *p3W, *p3B, *z, *ig, *states, *y1, *y2;
    __nv_bfloat16 *ah, *al, *bh, *bl;
    cudaGetSymbolAddress((void**)&preW, g_preW);
    cudaGetSymbolAddress((void**)&preB, g_preB);
    cudaGetSymbolAddress((void**)&p1W, g_p1W);
    cudaGetSymbolAddress((void**)&p1B, g_p1B);
    cudaGetSymbolAddress((void**)&p2W, g_p2W);
    cudaGetSymbolAddress((void**)&p2B, g_p2B);
    cudaGetSymbolAddress((void**)&p3W, g_p3W);
    cudaGetSymbolAddress((void**)&p3B, g_p3B);
    cudaGetSymbolAddress((void**)&z, g_z);
    cudaGetSymbolAddress((void**)&ig, g_ig);
    cudaGetSymbolAddress((void**)&states, g_states);
    cudaGetSymbolAddress((void**)&y1, g_y1);
    cudaGetSymbolAddress((void**)&y2, g_y2);
    cudaGetSymbolAddress((void**)&ah, g_ah);
    cudaGetSymbolAddress((void**)&al, g_al);
    cudaGetSymbolAddress((void**)&bh, g_bh);
    cudaGetSymbolAddress((void**)&bl, g_bl);

    cudaFuncSetAttribute(mma_gemm_kernel, cudaFuncAttributeMaxDynamicSharedMemorySize,
                         MMA_SMEM_BYTES);

    prep_kernel<<<1, 1024>>>(start);

    {
        int n;
        n = MLPD * OBS;  gen_noisy_kernel<<<(n + 255) / 256, 256>>>(pre_wm, pre_ws, preW, n, nk[0][0], nk[0][1]);
        n = MLPD;        gen_noisy_kernel<<<(n + 255) / 256, 256>>>(pre_bm, pre_bs, preB, n, nk[1][0], nk[1][1]);
        n = MLPD * HD;   gen_noisy_kernel<<<(n + 255) / 256, 256>>>(p1_wm, p1_ws, p1W, n, nk[2][0], nk[2][1]);
        n = MLPD;        gen_noisy_kernel<<<(n + 255) / 256, 256>>>(p1_bm, p1_bs, p1B, n, nk[3][0], nk[3][1]);
        n = MLPD * MLPD; gen_noisy_kernel<<<(n + 255) / 256, 256>>>(p2_wm, p2_ws, p2W, n, nk[4][0], nk[4][1]);
        n = MLPD;        gen_noisy_kernel<<<(n + 255) / 256, 256>>>(p2_bm, p2_bs, p2B, n, nk[5][0], nk[5][1]);
        n = ACTD * MLPD; gen_noisy_kernel<<<(n + 255) / 256, 256>>>(p3_wm, p3_ws, p3W, n, nk[6][0], nk[6][1]);
        n = ACTD;        gen_noisy_kernel<<<(n + 255) / 256, 256>>>(p3_bm, p3_bs, p3B, n, nk[7][0], nk[7][1]);
    }

    // GEMM1: z = mish(x @ preW^T + preB)   [2048,1024], K=512
    conv_split_kernel<<<(T_STEPS * OBS / 4 + 255) / 256, 256>>>(x, ah, al, T_STEPS * OBS / 4);
    conv_split_kernel<<<(MLPD * OBS / 4 + 255) / 256, 256>>>(preW, bh, bl, MLPD * OBS / 4);
    mma_gemm_kernel<<<dim3(MLPD / 64, T_STEPS / 128), 256, MMA_SMEM_BYTES>>>(
        ah, al, bh, bl, preB, z, T_STEPS, MLPD, OBS, 1);

    // GEMM2: igates = z @ wih^T + gru_b    [2048,3072], K=1024
    conv_split_kernel<<<(T_STEPS * MLPD / 4 + 255) / 256, 256>>>(z, ah, al, T_STEPS * MLPD / 4);
    conv_split_kernel<<<(3 * HD * MLPD / 4 + 255) / 256, 256>>>(wih, bh, bl, 3 * HD * MLPD / 4);
    mma_gemm_kernel<<<dim3(3 * HD / 64, T_STEPS / 128), 256, MMA_SMEM_BYTES>>>(
        ah, al, bh, bl, gru_b, ig, T_STEPS, 3 * HD, MLPD, 0);

    // segment-parallel GRU scan (writes final state into out tail)
    scan_kernel<<<SCAN_BLOCKS, 256>>>(whh, gru_bn, start, state, out);

    // GEMM3: y1 = mish(states @ p1W^T + p1B)
    conv_split_kernel<<<(T_STEPS * HD / 4 + 255) / 256, 256>>>(states, ah, al, T_STEPS * HD / 4);
    conv_split_kernel<<<(MLPD * HD / 4 + 255) / 256, 256>>>(p1W, bh, bl, MLPD * HD / 4);
    mma_gemm_kernel<<<dim3(MLPD / 64, T_STEPS / 128), 256, MMA_SMEM_BYTES>>>(
        ah, al, bh, bl, p1B, y1, T_STEPS, MLPD, HD, 1);

    // GEMM4: y2 = mish(y1 @ p2W^T + p2B)
    conv_split_kernel<<<(T_STEPS * MLPD / 4 + 255) / 256, 256>>>(y1, ah, al, T_STEPS * MLPD / 4);
    conv_split_kernel<<<(MLPD * MLPD / 4 + 255) / 256, 256>>>(p2W, bh, bl, MLPD * MLPD / 4);
    mma_gemm_kernel<<<dim3(MLPD / 64, T_STEPS / 128), 256, MMA_SMEM_BYTES>>>(
        ah, al, bh, bl, p2B, y2, T_STEPS, MLPD, MLPD, 1);

    // final layer -> d_out[0 : 2048*16]
    sgemm64_kernel<<<dim3(1, T_STEPS / 64), 256>>>(y2, p3W, p3B, out, T_STEPS, ACTD, MLPD);
}

// round 8
// speedup vs baseline: 6.9801x; 1.0160x over previous
#include <cuda_runtime.h>
#include <cuda_bf16.h>
#include <cstdint>

#define T_STEPS 2048
#define OBS 512
#define MLPD 1024
#define HD 1024
#define ACTD 16
#define SCAN_BLOCKS 128

// ---------------- device scratch (no allocations allowed) ----------------
__device__ float g_preB[MLPD];
__device__ float g_p1B[MLPD];
__device__ float g_p2B[MLPD];
__device__ float g_p3W[ACTD * MLPD];
__device__ float g_p3B[ACTD];
__device__ float g_ig[(size_t)T_STEPS * 3 * HD];
__device__ float g_states[(size_t)T_STEPS * HD];
__device__ float g_y2[T_STEPS * MLPD];
__device__ __nv_bfloat16 g_xh[T_STEPS * OBS],  g_xl[T_STEPS * OBS];
__device__ __nv_bfloat16 g_preWh[MLPD * OBS],  g_preWl[MLPD * OBS];
__device__ __nv_bfloat16 g_wihh[3 * HD * MLPD], g_wihl[3 * HD * MLPD];
__device__ __nv_bfloat16 g_p1Wh[MLPD * HD],    g_p1Wl[MLPD * HD];
__device__ __nv_bfloat16 g_p2Wh[MLPD * MLPD],  g_p2Wl[MLPD * MLPD];
__device__ __nv_bfloat16 g_zh[T_STEPS * MLPD], g_zl[T_STEPS * MLPD];
__device__ __nv_bfloat16 g_sth[(size_t)T_STEPS * HD], g_stl[(size_t)T_STEPS * HD];
__device__ __nv_bfloat16 g_y1h[T_STEPS * MLPD], g_y1l[T_STEPS * MLPD];
__device__ unsigned g_bar;
__device__ int g_order[T_STEPS];
__device__ int g_off[T_STEPS + 1];
__device__ int g_kmax;

// ---------------- threefry2x32 (matches JAX) ----------------
#define TF_ROUND(x0, x1, R) { x0 += x1; x1 = (x1 << R) | (x1 >> (32 - R)); x1 ^= x0; }

__host__ __device__ inline void tf_block(unsigned k0, unsigned k1, unsigned &x0, unsigned &x1) {
    unsigned ks2 = k0 ^ k1 ^ 0x1BD11BDAu;
    x0 += k0; x1 += k1;
    TF_ROUND(x0, x1, 13) TF_ROUND(x0, x1, 15) TF_ROUND(x0, x1, 26) TF_ROUND(x0, x1, 6)
    x0 += k1; x1 += ks2 + 1u;
    TF_ROUND(x0, x1, 17) TF_ROUND(x0, x1, 29) TF_ROUND(x0, x1, 16) TF_ROUND(x0, x1, 24)
    x0 += ks2; x1 += k0 + 2u;
    TF_ROUND(x0, x1, 13) TF_ROUND(x0, x1, 15) TF_ROUND(x0, x1, 26) TF_ROUND(x0, x1, 6)
    x0 += k0; x1 += k1 + 3u;
    TF_ROUND(x0, x1, 17) TF_ROUND(x0, x1, 29) TF_ROUND(x0, x1, 16) TF_ROUND(x0, x1, 24)
    x0 += k1; x1 += ks2 + 4u;
    TF_ROUND(x0, x1, 13) TF_ROUND(x0, x1, 15) TF_ROUND(x0, x1, 26) TF_ROUND(x0, x1, 6)
    x0 += ks2; x1 += k0 + 5u;
}

// XLA f32 erf_inv (Giles)
__device__ inline float xla_erfinv(float x) {
    float w = -log1pf(-x * x);
    float p;
    if (w < 5.0f) {
        w -= 2.5f;
        p = 2.81022636e-08f;
        p = fmaf(p, w, 3.43273939e-07f);
        p = fmaf(p, w, -3.5233877e-06f);
        p = fmaf(p, w, -4.39150654e-06f);
        p = fmaf(p, w, 0.00021858087f);
        p = fmaf(p, w, -0.00125372503f);
        p = fmaf(p, w, -0.00417768164f);
        p = fmaf(p, w, 0.246640727f);
        p = fmaf(p, w, 1.50140941f);
    } else {
        w = sqrtf(w) - 3.0f;
        p = -0.000200214257f;
        p = fmaf(p, w, 0.000100950558f);
        p = fmaf(p, w, 0.00134934322f);
        p = fmaf(p, w, -0.00367342844f);
        p = fmaf(p, w, 0.00573950773f);
        p = fmaf(p, w, -0.0076224613f);
        p = fmaf(p, w, 0.00943887047f);
        p = fmaf(p, w, 1.00167406f);
        p = fmaf(p, w, 2.83297682f);
    }
    return p * x;
}

__device__ inline float bits_to_normal(unsigned b) {
    float u1 = __uint_as_float((b >> 9) | 0x3f800000u) - 1.0f;
    float v = fmaf(u1, 1.99999994f, -0.99999994f);
    v = fmaxf(v, -0.99999994f);
    return 1.41421356f * xla_erfinv(v);
}

// Partitionable threefry: bits[i] = x0^x1 of block with counter (0, i)
__global__ void gen_noisy_kernel(const float* __restrict__ wm, const float* __restrict__ ws,
                                 float* __restrict__ dst, int n, unsigned k0, unsigned k1) {
    int i = blockIdx.x * blockDim.x + threadIdx.x;
    if (i >= n) return;
    unsigned x0 = 0u, x1 = (unsigned)i;
    tf_block(k0, k1, x0, x1);
    dst[i] = fmaf(ws[i], bits_to_normal(x0 ^ x1), wm[i]);
}

// noisy weights straight to bf16 hi/lo
__global__ void gen_noisy_w_kernel(const float* __restrict__ wm, const float* __restrict__ ws,
                                   __nv_bfloat16* __restrict__ hi, __nv_bfloat16* __restrict__ lo,
                                   int n, unsigned k0, unsigned k1) {
    int i = blockIdx.x * blockDim.x + threadIdx.x;
    if (i >= n) return;
    unsigned x0 = 0u, x1 = (unsigned)i;
    tf_block(k0, k1, x0, x1);
    float v = fmaf(ws[i], bits_to_normal(x0 ^ x1), wm[i]);
    __nv_bfloat16 h = __float2bfloat16_rn(v);
    hi[i] = h;
    lo[i] = __float2bfloat16_rn(v - __bfloat162float(h));
}

// ---------------- activations ----------------
__device__ inline float mishf(float x) {
    float sp = fmaxf(x, 0.0f) + log1pf(expf(-fabsf(x)));
    return x * tanhf(sp);
}
__device__ inline float sigmoidf_(float x) { return 1.0f / (1.0f + expf(-x)); }

__device__ __forceinline__ uint32_t bfu(__nv_bfloat162 v) {
    return *reinterpret_cast<uint32_t*>(&v);
}

// ---------------- fp32 -> bf16 hi/lo split (n4 = n/4) ----------------
__global__ void conv_split_kernel(const float* __restrict__ src,
                                  __nv_bfloat16* __restrict__ hi,
                                  __nv_bfloat16* __restrict__ lo, int n4) {
    int i = blockIdx.x * blockDim.x + threadIdx.x;
    if (i >= n4) return;
    float4 v = ((const float4*)src)[i];
    __nv_bfloat162 h0, h1, l0, l1;
    h0.x = __float2bfloat16_rn(v.x); h0.y = __float2bfloat16_rn(v.y);
    h1.x = __float2bfloat16_rn(v.z); h1.y = __float2bfloat16_rn(v.w);
    l0.x = __float2bfloat16_rn(v.x - __bfloat162float(h0.x));
    l0.y = __float2bfloat16_rn(v.y - __bfloat162float(h0.y));
    l1.x = __float2bfloat16_rn(v.z - __bfloat162float(h1.x));
    l1.y = __float2bfloat16_rn(v.w - __bfloat162float(h1.y));
    ((uint2*)hi)[i] = make_uint2(bfu(h0), bfu(h1));
    ((uint2*)lo)[i] = make_uint2(bfu(l0), bfu(l1));
}

// ---------------- mma / ldmatrix wrappers ----------------
__device__ __forceinline__ void mma16816(float* c, const uint32_t* a, const uint32_t* b) {
    asm volatile(
        "mma.sync.aligned.m16n8k16.row.col.f32.bf16.bf16.f32 "
        "{%0,%1,%2,%3}, {%4,%5,%6,%7}, {%8,%9}, {%0,%1,%2,%3};\n"
        : "+f"(c[0]), "+f"(c[1]), "+f"(c[2]), "+f"(c[3])
        : "r"(a[0]), "r"(a[1]), "r"(a[2]), "r"(a[3]), "r"(b[0]), "r"(b[1]));
}
__device__ __forceinline__ void ldsm4(uint32_t& r0, uint32_t& r1, uint32_t& r2, uint32_t& r3,
                                      uint32_t addr) {
    asm volatile("ldmatrix.sync.aligned.m8n8.x4.shared.b16 {%0,%1,%2,%3}, [%4];"
                 : "=r"(r0), "=r"(r1), "=r"(r2), "=r"(r3) : "r"(addr));
}
__device__ __forceinline__ uint32_t smem_u32(const void* p) {
    uint32_t a;
    asm("{ .reg .u64 t; cvta.to.shared.u64 t, %1; cvt.u32.u64 %0, t; }" : "=r"(a) : "l"(p));
    return a;
}

// ============ split-bf16 tensor-core GEMM: C[M,N] = A[M,K] @ B[N,K]^T + bias ============
// CTA tile 128x128, 8 warps (2m x 4n), warp tile 64x32, k-chunk 32, double-buffered,
// row pitch 40 bf16 (80B) -> conflict-free LDSM.
#define PADE 40
#define OFF_AH 0
#define OFF_AL (128 * PADE)
#define OFF_BH (2 * 128 * PADE)
#define OFF_BL (3 * 128 * PADE)
#define BUFE (4 * 128 * PADE)
#define MMA_SMEM_BYTES (2 * BUFE * 2)

__global__ __launch_bounds__(256) void mma_gemm_kernel(
    const __nv_bfloat16* __restrict__ Ah, const __nv_bfloat16* __restrict__ Al,
    const __nv_bfloat16* __restrict__ Bh, const __nv_bfloat16* __restrict__ Bl,
    const float* __restrict__ bias, float* __restrict__ C,
    __nv_bfloat16* __restrict__ Ch, __nv_bfloat16* __restrict__ Cl,
    int M, int N, int K, int act, int osplit) {
    extern __shared__ __nv_bfloat16 smb[];
    const uint32_t sbase = smem_u32(smb);
    const int tid = threadIdx.x;
    const int wid = tid >> 5, lane = tid & 31;
    const int r4 = lane >> 2, lq = lane & 3;
    const int m0 = blockIdx.y * 128, n0 = blockIdx.x * 128;
    const int wm = (wid & 1) * 64, wn = (wid >> 1) * 32;

    // lane-dependent LDSM offsets (elements)
    const int aro = lane & 15, ako = (lane >> 4) << 3;
    const int bro = (lane & 7) + ((lane >> 4) << 3), bko = ((lane >> 3) & 1) << 3;

    float acc[4][4][4] = {};
    const int nch = K >> 5;

    // preload chunk 0
#pragma unroll
    for (int q = 0; q < 4; q++) {
        int i = tid + 256 * q; int r = i >> 3, kq = i & 7;
        int e = r * PADE + kq * 4;
        *(uint2*)(smb + OFF_AH + e) = *(const uint2*)(Ah + (size_t)(m0 + r) * K + kq * 4);
        *(uint2*)(smb + OFF_AL + e) = *(const uint2*)(Al + (size_t)(m0 + r) * K + kq * 4);
        *(uint2*)(smb + OFF_BH + e) = *(const uint2*)(Bh + (size_t)(n0 + r) * K + kq * 4);
        *(uint2*)(smb + OFF_BL + e) = *(const uint2*)(Bl + (size_t)(n0 + r) * K + kq * 4);
    }
    __syncthreads();

    for (int c = 0; c < nch; c++) {
        uint2 pah[4], pal[4], pbh[4], pbl[4];
        const bool pf = (c + 1 < nch);
        if (pf) {
            const int k0 = (c + 1) << 5;
#pragma unroll
            for (int q = 0; q < 4; q++) {
                int i = tid + 256 * q; int r = i >> 3, kq = i & 7;
                pah[q] = *(const uint2*)(Ah + (size_t)(m0 + r) * K + k0 + kq * 4);
                pal[q] = *(const uint2*)(Al + (size_t)(m0 + r) * K + k0 + kq * 4);
                pbh[q] = *(const uint2*)(Bh + (size_t)(n0 + r) * K + k0 + kq * 4);
                pbl[q] = *(const uint2*)(Bl + (size_t)(n0 + r) * K + k0 + kq * 4);
            }
        }
        const uint32_t bb = sbase + (uint32_t)((c & 1) * BUFE * 2);
#pragma unroll
        for (int ks = 0; ks < 2; ks++) {
            uint32_t ahf[4][4], alf[4][4], bhf[4][2], blf[4][2];
#pragma unroll
            for (int am = 0; am < 4; am++) {
                uint32_t ar = (uint32_t)((wm + am * 16 + aro) * PADE + ks * 16 + ako) * 2;
                ldsm4(ahf[am][0], ahf[am][1], ahf[am][2], ahf[am][3], bb + OFF_AH * 2 + ar);
                ldsm4(alf[am][0], alf[am][1], alf[am][2], alf[am][3], bb + OFF_AL * 2 + ar);
            }
#pragma unroll
            for (int nb = 0; nb < 2; nb++) {
                uint32_t br = (uint32_t)((wn + nb * 16 + bro) * PADE + ks * 16 + bko) * 2;
                ldsm4(bhf[nb * 2][0], bhf[nb * 2][1], bhf[nb * 2 + 1][0], bhf[nb * 2 + 1][1],
                      bb + OFF_BH * 2 + br);
                ldsm4(blf[nb * 2][0], blf[nb * 2][1], blf[nb * 2 + 1][0], blf[nb * 2 + 1][1],
                      bb + OFF_BL * 2 + br);
            }
#pragma unroll
            for (int am = 0; am < 4; am++)
#pragma unroll
                for (int bn = 0; bn < 4; bn++) {
                    mma16816(acc[am][bn], ahf[am], bhf[bn]);
                    mma16816(acc[am][bn], alf[am], bhf[bn]);
                    mma16816(acc[am][bn], ahf[am], blf[bn]);
                }
        }
        if (pf) {
            __nv_bfloat16* nb = smb + ((c + 1) & 1) * BUFE;
#pragma unroll
            for (int q = 0; q < 4; q++) {
                int i = tid + 256 * q; int r = i >> 3, kq = i & 7;
                int e = r * PADE + kq * 4;
                *(uint2*)(nb + OFF_AH + e) = pah[q];
                *(uint2*)(nb + OFF_AL + e) = pal[q];
                *(uint2*)(nb + OFF_BH + e) = pbh[q];
                *(uint2*)(nb + OFF_BL + e) = pbl[q];
            }
        }
        __syncthreads();
    }

    // epilogue: bias + optional mish; fp32 or bf16-split output
#pragma unroll
    for (int am = 0; am < 4; am++) {
        const int row = m0 + wm + am * 16 + r4;
#pragma unroll
        for (int bn = 0; bn < 4; bn++) {
            const int col = n0 + wn + bn * 8 + 2 * lq;
            const float b0 = bias[col], b1 = bias[col + 1];
            float v0 = acc[am][bn][0] + b0, v1 = acc[am][bn][1] + b1;
            float v2 = acc[am][bn][2] + b0, v3 = acc[am][bn][3] + b1;
            if (act) { v0 = mishf(v0); v1 = mishf(v1); v2 = mishf(v2); v3 = mishf(v3); }
            if (osplit) {
                __nv_bfloat162 h01, h23, l01, l23;
                h01.x = __float2bfloat16_rn(v0); h01.y = __float2bfloat16_rn(v1);
                h23.x = __float2bfloat16_rn(v2); h23.y = __float2bfloat16_rn(v3);
                l01.x = __float2bfloat16_rn(v0 - __bfloat162float(h01.x));
                l01.y = __float2bfloat16_rn(v1 - __bfloat162float(h01.y));
                l23.x = __float2bfloat16_rn(v2 - __bfloat162float(h23.x));
                l23.y = __float2bfloat16_rn(v3 - __bfloat162float(h23.y));
                *(uint32_t*)(Ch + (size_t)row * N + col) = bfu(h01);
                *(uint32_t*)(Cl + (size_t)row * N + col) = bfu(l01);
                *(uint32_t*)(Ch + (size_t)(row + 8) * N + col) = bfu(h23);
                *(uint32_t*)(Cl + (size_t)(row + 8) * N + col) = bfu(l23);
            } else {
                *(float2*)(C + (size_t)row * N + col) = make_float2(v0, v1);
                *(float2*)(C + (size_t)(row + 8) * N + col) = make_float2(v2, v3);
            }
        }
    }
}

// ---------------- small SGEMM (p3, N=16) ----------------
__global__ __launch_bounds__(256) void sgemm64_kernel(
    const float* __restrict__ A, const float* __restrict__ B,
    const float* __restrict__ bias, float* __restrict__ C,
    int M, int N, int K) {
    __shared__ float As[16][64];
    __shared__ float Bs[16][64];
    const int m0 = blockIdx.y * 64;
    const int n0 = blockIdx.x * 64;
    const int tid = threadIdx.x;
    const int tx = tid & 15, ty = tid >> 4;
    const int lr = tid >> 2, lq = tid & 3;
    float acc[4][4] = {};
    for (int k0 = 0; k0 < K; k0 += 16) {
        float4 a4 = *(const float4*)(A + (size_t)(m0 + lr) * K + k0 + lq * 4);
        As[lq * 4 + 0][lr] = a4.x; As[lq * 4 + 1][lr] = a4.y;
        As[lq * 4 + 2][lr] = a4.z; As[lq * 4 + 3][lr] = a4.w;
        float4 b4 = make_float4(0.f, 0.f, 0.f, 0.f);
        if (n0 + lr < N) b4 = *(const float4*)(B + (size_t)(n0 + lr) * K + k0 + lq * 4);
        Bs[lq * 4 + 0][lr] = b4.x; Bs[lq * 4 + 1][lr] = b4.y;
        Bs[lq * 4 + 2][lr] = b4.z; Bs[lq * 4 + 3][lr] = b4.w;
        __syncthreads();
#pragma unroll
        for (int k = 0; k < 16; k++) {
            float4 av = *(const float4*)(&As[k][ty * 4]);
            float4 bv = *(const float4*)(&Bs[k][tx * 4]);
            float avs[4] = {av.x, av.y, av.z, av.w};
            float bvs[4] = {bv.x, bv.y, bv.z, bv.w};
#pragma unroll
            for (int i = 0; i < 4; i++)
#pragma unroll
                for (int jj = 0; jj < 4; jj++)
                    acc[i][jj] = fmaf(avs[i], bvs[jj], acc[i][jj]);
        }
        __syncthreads();
    }
#pragma unroll
    for (int i = 0; i < 4; i++) {
        int m = m0 + ty * 4 + i;
#pragma unroll
        for (int jj = 0; jj < 4; jj++) {
            int n = n0 + tx * 4 + jj;
            if (n < N) C[(size_t)m * N + n] = acc[i][jj] + (bias ? bias[n] : 0.0f);
        }
    }
}

// ---------------- prep: bucket timesteps by age within reset-segment ----------------
__global__ __launch_bounds__(1024) void prep_kernel(const int* __restrict__ start) {
    __shared__ int sa[2048], sb_[2048], sc[2048];
    __shared__ int skmax;
    const int tid = threadIdx.x;
    const int t0 = tid, t1 = tid + 1024;
    if (tid == 0) { g_bar = 0u; skmax = 0; }
    sa[t0] = start[t0] ? t0 : -1;
    sa[t1] = start[t1] ? t1 : -1;
    __syncthreads();
    int* src = sa; int* dst = sb_;
    for (int d = 1; d < 2048; d <<= 1) {
        int v0 = src[t0]; if (t0 >= d) v0 = max(v0, src[t0 - d]);
        int v1 = src[t1]; if (t1 >= d) v1 = max(v1, src[t1 - d]);
        dst[t0] = v0; dst[t1] = v1;
        __syncthreads();
        int* tmp = src; src = dst; dst = tmp;
    }
    int r0v = src[t0], r1v = src[t1];
    int age0 = (r0v < 0) ? t0 : t0 - r0v;
    int age1 = (r1v < 0) ? t1 : t1 - r1v;
    __syncthreads();
    sc[t0] = 0; sc[t1] = 0;
    __syncthreads();
    atomicAdd(&sc[age0], 1);
    atomicAdd(&sc[age1], 1);
    atomicMax(&skmax, max(age0, age1) + 1);
    __syncthreads();
    sa[t0] = sc[t0]; sa[t1] = sc[t1];
    __syncthreads();
    src = sa; dst = sb_;
    for (int d = 1; d < 2048; d <<= 1) {
        int v0 = src[t0]; if (t0 >= d) v0 += src[t0 - d];
        int v1 = src[t1]; if (t1 >= d) v1 += src[t1 - d];
        dst[t0] = v0; dst[t1] = v1;
        __syncthreads();
        int* tmp = src; src = dst; dst = tmp;
    }
    if (tid == 0) { g_off[0] = 0; g_kmax = skmax; }
    g_off[t0 + 1] = src[t0];
    g_off[t1 + 1] = src[t1];
    sc[t0] = 0; sc[t1] = 0;
    __syncthreads();
    int base0 = (age0 == 0) ? 0 : src[age0 - 1];
    g_order[base0 + atomicAdd(&sc[age0], 1)] = t0;
    int base1 = (age1 == 0) ? 0 : src[age1 - 1];
    g_order[base1 + atomicAdd(&sc[age1], 1)] = t1;
}

// ---------------- grid barrier ----------------
__device__ inline void grid_bar(unsigned* barp, unsigned target) {
    __syncthreads();
    if (threadIdx.x == 0) {
        asm volatile("red.release.gpu.global.add.u32 [%0], %1;" :: "l"(barp), "r"(1u) : "memory");
        unsigned v;
        do {
            asm volatile("ld.acquire.gpu.global.u32 %0, [%1];" : "=r"(v) : "l"(barp) : "memory");
        } while (v < target);
    }
    __syncthreads();
}

__device__ __forceinline__ void store_state(int t, int j, float hnew, float* out) {
    g_states[(size_t)t * HD + j] = hnew;
    __nv_bfloat16 h = __float2bfloat16_rn(hnew);
    g_sth[(size_t)t * HD + j] = h;
    g_stl[(size_t)t * HD + j] = __float2bfloat16_rn(hnew - __bfloat162float(h));
    if (t == T_STEPS - 1) out[(size_t)T_STEPS * ACTD + j] = hnew;
}

// ---------------- segment-parallel GRU scan, register-resident whh ----------------
__global__ __launch_bounds__(256, 1) void scan_kernel(
    const float* __restrict__ whh, const float* __restrict__ gbn,
    const int* __restrict__ start, const float* __restrict__ state,
    float* __restrict__ out) {
    __shared__ float sH[HD];
    const int tid = threadIdx.x;
    const int w = tid >> 5, lane = tid & 31;
    const int j = blockIdx.x * 8 + w;

    const float4* w4 = (const float4*)whh;
    float4 wr[8], wz[8], wn[8];
#pragma unroll
    for (int q = 0; q < 8; q++) {
        wr[q] = w4[(size_t)(0 * HD + j) * 256 + lane + 32 * q];
        wz[q] = w4[(size_t)(1 * HD + j) * 256 + lane + 32 * q];
        wn[q] = w4[(size_t)(2 * HD + j) * 256 + lane + 32 * q];
    }
    const float bnj = gbn[j];
    float4* sH4s = (float4*)sH;
    const float4* sH4 = (const float4*)sH;
    unsigned* barp = &g_bar;
    const int kmax = g_kmax;
    const int s0 = start[0];
    unsigned epoch = 0;

    if (s0 == 0) {
        sH4s[tid] = ((const float4*)state)[tid];
        __syncthreads();
        float ir = 0.f, iz = 0.f, inn = 0.f;
        if (lane == 0) { ir = g_ig[j]; iz = g_ig[HD + j]; inn = g_ig[2 * HD + j]; }
        float aR = 0.f, aZ = 0.f, aN = 0.f;
#pragma unroll
        for (int q = 0; q < 8; q++) {
            float4 h4 = sH4[lane + 32 * q];
            aR = fmaf(h4.x, wr[q].x, fmaf(h4.y, wr[q].y, fmaf(h4.z, wr[q].z, fmaf(h4.w, wr[q].w, aR))));
            aZ = fmaf(h4.x, wz[q].x, fmaf(h4.y, wz[q].y, fmaf(h4.z, wz[q].z, fmaf(h4.w, wz[q].w, aZ))));
            aN = fmaf(h4.x, wn[q].x, fmaf(h4.y, wn[q].y, fmaf(h4.z, wn[q].z, fmaf(h4.w, wn[q].w, aN))));
        }
#pragma unroll
        for (int off = 16; off; off >>= 1) {
            aR += __shfl_xor_sync(0xffffffffu, aR, off);
            aZ += __shfl_xor_sync(0xffffffffu, aZ, off);
            aN += __shfl_xor_sync(0xffffffffu, aN, off);
        }
        if (lane == 0) {
            float rv = sigmoidf_(ir + aR);
            float uv = sigmoidf_(iz + aZ);
            float nv = tanhf(inn + rv * (aN + bnj));
            float hin = sH[j];
            store_state(0, j, nv + uv * (hin - nv), out);
        }
        __syncthreads();
    }
    {
        const int beg = g_off[0], end = g_off[1];
        for (int r = beg + lane; r < end; r += 32) {
            const int t = g_order[r];
            if (t == 0 && s0 == 0) continue;
            const float* igt = g_ig + (size_t)t * (3 * HD);
            float rv = sigmoidf_(igt[j]);
            float uv = sigmoidf_(igt[HD + j]);
            float nv = tanhf(igt[2 * HD + j] + rv * bnj);
            store_state(t, j, nv - uv * nv, out);
        }
    }
    grid_bar(barp, (++epoch) * SCAN_BLOCKS);

    for (int k = 1; k < kmax; k++) {
        const int beg = g_off[k], end = g_off[k + 1];
        int t = g_order[beg];
        float4 nxt = __ldcg((const float4*)(g_states + (size_t)(t - 1) * HD) + tid);
        for (int r = beg; r < end; r++) {
            sH4s[tid] = nxt;
            __syncthreads();
            const int tcur = t;
            if (r + 1 < end) {
                t = g_order[r + 1];
                nxt = __ldcg((const float4*)(g_states + (size_t)(t - 1) * HD) + tid);
            }
            float ir = 0.f, iz = 0.f, inn = 0.f;
            if (lane == 0) {
                const float* igt = g_ig + (size_t)tcur * (3 * HD);
                ir = igt[j]; iz = igt[HD + j]; inn = igt[2 * HD + j];
            }
            float aR = 0.f, aZ = 0.f, aN = 0.f;
#pragma unroll
            for (int q = 0; q < 8; q++) {
                float4 h4 = sH4[lane + 32 * q];
                aR = fmaf(h4.x, wr[q].x, fmaf(h4.y, wr[q].y, fmaf(h4.z, wr[q].z, fmaf(h4.w, wr[q].w, aR))));
                aZ = fmaf(h4.x, wz[q].x, fmaf(h4.y, wz[q].y, fmaf(h4.z, wz[q].z, fmaf(h4.w, wz[q].w, aZ))));
                aN = fmaf(h4.x, wn[q].x, fmaf(h4.y, wn[q].y, fmaf(h4.z, wn[q].z, fmaf(h4.w, wn[q].w, aN))));
            }
#pragma unroll
            for (int off = 16; off; off >>= 1) {
                aR += __shfl_xor_sync(0xffffffffu, aR, off);
                aZ += __shfl_xor_sync(0xffffffffu, aZ, off);
                aN += __shfl_xor_sync(0xffffffffu, aN, off);
            }
            if (lane == 0) {
                float rv = sigmoidf_(ir + aR);
                float uv = sigmoidf_(iz + aZ);
                float nv = tanhf(inn + rv * (aN + bnj));
                float hin = sH[j];
                store_state(tcur, j, nv + uv * (hin - nv), out);
            }
            __syncthreads();
        }
        grid_bar(barp, (++epoch) * SCAN_BLOCKS);
    }
}

// ---------------- launch ----------------
extern "C" void kernel_launch(void* const* d_in, const int* in_sizes, int n_in,
                              void* d_out, int out_size) {
    (void)in_sizes; (void)n_in;
    const float* x      = (const float*)d_in[0];
    const float* state  = (const float*)d_in[1];
    const int*   start  = (const int*)d_in[2];
    const float* pre_wm = (const float*)d_in[4];
    const float* pre_ws = (const float*)d_in[5];
    const float* pre_bm = (const float*)d_in[6];
    const float* pre_bs = (const float*)d_in[7];
    const float* wih    = (const float*)d_in[8];
    const float* whh    = (const float*)d_in[9];
    const float* gru_b  = (const float*)d_in[10];
    const float* gru_bn = (const float*)d_in[11];
    const float* p1_wm  = (const float*)d_in[12];
    const float* p1_ws  = (const float*)d_in[13];
    const float* p1_bm  = (const float*)d_in[14];
    const float* p1_bs  = (const float*)d_in[15];
    const float* p2_wm  = (const float*)d_in[16];
    const float* p2_ws  = (const float*)d_in[17];
    const float* p2_bm  = (const float*)d_in[18];
    const float* p2_bs  = (const float*)d_in[19];
    const float* p3_wm  = (const float*)d_in[20];
    const float* p3_ws  = (const float*)d_in[21];
    const float* p3_bm  = (const float*)d_in[22];
    const float* p3_bs  = (const float*)d_in[23];
    float* out = (float*)d_out;
    (void)out_size;

    unsigned nk[8][2];
    for (int i = 0; i < 8; i++) {
        unsigned a = 0u, b = (unsigned)i;
        tf_block(0u, 7u, a, b);
        nk[i][0] = a; nk[i][1] = b;
    }

    float *preB, *p1B, *p2B, *p3W, *p3B, *ig, *states, *y2;
    __nv_bfloat16 *xh, *xl, *preWh, *preWl, *wihh, *wihl, *p1Wh, *p1Wl, *p2Wh, *p2Wl;
    __nv_bfloat16 *zh, *zl, *sth, *stl, *y1h, *y1l;
    cudaGetSymbolAddress((void**)&preB, g_preB);
    cudaGetSymbolAddress((void**)&p1B, g_p1B);
    cudaGetSymbolAddress((void**)&p2B, g_p2B);
    cudaGetSymbolAddress((void**)&p3W, g_p3W);
    cudaGetSymbolAddress((void**)&p3B, g_p3B);
    cudaGetSymbolAddress((void**)&ig, g_ig);
    cudaGetSymbolAddress((void**)&states, g_states);
    cudaGetSymbolAddress((void**)&y2, g_y2);
    cudaGetSymbolAddress((void**)&xh, g_xh);
    cudaGetSymbolAddress((void**)&xl, g_xl);
    cudaGetSymbolAddress((void**)&preWh, g_preWh);
    cudaGetSymbolAddress((void**)&preWl, g_preWl);
    cudaGetSymbolAddress((void**)&wihh, g_wihh);
    cudaGetSymbolAddress((void**)&wihl, g_wihl);
    cudaGetSymbolAddress((void**)&p1Wh, g_p1Wh);
    cudaGetSymbolAddress((void**)&p1Wl, g_p1Wl);
    cudaGetSymbolAddress((void**)&p2Wh, g_p2Wh);
    cudaGetSymbolAddress((void**)&p2Wl, g_p2Wl);
    cudaGetSymbolAddress((void**)&zh, g_zh);
    cudaGetSymbolAddress((void**)&zl, g_zl);
    cudaGetSymbolAddress((void**)&sth, g_sth);
    cudaGetSymbolAddress((void**)&stl, g_stl);
    cudaGetSymbolAddress((void**)&y1h, g_y1h);
    cudaGetSymbolAddress((void**)&y1l, g_y1l);

    cudaFuncSetAttribute(mma_gemm_kernel, cudaFuncAttributeMaxDynamicSharedMemorySize,
                         MMA_SMEM_BYTES);

    prep_kernel<<<1, 1024>>>(start);

    // noisy weights/biases: nk order = pre(w,b), p1(w,b), p2(w,b), p3(w,b)
    {
        int n;
        n = MLPD * OBS;  gen_noisy_w_kernel<<<(n + 255) / 256, 256>>>(pre_wm, pre_ws, preWh, preWl, n, nk[0][0], nk[0][1]);
        n = MLPD;        gen_noisy_kernel<<<(n + 255) / 256, 256>>>(pre_bm, pre_bs, preB, n, nk[1][0], nk[1][1]);
        n = MLPD * HD;   gen_noisy_w_kernel<<<(n + 255) / 256, 256>>>(p1_wm, p1_ws, p1Wh, p1Wl, n, nk[2][0], nk[2][1]);
        n = MLPD;        gen_noisy_kernel<<<(n + 255) / 256, 256>>>(p1_bm, p1_bs, p1B, n, nk[3][0], nk[3][1]);
        n = MLPD * MLPD; gen_noisy_w_kernel<<<(n + 255) / 256, 256>>>(p2_wm, p2_ws, p2Wh, p2Wl, n, nk[4][0], nk[4][1]);
        n = MLPD;        gen_noisy_kernel<<<(n + 255) / 256, 256>>>(p2_bm, p2_bs, p2B, n, nk[5][0], nk[5][1]);
        n = ACTD * MLPD; gen_noisy_kernel<<<(n + 255) / 256, 256>>>(p3_wm, p3_ws, p3W, n, nk[6][0], nk[6][1]);
        n = ACTD;        gen_noisy_kernel<<<(n + 255) / 256, 256>>>(p3_bm, p3_bs, p3B, n, nk[7][0], nk[7][1]);
    }

    // splits for non-noisy operands
    conv_split_kernel<<<(T_STEPS * OBS / 4 + 255) / 256, 256>>>(x, xh, xl, T_STEPS * OBS / 4);
    conv_split_kernel<<<(3 * HD * MLPD / 4 + 255) / 256, 256>>>(wih, wihh, wihl, 3 * HD * MLPD / 4);

    // GEMM1: z = mish(x @ preW^T + preB) -> zh/zl   [2048,1024], K=512
    mma_gemm_kernel<<<dim3(MLPD / 128, T_STEPS / 128), 256, MMA_SMEM_BYTES>>>(
        xh, xl, preWh, preWl, preB, nullptr, zh, zl, T_STEPS, MLPD, OBS, 1, 1);

    // GEMM2: igates = z @ wih^T + gru_b -> fp32     [2048,3072], K=1024
    mma_gemm_kernel<<<dim3(3 * HD / 128, T_STEPS / 128), 256, MMA_SMEM_BYTES>>>(
        zh, zl, wihh, wihl, gru_b, ig, nullptr, nullptr, T_STEPS, 3 * HD, MLPD, 0, 0);

    // segment-parallel GRU scan (writes states fp32 + h/l, final state into out tail)
    scan_kernel<<<SCAN_BLOCKS, 256>>>(whh, gru_bn, start, state, out);

    // GEMM3: y1 = mish(states @ p1W^T + p1B) -> y1h/y1l
    mma_gemm_kernel<<<dim3(MLPD / 128, T_STEPS / 128), 256, MMA_SMEM_BYTES>>>(
        sth, stl, p1Wh, p1Wl, p1B, nullptr, y1h, y1l, T_STEPS, MLPD, HD, 1, 1);

    // GEMM4: y2 = mish(y1 @ p2W^T + p2B) -> fp32
    mma_gemm_kernel<<<dim3(MLPD / 128, T_STEPS / 128), 256, MMA_SMEM_BYTES>>>(
        y1h, y1l, p2Wh, p2Wl, p2B, y2, nullptr, nullptr, T_STEPS, MLPD, MLPD, 1, 0);

    // final layer -> d_out[0 : 2048*16]
    sgemm64_kernel<<<dim3(1, T_STEPS / 64), 256>>>(y2, p3W, p3B, out, T_STEPS, ACTD, MLPD);
}

// round 9
// speedup vs baseline: 7.1522x; 1.0247x over previous
#include <cuda_runtime.h>
#include <cuda_fp16.h>
#include <cstdint>

#define T_STEPS 2048
#define OBS 512
#define MLPD 1024
#define HD 1024
#define ACTD 16
#define SCAN_BLOCKS 128

// ---------------- device scratch (no allocations allowed) ----------------
__device__ float g_preB[MLPD];
__device__ float g_p1B[MLPD];
__device__ float g_p2B[MLPD];
__device__ float g_p3W[ACTD * MLPD];
__device__ float g_p3B[ACTD];
__device__ float g_ig[(size_t)T_STEPS * 3 * HD];
__device__ float g_states[(size_t)T_STEPS * HD];
__device__ float g_y2[T_STEPS * MLPD];
__device__ __half g_xh[T_STEPS * OBS],  g_xl[T_STEPS * OBS];
__device__ __half g_preWh[MLPD * OBS],  g_preWl[MLPD * OBS];
__device__ __half g_wihh[3 * HD * MLPD], g_wihl[3 * HD * MLPD];
__device__ __half g_p1Wh[MLPD * HD],    g_p1Wl[MLPD * HD];
__device__ __half g_p2Wh[MLPD * MLPD],  g_p2Wl[MLPD * MLPD];
__device__ __half g_zh[T_STEPS * MLPD], g_zl[T_STEPS * MLPD];
__device__ __half g_sth[(size_t)T_STEPS * HD], g_stl[(size_t)T_STEPS * HD];
__device__ __half g_y1h[T_STEPS * MLPD], g_y1l[T_STEPS * MLPD];
__device__ unsigned g_bar;
__device__ int g_order[T_STEPS];
__device__ int g_off[T_STEPS + 1];
__device__ int g_kmax;

// ---------------- threefry2x32 (matches JAX) ----------------
#define TF_ROUND(x0, x1, R) { x0 += x1; x1 = (x1 << R) | (x1 >> (32 - R)); x1 ^= x0; }

__host__ __device__ inline void tf_block(unsigned k0, unsigned k1, unsigned &x0, unsigned &x1) {
    unsigned ks2 = k0 ^ k1 ^ 0x1BD11BDAu;
    x0 += k0; x1 += k1;
    TF_ROUND(x0, x1, 13) TF_ROUND(x0, x1, 15) TF_ROUND(x0, x1, 26) TF_ROUND(x0, x1, 6)
    x0 += k1; x1 += ks2 + 1u;
    TF_ROUND(x0, x1, 17) TF_ROUND(x0, x1, 29) TF_ROUND(x0, x1, 16) TF_ROUND(x0, x1, 24)
    x0 += ks2; x1 += k0 + 2u;
    TF_ROUND(x0, x1, 13) TF_ROUND(x0, x1, 15) TF_ROUND(x0, x1, 26) TF_ROUND(x0, x1, 6)
    x0 += k0; x1 += k1 + 3u;
    TF_ROUND(x0, x1, 17) TF_ROUND(x0, x1, 29) TF_ROUND(x0, x1, 16) TF_ROUND(x0, x1, 24)
    x0 += k1; x1 += ks2 + 4u;
    TF_ROUND(x0, x1, 13) TF_ROUND(x0, x1, 15) TF_ROUND(x0, x1, 26) TF_ROUND(x0, x1, 6)
    x0 += ks2; x1 += k0 + 5u;
}

// XLA f32 erf_inv (Giles)
__device__ inline float xla_erfinv(float x) {
    float w = -log1pf(-x * x);
    float p;
    if (w < 5.0f) {
        w -= 2.5f;
        p = 2.81022636e-08f;
        p = fmaf(p, w, 3.43273939e-07f);
        p = fmaf(p, w, -3.5233877e-06f);
        p = fmaf(p, w, -4.39150654e-06f);
        p = fmaf(p, w, 0.00021858087f);
        p = fmaf(p, w, -0.00125372503f);
        p = fmaf(p, w, -0.00417768164f);
        p = fmaf(p, w, 0.246640727f);
        p = fmaf(p, w, 1.50140941f);
    } else {
        w = sqrtf(w) - 3.0f;
        p = -0.000200214257f;
        p = fmaf(p, w, 0.000100950558f);
        p = fmaf(p, w, 0.00134934322f);
        p = fmaf(p, w, -0.00367342844f);
        p = fmaf(p, w, 0.00573950773f);
        p = fmaf(p, w, -0.0076224613f);
        p = fmaf(p, w, 0.00943887047f);
        p = fmaf(p, w, 1.00167406f);
        p = fmaf(p, w, 2.83297682f);
    }
    return p * x;
}

__device__ inline float bits_to_normal(unsigned b) {
    float u1 = __uint_as_float((b >> 9) | 0x3f800000u) - 1.0f;
    float v = fmaf(u1, 1.99999994f, -0.99999994f);
    v = fmaxf(v, -0.99999994f);
    return 1.41421356f * xla_erfinv(v);
}

// Partitionable threefry: bits[i] = x0^x1 of block with counter (0, i)
__global__ void gen_noisy_kernel(const float* __restrict__ wm, const float* __restrict__ ws,
                                 float* __restrict__ dst, int n, unsigned k0, unsigned k1) {
    int i = blockIdx.x * blockDim.x + threadIdx.x;
    if (i >= n) return;
    unsigned x0 = 0u, x1 = (unsigned)i;
    tf_block(k0, k1, x0, x1);
    dst[i] = fmaf(ws[i], bits_to_normal(x0 ^ x1), wm[i]);
}

// noisy weights straight to fp16 hi/lo
__global__ void gen_noisy_w_kernel(const float* __restrict__ wm, const float* __restrict__ ws,
                                   __half* __restrict__ hi, __half* __restrict__ lo,
                                   int n, unsigned k0, unsigned k1) {
    int i = blockIdx.x * blockDim.x + threadIdx.x;
    if (i >= n) return;
    unsigned x0 = 0u, x1 = (unsigned)i;
    tf_block(k0, k1, x0, x1);
    float v = fmaf(ws[i], bits_to_normal(x0 ^ x1), wm[i]);
    __half h = __float2half_rn(v);
    hi[i] = h;
    lo[i] = __float2half_rn(v - __half2float(h));
}

// ---------------- activations ----------------
__device__ inline float mishf(float x) {
    float sp = fmaxf(x, 0.0f) + log1pf(expf(-fabsf(x)));
    return x * tanhf(sp);
}
__device__ inline float sigmoidf_(float x) { return 1.0f / (1.0f + expf(-x)); }

__device__ __forceinline__ uint32_t h2u(__half2 v) {
    return *reinterpret_cast<uint32_t*>(&v);
}

// ---------------- fp32 -> fp16 hi/lo split (n4 = n/4) ----------------
__global__ void conv_split_kernel(const float* __restrict__ src,
                                  __half* __restrict__ hi,
                                  __half* __restrict__ lo, int n4) {
    int i = blockIdx.x * blockDim.x + threadIdx.x;
    if (i >= n4) return;
    float4 v = ((const float4*)src)[i];
    __half2 h0, h1, l0, l1;
    h0.x = __float2half_rn(v.x); h0.y = __float2half_rn(v.y);
    h1.x = __float2half_rn(v.z); h1.y = __float2half_rn(v.w);
    l0.x = __float2half_rn(v.x - __half2float(h0.x));
    l0.y = __float2half_rn(v.y - __half2float(h0.y));
    l1.x = __float2half_rn(v.z - __half2float(h1.x));
    l1.y = __float2half_rn(v.w - __half2float(h1.y));
    ((uint2*)hi)[i] = make_uint2(h2u(h0), h2u(h1));
    ((uint2*)lo)[i] = make_uint2(h2u(l0), h2u(l1));
}

// ---------------- mma / ldmatrix wrappers ----------------
__device__ __forceinline__ void mma16816(float* c, const uint32_t* a, const uint32_t* b) {
    asm volatile(
        "mma.sync.aligned.m16n8k16.row.col.f32.f16.f16.f32 "
        "{%0,%1,%2,%3}, {%4,%5,%6,%7}, {%8,%9}, {%0,%1,%2,%3};\n"
        : "+f"(c[0]), "+f"(c[1]), "+f"(c[2]), "+f"(c[3])
        : "r"(a[0]), "r"(a[1]), "r"(a[2]), "r"(a[3]), "r"(b[0]), "r"(b[1]));
}
// fp16-accumulate variant (2x rate) for small correction terms
__device__ __forceinline__ void mma16816h(uint32_t* c, const uint32_t* a, const uint32_t* b) {
    asm volatile(
        "mma.sync.aligned.m16n8k16.row.col.f16.f16.f16.f16 "
        "{%0,%1}, {%2,%3,%4,%5}, {%6,%7}, {%0,%1};\n"
        : "+r"(c[0]), "+r"(c[1])
        : "r"(a[0]), "r"(a[1]), "r"(a[2]), "r"(a[3]), "r"(b[0]), "r"(b[1]));
}
__device__ __forceinline__ void ldsm4(uint32_t& r0, uint32_t& r1, uint32_t& r2, uint32_t& r3,
                                      uint32_t addr) {
    asm volatile("ldmatrix.sync.aligned.m8n8.x4.shared.b16 {%0,%1,%2,%3}, [%4];"
                 : "=r"(r0), "=r"(r1), "=r"(r2), "=r"(r3) : "r"(addr));
}
__device__ __forceinline__ uint32_t smem_u32(const void* p) {
    uint32_t a;
    asm("{ .reg .u64 t; cvta.to.shared.u64 t, %1; cvt.u32.u64 %0, t; }" : "=r"(a) : "l"(p));
    return a;
}

// ============ split-fp16 tensor-core GEMM: C[M,N] = A[M,K] @ B[N,K]^T + bias ============
// CTA tile 128x128, 8 warps (2m x 4n), warp tile 64x32, k-chunk 32, double-buffered,
// row pitch 40 halves (80B) -> conflict-free LDSM.
// Main term f32-accum; corrections (Al*Bh + Ah*Bl) in f16-accum (2x rate).
#define PADE 40
#define OFF_AH 0
#define OFF_AL (128 * PADE)
#define OFF_BH (2 * 128 * PADE)
#define OFF_BL (3 * 128 * PADE)
#define BUFE (4 * 128 * PADE)
#define MMA_SMEM_BYTES (2 * BUFE * 2)

__global__ __launch_bounds__(256) void mma_gemm_kernel(
    const __half* __restrict__ Ah, const __half* __restrict__ Al,
    const __half* __restrict__ Bh, const __half* __restrict__ Bl,
    const float* __restrict__ bias, float* __restrict__ C,
    __half* __restrict__ Ch, __half* __restrict__ Cl,
    int M, int N, int K, int act, int osplit) {
    extern __shared__ __half smb[];
    const uint32_t sbase = smem_u32(smb);
    const int tid = threadIdx.x;
    const int wid = tid >> 5, lane = tid & 31;
    const int r4 = lane >> 2, lq = lane & 3;
    const int m0 = blockIdx.y * 128, n0 = blockIdx.x * 128;
    const int wm = (wid & 1) * 64, wn = (wid >> 1) * 32;

    const int aro = lane & 15, ako = (lane >> 4) << 3;
    const int bro = (lane & 7) + ((lane >> 4) << 3), bko = ((lane >> 3) & 1) << 3;

    float acc[4][4][4] = {};
    uint32_t corr[4][4][2] = {};
    const int nch = K >> 5;

    // preload chunk 0
#pragma unroll
    for (int q = 0; q < 4; q++) {
        int i = tid + 256 * q; int r = i >> 3, kq = i & 7;
        int e = r * PADE + kq * 4;
        *(uint2*)(smb + OFF_AH + e) = *(const uint2*)(Ah + (size_t)(m0 + r) * K + kq * 4);
        *(uint2*)(smb + OFF_AL + e) = *(const uint2*)(Al + (size_t)(m0 + r) * K + kq * 4);
        *(uint2*)(smb + OFF_BH + e) = *(const uint2*)(Bh + (size_t)(n0 + r) * K + kq * 4);
        *(uint2*)(smb + OFF_BL + e) = *(const uint2*)(Bl + (size_t)(n0 + r) * K + kq * 4);
    }
    __syncthreads();

    for (int c = 0; c < nch; c++) {
        uint2 pah[4], pal[4], pbh[4], pbl[4];
        const bool pf = (c + 1 < nch);
        if (pf) {
            const int k0 = (c + 1) << 5;
#pragma unroll
            for (int q = 0; q < 4; q++) {
                int i = tid + 256 * q; int r = i >> 3, kq = i & 7;
                pah[q] = *(const uint2*)(Ah + (size_t)(m0 + r) * K + k0 + kq * 4);
                pal[q] = *(const uint2*)(Al + (size_t)(m0 + r) * K + k0 + kq * 4);
                pbh[q] = *(const uint2*)(Bh + (size_t)(n0 + r) * K + k0 + kq * 4);
                pbl[q] = *(const uint2*)(Bl + (size_t)(n0 + r) * K + k0 + kq * 4);
            }
        }
        const uint32_t bb = sbase + (uint32_t)((c & 1) * BUFE * 2);
#pragma unroll
        for (int ks = 0; ks < 2; ks++) {
            uint32_t ahf[4][4], alf[4][4], bhf[4][2], blf[4][2];
#pragma unroll
            for (int am = 0; am < 4; am++) {
                uint32_t ar = (uint32_t)((wm + am * 16 + aro) * PADE + ks * 16 + ako) * 2;
                ldsm4(ahf[am][0], ahf[am][1], ahf[am][2], ahf[am][3], bb + OFF_AH * 2 + ar);
                ldsm4(alf[am][0], alf[am][1], alf[am][2], alf[am][3], bb + OFF_AL * 2 + ar);
            }
#pragma unroll
            for (int nb = 0; nb < 2; nb++) {
                uint32_t br = (uint32_t)((wn + nb * 16 + bro) * PADE + ks * 16 + bko) * 2;
                ldsm4(bhf[nb * 2][0], bhf[nb * 2][1], bhf[nb * 2 + 1][0], bhf[nb * 2 + 1][1],
                      bb + OFF_BH * 2 + br);
                ldsm4(blf[nb * 2][0], blf[nb * 2][1], blf[nb * 2 + 1][0], blf[nb * 2 + 1][1],
                      bb + OFF_BL * 2 + br);
            }
#pragma unroll
            for (int am = 0; am < 4; am++)
#pragma unroll
                for (int bn = 0; bn < 4; bn++) {
                    mma16816(acc[am][bn], ahf[am], bhf[bn]);
                    mma16816h(corr[am][bn], alf[am], bhf[bn]);
                    mma16816h(corr[am][bn], ahf[am], blf[bn]);
                }
        }
        if (pf) {
            __half* nb = smb + ((c + 1) & 1) * BUFE;
#pragma unroll
            for (int q = 0; q < 4; q++) {
                int i = tid + 256 * q; int r = i >> 3, kq = i & 7;
                int e = r * PADE + kq * 4;
                *(uint2*)(nb + OFF_AH + e) = pah[q];
                *(uint2*)(nb + OFF_AL + e) = pal[q];
                *(uint2*)(nb + OFF_BH + e) = pbh[q];
                *(uint2*)(nb + OFF_BL + e) = pbl[q];
            }
        }
        __syncthreads();
    }

    // epilogue: main + correction + bias, optional mish; fp32 or fp16-split output
#pragma unroll
    for (int am = 0; am < 4; am++) {
        const int row = m0 + wm + am * 16 + r4;
#pragma unroll
        for (int bn = 0; bn < 4; bn++) {
            const int col = n0 + wn + bn * 8 + 2 * lq;
            const float b0 = bias[col], b1 = bias[col + 1];
            float2 c01 = __half22float2(*reinterpret_cast<__half2*>(&corr[am][bn][0]));
            float2 c23 = __half22float2(*reinterpret_cast<__half2*>(&corr[am][bn][1]));
            float v0 = acc[am][bn][0] + c01.x + b0, v1 = acc[am][bn][1] + c01.y + b1;
            float v2 = acc[am][bn][2] + c23.x + b0, v3 = acc[am][bn][3] + c23.y + b1;
            if (act) { v0 = mishf(v0); v1 = mishf(v1); v2 = mishf(v2); v3 = mishf(v3); }
            if (osplit) {
                __half2 h01, h23, l01, l23;
                h01.x = __float2half_rn(v0); h01.y = __float2half_rn(v1);
                h23.x = __float2half_rn(v2); h23.y = __float2half_rn(v3);
                l01.x = __float2half_rn(v0 - __half2float(h01.x));
                l01.y = __float2half_rn(v1 - __half2float(h01.y));
                l23.x = __float2half_rn(v2 - __half2float(h23.x));
                l23.y = __float2half_rn(v3 - __half2float(h23.y));
                *(uint32_t*)(Ch + (size_t)row * N + col) = h2u(h01);
                *(uint32_t*)(Cl + (size_t)row * N + col) = h2u(l01);
                *(uint32_t*)(Ch + (size_t)(row + 8) * N + col) = h2u(h23);
                *(uint32_t*)(Cl + (size_t)(row + 8) * N + col) = h2u(l23);
            } else {
                *(float2*)(C + (size_t)row * N + col) = make_float2(v0, v1);
                *(float2*)(C + (size_t)(row + 8) * N + col) = make_float2(v2, v3);
            }
        }
    }
}

// ---------------- small SGEMM (p3, N=16) ----------------
__global__ __launch_bounds__(256) void sgemm64_kernel(
    const float* __restrict__ A, const float* __restrict__ B,
    const float* __restrict__ bias, float* __restrict__ C,
    int M, int N, int K) {
    __shared__ float As[16][64];
    __shared__ float Bs[16][64];
    const int m0 = blockIdx.y * 64;
    const int n0 = blockIdx.x * 64;
    const int tid = threadIdx.x;
    const int tx = tid & 15, ty = tid >> 4;
    const int lr = tid >> 2, lq = tid & 3;
    float acc[4][4] = {};
    for (int k0 = 0; k0 < K; k0 += 16) {
        float4 a4 = *(const float4*)(A + (size_t)(m0 + lr) * K + k0 + lq * 4);
        As[lq * 4 + 0][lr] = a4.x; As[lq * 4 + 1][lr] = a4.y;
        As[lq * 4 + 2][lr] = a4.z; As[lq * 4 + 3][lr] = a4.w;
        float4 b4 = make_float4(0.f, 0.f, 0.f, 0.f);
        if (n0 + lr < N) b4 = *(const float4*)(B + (size_t)(n0 + lr) * K + k0 + lq * 4);
        Bs[lq * 4 + 0][lr] = b4.x; Bs[lq * 4 + 1][lr] = b4.y;
        Bs[lq * 4 + 2][lr] = b4.z; Bs[lq * 4 + 3][lr] = b4.w;
        __syncthreads();
#pragma unroll
        for (int k = 0; k < 16; k++) {
            float4 av = *(const float4*)(&As[k][ty * 4]);
            float4 bv = *(const float4*)(&Bs[k][tx * 4]);
            float avs[4] = {av.x, av.y, av.z, av.w};
            float bvs[4] = {bv.x, bv.y, bv.z, bv.w};
#pragma unroll
            for (int i = 0; i < 4; i++)
#pragma unroll
                for (int jj = 0; jj < 4; jj++)
                    acc[i][jj] = fmaf(avs[i], bvs[jj], acc[i][jj]);
        }
        __syncthreads();
    }
#pragma unroll
    for (int i = 0; i < 4; i++) {
        int m = m0 + ty * 4 + i;
#pragma unroll
        for (int jj = 0; jj < 4; jj++) {
            int n = n0 + tx * 4 + jj;
            if (n < N) C[(size_t)m * N + n] = acc[i][jj] + (bias ? bias[n] : 0.0f);
        }
    }
}

// ---------------- prep: bucket timesteps by age within reset-segment ----------------
__global__ __launch_bounds__(1024) void prep_kernel(const int* __restrict__ start) {
    __shared__ int sa[2048], sb_[2048], sc[2048];
    __shared__ int skmax;
    const int tid = threadIdx.x;
    const int t0 = tid, t1 = tid + 1024;
    if (tid == 0) { g_bar = 0u; skmax = 0; }
    sa[t0] = start[t0] ? t0 : -1;
    sa[t1] = start[t1] ? t1 : -1;
    __syncthreads();
    int* src = sa; int* dst = sb_;
    for (int d = 1; d < 2048; d <<= 1) {
        int v0 = src[t0]; if (t0 >= d) v0 = max(v0, src[t0 - d]);
        int v1 = src[t1]; if (t1 >= d) v1 = max(v1, src[t1 - d]);
        dst[t0] = v0; dst[t1] = v1;
        __syncthreads();
        int* tmp = src; src = dst; dst = tmp;
    }
    int r0v = src[t0], r1v = src[t1];
    int age0 = (r0v < 0) ? t0 : t0 - r0v;
    int age1 = (r1v < 0) ? t1 : t1 - r1v;
    __syncthreads();
    sc[t0] = 0; sc[t1] = 0;
    __syncthreads();
    atomicAdd(&sc[age0], 1);
    atomicAdd(&sc[age1], 1);
    atomicMax(&skmax, max(age0, age1) + 1);
    __syncthreads();
    sa[t0] = sc[t0]; sa[t1] = sc[t1];
    __syncthreads();
    src = sa; dst = sb_;
    for (int d = 1; d < 2048; d <<= 1) {
        int v0 = src[t0]; if (t0 >= d) v0 += src[t0 - d];
        int v1 = src[t1]; if (t1 >= d) v1 += src[t1 - d];
        dst[t0] = v0; dst[t1] = v1;
        __syncthreads();
        int* tmp = src; src = dst; dst = tmp;
    }
    if (tid == 0) { g_off[0] = 0; g_kmax = skmax; }
    g_off[t0 + 1] = src[t0];
    g_off[t1 + 1] = src[t1];
    sc[t0] = 0; sc[t1] = 0;
    __syncthreads();
    int base0 = (age0 == 0) ? 0 : src[age0 - 1];
    g_order[base0 + atomicAdd(&sc[age0], 1)] = t0;
    int base1 = (age1 == 0) ? 0 : src[age1 - 1];
    g_order[base1 + atomicAdd(&sc[age1], 1)] = t1;
}

// ---------------- grid barrier ----------------
__device__ inline void grid_bar(unsigned* barp, unsigned target) {
    __syncthreads();
    if (threadIdx.x == 0) {
        asm volatile("red.release.gpu.global.add.u32 [%0], %1;" :: "l"(barp), "r"(1u) : "memory");
        unsigned v;
        do {
            asm volatile("ld.acquire.gpu.global.u32 %0, [%1];" : "=r"(v) : "l"(barp) : "memory");
        } while (v < target);
    }
    __syncthreads();
}

__device__ __forceinline__ void store_state(int t, int j, float hnew, float* out) {
    g_states[(size_t)t * HD + j] = hnew;
    __half h = __float2half_rn(hnew);
    g_sth[(size_t)t * HD + j] = h;
    g_stl[(size_t)t * HD + j] = __float2half_rn(hnew - __half2float(h));
    if (t == T_STEPS - 1) out[(size_t)T_STEPS * ACTD + j] = hnew;
}

// ---------------- segment-parallel GRU scan, register-resident whh, 2 rows/iter ----------------
__global__ __launch_bounds__(256, 1) void scan_kernel(
    const float* __restrict__ whh, const float* __restrict__ gbn,
    const int* __restrict__ start, const float* __restrict__ state,
    float* __restrict__ out) {
    __shared__ float sH[2][HD];
    const int tid = threadIdx.x;
    const int w = tid >> 5, lane = tid & 31;
    const int j = blockIdx.x * 8 + w;

    const float4* w4 = (const float4*)whh;
    float4 wr[8], wz[8], wn[8];
#pragma unroll
    for (int q = 0; q < 8; q++) {
        wr[q] = w4[(size_t)(0 * HD + j) * 256 + lane + 32 * q];
        wz[q] = w4[(size_t)(1 * HD + j) * 256 + lane + 32 * q];
        wn[q] = w4[(size_t)(2 * HD + j) * 256 + lane + 32 * q];
    }
    const float bnj = gbn[j];
    float4* sH0s = (float4*)sH[0];
    float4* sH1s = (float4*)sH[1];
    const float4* sH0 = (const float4*)sH[0];
    const float4* sH1 = (const float4*)sH[1];
    unsigned* barp = &g_bar;
    const int kmax = g_kmax;
    const int s0 = start[0];
    unsigned epoch = 0;

    // ---- round 0: t=0 with start[0]==0 (h_in = state) ----
    if (s0 == 0) {
        sH0s[tid] = ((const float4*)state)[tid];
        __syncthreads();
        float ir = 0.f, iz = 0.f, inn = 0.f;
        if (lane == 0) { ir = g_ig[j]; iz = g_ig[HD + j]; inn = g_ig[2 * HD + j]; }
        float aR = 0.f, aZ = 0.f, aN = 0.f;
#pragma unroll
        for (int q = 0; q < 8; q++) {
            float4 h4 = sH0[lane + 32 * q];
            aR = fmaf(h4.x, wr[q].x, fmaf(h4.y, wr[q].y, fmaf(h4.z, wr[q].z, fmaf(h4.w, wr[q].w, aR))));
            aZ = fmaf(h4.x, wz[q].x, fmaf(h4.y, wz[q].y, fmaf(h4.z, wz[q].z, fmaf(h4.w, wz[q].w, aZ))));
            aN = fmaf(h4.x, wn[q].x, fmaf(h4.y, wn[q].y, fmaf(h4.z, wn[q].z, fmaf(h4.w, wn[q].w, aN))));
        }
#pragma unroll
        for (int off = 16; off; off >>= 1) {
            aR += __shfl_xor_sync(0xffffffffu, aR, off);
            aZ += __shfl_xor_sync(0xffffffffu, aZ, off);
            aN += __shfl_xor_sync(0xffffffffu, aN, off);
        }
        if (lane == 0) {
            float rv = sigmoidf_(ir + aR);
            float uv = sigmoidf_(iz + aZ);
            float nv = tanhf(inn + rv * (aN + bnj));
            float hin = sH[0][j];
            store_state(0, j, nv + uv * (hin - nv), out);
        }
        __syncthreads();
    }
    // round 0: start rows (h_in = 0), lane-parallel
    {
        const int beg = g_off[0], end = g_off[1];
        for (int r = beg + lane; r < end; r += 32) {
            const int t = g_order[r];
            if (t == 0 && s0 == 0) continue;
            const float* igt = g_ig + (size_t)t * (3 * HD);
            float rv = sigmoidf_(igt[j]);
            float uv = sigmoidf_(igt[HD + j]);
            float nv = tanhf(igt[2 * HD + j] + rv * bnj);
            store_state(t, j, nv - uv * nv, out);
        }
    }
    grid_bar(barp, (++epoch) * SCAN_BLOCKS);

    // ---- rounds k >= 1: two independent rows per iteration ----
    for (int k = 1; k < kmax; k++) {
        const int beg = g_off[k], end = g_off[k + 1];
        int r = beg;
        int tA = g_order[r];
        float4 nxtA = __ldcg((const float4*)(g_states + (size_t)(tA - 1) * HD) + tid);
        int tB = (r + 1 < end) ? g_order[r + 1] : -1;
        float4 nxtB = make_float4(0.f, 0.f, 0.f, 0.f);
        if (tB >= 0) nxtB = __ldcg((const float4*)(g_states + (size_t)(tB - 1) * HD) + tid);

        while (r < end) {
            const int curA = tA, curB = tB;
            sH0s[tid] = nxtA;
            if (curB >= 0) sH1s[tid] = nxtB;
            __syncthreads();

            const int rn = r + 2;
            if (rn < end) {
                tA = g_order[rn];
                nxtA = __ldcg((const float4*)(g_states + (size_t)(tA - 1) * HD) + tid);
            }
            if (rn + 1 < end) {
                tB = g_order[rn + 1];
                nxtB = __ldcg((const float4*)(g_states + (size_t)(tB - 1) * HD) + tid);
            } else {
                tB = -1;
            }

            float irA = 0.f, izA = 0.f, inA = 0.f, irB = 0.f, izB = 0.f, inB = 0.f;
            if (lane == 0) {
                const float* iga = g_ig + (size_t)curA * (3 * HD);
                irA = iga[j]; izA = iga[HD + j]; inA = iga[2 * HD + j];
                if (curB >= 0) {
                    const float* igb = g_ig + (size_t)curB * (3 * HD);
                    irB = igb[j]; izB = igb[HD + j]; inB = igb[2 * HD + j];
                }
            }

            float aR = 0.f, aZ = 0.f, aN = 0.f, bR = 0.f, bZ = 0.f, bN = 0.f;
#pragma unroll
            for (int q = 0; q < 8; q++) {
                const int c = lane + 32 * q;
                float4 hA = sH0[c];
                float4 hB = sH1[c];
                float4 r4v = wr[q], z4v = wz[q], n4v = wn[q];
                aR = fmaf(hA.x, r4v.x, fmaf(hA.y, r4v.y, fmaf(hA.z, r4v.z, fmaf(hA.w, r4v.w, aR))));
                bR = fmaf(hB.x, r4v.x, fmaf(hB.y, r4v.y, fmaf(hB.z, r4v.z, fmaf(hB.w, r4v.w, bR))));
                aZ = fmaf(hA.x, z4v.x, fmaf(hA.y, z4v.y, fmaf(hA.z, z4v.z, fmaf(hA.w, z4v.w, aZ))));
                bZ = fmaf(hB.x, z4v.x, fmaf(hB.y, z4v.y, fmaf(hB.z, z4v.z, fmaf(hB.w, z4v.w, bZ))));
                aN = fmaf(hA.x, n4v.x, fmaf(hA.y, n4v.y, fmaf(hA.z, n4v.z, fmaf(hA.w, n4v.w, aN))));
                bN = fmaf(hB.x, n4v.x, fmaf(hB.y, n4v.y, fmaf(hB.z, n4v.z, fmaf(hB.w, n4v.w, bN))));
            }
#pragma unroll
            for (int off = 16; off; off >>= 1) {
                aR += __shfl_xor_sync(0xffffffffu, aR, off);
                aZ += __shfl_xor_sync(0xffffffffu, aZ, off);
                aN += __shfl_xor_sync(0xffffffffu, aN, off);
                bR += __shfl_xor_sync(0xffffffffu, bR, off);
                bZ += __shfl_xor_sync(0xffffffffu, bZ, off);
                bN += __shfl_xor_sync(0xffffffffu, bN, off);
            }
            if (lane == 0) {
                {
                    float rv = sigmoidf_(irA + aR);
                    float uv = sigmoidf_(izA + aZ);
                    float nv = tanhf(inA + rv * (aN + bnj));
                    float hin = sH[0][j];
                    store_state(curA, j, nv + uv * (hin - nv), out);
                }
                if (curB >= 0) {
                    float rv = sigmoidf_(irB + bR);
                    float uv = sigmoidf_(izB + bZ);
                    float nv = tanhf(inB + rv * (bN + bnj));
                    float hin = sH[1][j];
                    store_state(curB, j, nv + uv * (hin - nv), out);
                }
            }
            __syncthreads();
            r = rn;
        }
        grid_bar(barp, (++epoch) * SCAN_BLOCKS);
    }
}

// ---------------- launch ----------------
extern "C" void kernel_launch(void* const* d_in, const int* in_sizes, int n_in,
                              void* d_out, int out_size) {
    (void)in_sizes; (void)n_in;
    const float* x      = (const float*)d_in[0];
    const float* state  = (const float*)d_in[1];
    const int*   start  = (const int*)d_in[2];
    const float* pre_wm = (const float*)d_in[4];
    const float* pre_ws = (const float*)d_in[5];
    const float* pre_bm = (const float*)d_in[6];
    const float* pre_bs = (const float*)d_in[7];
    const float* wih    = (const float*)d_in[8];
    const float* whh    = (const float*)d_in[9];
    const float* gru_b  = (const float*)d_in[10];
    const float* gru_bn = (const float*)d_in[11];
    const float* p1_wm  = (const float*)d_in[12];
    const float* p1_ws  = (const float*)d_in[13];
    const float* p1_bm  = (const float*)d_in[14];
    const float* p1_bs  = (const float*)d_in[15];
    const float* p2_wm  = (const float*)d_in[16];
    const float* p2_ws  = (const float*)d_in[17];
    const float* p2_bm  = (const float*)d_in[18];
    const float* p2_bs  = (const float*)d_in[19];
    const float* p3_wm  = (const float*)d_in[20];
    const float* p3_ws  = (const float*)d_in[21];
    const float* p3_bm  = (const float*)d_in[22];
    const float* p3_bs  = (const float*)d_in[23];
    float* out = (float*)d_out;
    (void)out_size;

    unsigned nk[8][2];
    for (int i = 0; i < 8; i++) {
        unsigned a = 0u, b = (unsigned)i;
        tf_block(0u, 7u, a, b);
        nk[i][0] = a; nk[i][1] = b;
    }

    float *preB, *p1B, *p2B, *p3W, *p3B, *ig, *states, *y2;
    __half *xh, *xl, *preWh, *preWl, *wihh, *wihl, *p1Wh, *p1Wl, *p2Wh, *p2Wl;
    __half *zh, *zl, *sth, *stl, *y1h, *y1l;
    cudaGetSymbolAddress((void**)&preB, g_preB);
    cudaGetSymbolAddress((void**)&p1B, g_p1B);
    cudaGetSymbolAddress((void**)&p2B, g_p2B);
    cudaGetSymbolAddress((void**)&p3W, g_p3W);
    cudaGetSymbolAddress((void**)&p3B, g_p3B);
    cudaGetSymbolAddress((void**)&ig, g_ig);
    cudaGetSymbolAddress((void**)&states, g_states);
    cudaGetSymbolAddress((void**)&y2, g_y2);
    cudaGetSymbolAddress((void**)&xh, g_xh);
    cudaGetSymbolAddress((void**)&xl, g_xl);
    cudaGetSymbolAddress((void**)&preWh, g_preWh);
    cudaGetSymbolAddress((void**)&preWl, g_preWl);
    cudaGetSymbolAddress((void**)&wihh, g_wihh);
    cudaGetSymbolAddress((void**)&wihl, g_wihl);
    cudaGetSymbolAddress((void**)&p1Wh, g_p1Wh);
    cudaGetSymbolAddress((void**)&p1Wl, g_p1Wl);
    cudaGetSymbolAddress((void**)&p2Wh, g_p2Wh);
    cudaGetSymbolAddress((void**)&p2Wl, g_p2Wl);
    cudaGetSymbolAddress((void**)&zh, g_zh);
    cudaGetSymbolAddress((void**)&zl, g_zl);
    cudaGetSymbolAddress((void**)&sth, g_sth);
    cudaGetSymbolAddress((void**)&stl, g_stl);
    cudaGetSymbolAddress((void**)&y1h, g_y1h);
    cudaGetSymbolAddress((void**)&y1l, g_y1l);

    cudaFuncSetAttribute(mma_gemm_kernel, cudaFuncAttributeMaxDynamicSharedMemorySize,
                         MMA_SMEM_BYTES);

    prep_kernel<<<1, 1024>>>(start);

    // noisy weights/biases: nk order = pre(w,b), p1(w,b), p2(w,b), p3(w,b)
    {
        int n;
        n = MLPD * OBS;  gen_noisy_w_kernel<<<(n + 255) / 256, 256>>>(pre_wm, pre_ws, preWh, preWl, n, nk[0][0], nk[0][1]);
        n = MLPD;        gen_noisy_kernel<<<(n + 255) / 256, 256>>>(pre_bm, pre_bs, preB, n, nk[1][0], nk[1][1]);
        n = MLPD * HD;   gen_noisy_w_kernel<<<(n + 255) / 256, 256>>>(p1_wm, p1_ws, p1Wh, p1Wl, n, nk[2][0], nk[2][1]);
        n = MLPD;        gen_noisy_kernel<<<(n + 255) / 256, 256>>>(p1_bm, p1_bs, p1B, n, nk[3][0], nk[3][1]);
        n = MLPD * MLPD; gen_noisy_w_kernel<<<(n + 255) / 256, 256>>>(p2_wm, p2_ws, p2Wh, p2Wl, n, nk[4][0], nk[4][1]);
        n = MLPD;        gen_noisy_kernel<<<(n + 255) / 256, 256>>>(p2_bm, p2_bs, p2B, n, nk[5][0], nk[5][1]);
        n = ACTD * MLPD; gen_noisy_kernel<<<(n + 255) / 256, 256>>>(p3_wm, p3_ws, p3W, n, nk[6][0], nk[6][1]);
        n = ACTD;        gen_noisy_kernel<<<(n + 255) / 256, 256>>>(p3_bm, p3_bs, p3B, n, nk[7][0], nk[7][1]);
    }

    // splits for non-noisy operands
    conv_split_kernel<<<(T_STEPS * OBS / 4 + 255) / 256, 256>>>(x, xh, xl, T_STEPS * OBS / 4);
    conv_split_kernel<<<(3 * HD * MLPD / 4 + 255) / 256, 256>>>(wih, wihh, wihl, 3 * HD * MLPD / 4);

    // GEMM1: z = mish(x @ preW^T + preB) -> zh/zl   [2048,1024], K=512
    mma_gemm_kernel<<<dim3(MLPD / 128, T_STEPS / 128), 256, MMA_SMEM_BYTES>>>(
        xh, xl, preWh, preWl, preB, nullptr, zh, zl, T_STEPS, MLPD, OBS, 1, 1);

    // GEMM2: igates = z @ wih^T + gru_b -> fp32     [2048,3072], K=1024
    mma_gemm_kernel<<<dim3(3 * HD / 128, T_STEPS / 128), 256, MMA_SMEM_BYTES>>>(
        zh, zl, wihh, wihl, gru_b, ig, nullptr, nullptr, T_STEPS, 3 * HD, MLPD, 0, 0);

    // segment-parallel GRU scan (writes states fp32 + h/l, final state into out tail)
    scan_kernel<<<SCAN_BLOCKS, 256>>>(whh, gru_bn, start, state, out);

    // GEMM3: y1 = mish(states @ p1W^T + p1B) -> y1h/y1l
    mma_gemm_kernel<<<dim3(MLPD / 128, T_STEPS / 128), 256, MMA_SMEM_BYTES>>>(
        sth, stl, p1Wh, p1Wl, p1B, nullptr, y1h, y1l, T_STEPS, MLPD, HD, 1, 1);

    // GEMM4: y2 = mish(y1 @ p2W^T + p2B) -> fp32
    mma_gemm_kernel<<<dim3(MLPD / 128, T_STEPS / 128), 256, MMA_SMEM_BYTES>>>(
        y1h, y1l, p2Wh, p2Wl, p2B, y2, nullptr, nullptr, T_STEPS, MLPD, MLPD, 1, 0);

    // final layer -> d_out[0 : 2048*16]
    sgemm64_kernel<<<dim3(1, T_STEPS / 64), 256>>>(y2, p3W, p3B, out, T_STEPS, ACTD, MLPD);
}

// round 10
// speedup vs baseline: 7.4245x; 1.0381x over previous
#include <cuda_runtime.h>
#include <cuda_fp16.h>
#include <cstdint>

#define T_STEPS 2048
#define OBS 512
#define MLPD 1024
#define HD 1024
#define ACTD 16
#define SCAN_BLOCKS 128

// ---------------- device scratch (no allocations allowed) ----------------
__device__ float g_preB[MLPD];
__device__ float g_p1B[MLPD];
__device__ float g_p2B[MLPD];
__device__ float g_p3W[ACTD * MLPD];
__device__ float g_p3B[ACTD];
__device__ float g_ig[(size_t)T_STEPS * 3 * HD];
__device__ float g_states[(size_t)T_STEPS * HD];
__device__ float g_y2[T_STEPS * MLPD];
__device__ __half g_xh[T_STEPS * OBS],  g_xl[T_STEPS * OBS];
__device__ __half g_preWh[MLPD * OBS],  g_preWl[MLPD * OBS];
__device__ __half g_wihh[3 * HD * MLPD], g_wihl[3 * HD * MLPD];
__device__ __half g_p1Wh[MLPD * HD],    g_p1Wl[MLPD * HD];
__device__ __half g_p2Wh[MLPD * MLPD],  g_p2Wl[MLPD * MLPD];
__device__ __half g_zh[T_STEPS * MLPD], g_zl[T_STEPS * MLPD];
__device__ __half g_sth[(size_t)T_STEPS * HD], g_stl[(size_t)T_STEPS * HD];
__device__ __half g_y1h[T_STEPS * MLPD], g_y1l[T_STEPS * MLPD];
__device__ unsigned g_bar;
__device__ int g_order[T_STEPS];
__device__ int g_off[T_STEPS + 1];
__device__ int g_kmax;

// ---------------- threefry2x32 (matches JAX) ----------------
#define TF_ROUND(x0, x1, R) { x0 += x1; x1 = (x1 << R) | (x1 >> (32 - R)); x1 ^= x0; }

__host__ __device__ inline void tf_block(unsigned k0, unsigned k1, unsigned &x0, unsigned &x1) {
    unsigned ks2 = k0 ^ k1 ^ 0x1BD11BDAu;
    x0 += k0; x1 += k1;
    TF_ROUND(x0, x1, 13) TF_ROUND(x0, x1, 15) TF_ROUND(x0, x1, 26) TF_ROUND(x0, x1, 6)
    x0 += k1; x1 += ks2 + 1u;
    TF_ROUND(x0, x1, 17) TF_ROUND(x0, x1, 29) TF_ROUND(x0, x1, 16) TF_ROUND(x0, x1, 24)
    x0 += ks2; x1 += k0 + 2u;
    TF_ROUND(x0, x1, 13) TF_ROUND(x0, x1, 15) TF_ROUND(x0, x1, 26) TF_ROUND(x0, x1, 6)
    x0 += k0; x1 += k1 + 3u;
    TF_ROUND(x0, x1, 17) TF_ROUND(x0, x1, 29) TF_ROUND(x0, x1, 16) TF_ROUND(x0, x1, 24)
    x0 += k1; x1 += ks2 + 4u;
    TF_ROUND(x0, x1, 13) TF_ROUND(x0, x1, 15) TF_ROUND(x0, x1, 26) TF_ROUND(x0, x1, 6)
    x0 += ks2; x1 += k0 + 5u;
}

// XLA f32 erf_inv (Giles)
__device__ inline float xla_erfinv(float x) {
    float w = -log1pf(-x * x);
    float p;
    if (w < 5.0f) {
        w -= 2.5f;
        p = 2.81022636e-08f;
        p = fmaf(p, w, 3.43273939e-07f);
        p = fmaf(p, w, -3.5233877e-06f);
        p = fmaf(p, w, -4.39150654e-06f);
        p = fmaf(p, w, 0.00021858087f);
        p = fmaf(p, w, -0.00125372503f);
        p = fmaf(p, w, -0.00417768164f);
        p = fmaf(p, w, 0.246640727f);
        p = fmaf(p, w, 1.50140941f);
    } else {
        w = sqrtf(w) - 3.0f;
        p = -0.000200214257f;
        p = fmaf(p, w, 0.000100950558f);
        p = fmaf(p, w, 0.00134934322f);
        p = fmaf(p, w, -0.00367342844f);
        p = fmaf(p, w, 0.00573950773f);
        p = fmaf(p, w, -0.0076224613f);
        p = fmaf(p, w, 0.00943887047f);
        p = fmaf(p, w, 1.00167406f);
        p = fmaf(p, w, 2.83297682f);
    }
    return p * x;
}

__device__ inline float bits_to_normal(unsigned b) {
    float u1 = __uint_as_float((b >> 9) | 0x3f800000u) - 1.0f;
    float v = fmaf(u1, 1.99999994f, -0.99999994f);
    v = fmaxf(v, -0.99999994f);
    return 1.41421356f * xla_erfinv(v);
}

// Partitionable threefry: bits[i] = x0^x1 of block with counter (0, i)
__global__ void gen_noisy_kernel(const float* __restrict__ wm, const float* __restrict__ ws,
                                 float* __restrict__ dst, int n, unsigned k0, unsigned k1) {
    int i = blockIdx.x * blockDim.x + threadIdx.x;
    if (i >= n) return;
    unsigned x0 = 0u, x1 = (unsigned)i;
    tf_block(k0, k1, x0, x1);
    dst[i] = fmaf(ws[i], bits_to_normal(x0 ^ x1), wm[i]);
}

// noisy weights straight to fp16 hi/lo
__global__ void gen_noisy_w_kernel(const float* __restrict__ wm, const float* __restrict__ ws,
                                   __half* __restrict__ hi, __half* __restrict__ lo,
                                   int n, unsigned k0, unsigned k1) {
    int i = blockIdx.x * blockDim.x + threadIdx.x;
    if (i >= n) return;
    unsigned x0 = 0u, x1 = (unsigned)i;
    tf_block(k0, k1, x0, x1);
    float v = fmaf(ws[i], bits_to_normal(x0 ^ x1), wm[i]);
    __half h = __float2half_rn(v);
    hi[i] = h;
    lo[i] = __float2half_rn(v - __half2float(h));
}

// ---------------- activations ----------------
__device__ inline float mishf(float x) {
    float sp = fmaxf(x, 0.0f) + log1pf(expf(-fabsf(x)));
    return x * tanhf(sp);
}
__device__ inline float sigmoidf_(float x) { return 1.0f / (1.0f + expf(-x)); }

__device__ __forceinline__ uint32_t h2u(__half2 v) {
    return *reinterpret_cast<uint32_t*>(&v);
}

// ---------------- fp32 -> fp16 hi/lo split (n4 = n/4) ----------------
__global__ void conv_split_kernel(const float* __restrict__ src,
                                  __half* __restrict__ hi,
                                  __half* __restrict__ lo, int n4) {
    int i = blockIdx.x * blockDim.x + threadIdx.x;
    if (i >= n4) return;
    float4 v = ((const float4*)src)[i];
    __half2 h0, h1, l0, l1;
    h0.x = __float2half_rn(v.x); h0.y = __float2half_rn(v.y);
    h1.x = __float2half_rn(v.z); h1.y = __float2half_rn(v.w);
    l0.x = __float2half_rn(v.x - __half2float(h0.x));
    l0.y = __float2half_rn(v.y - __half2float(h0.y));
    l1.x = __float2half_rn(v.z - __half2float(h1.x));
    l1.y = __float2half_rn(v.w - __half2float(h1.y));
    ((uint2*)hi)[i] = make_uint2(h2u(h0), h2u(h1));
    ((uint2*)lo)[i] = make_uint2(h2u(l0), h2u(l1));
}

// ---------------- mma / ldmatrix / cp.async wrappers ----------------
__device__ __forceinline__ void mma16816(float* c, const uint32_t* a, const uint32_t* b) {
    asm volatile(
        "mma.sync.aligned.m16n8k16.row.col.f32.f16.f16.f32 "
        "{%0,%1,%2,%3}, {%4,%5,%6,%7}, {%8,%9}, {%0,%1,%2,%3};\n"
        : "+f"(c[0]), "+f"(c[1]), "+f"(c[2]), "+f"(c[3])
        : "r"(a[0]), "r"(a[1]), "r"(a[2]), "r"(a[3]), "r"(b[0]), "r"(b[1]));
}
__device__ __forceinline__ void mma16816h(uint32_t* c, const uint32_t* a, const uint32_t* b) {
    asm volatile(
        "mma.sync.aligned.m16n8k16.row.col.f16.f16.f16.f16 "
        "{%0,%1}, {%2,%3,%4,%5}, {%6,%7}, {%0,%1};\n"
        : "+r"(c[0]), "+r"(c[1])
        : "r"(a[0]), "r"(a[1]), "r"(a[2]), "r"(a[3]), "r"(b[0]), "r"(b[1]));
}
__device__ __forceinline__ void ldsm4(uint32_t& r0, uint32_t& r1, uint32_t& r2, uint32_t& r3,
                                      uint32_t addr) {
    asm volatile("ldmatrix.sync.aligned.m8n8.x4.shared.b16 {%0,%1,%2,%3}, [%4];"
                 : "=r"(r0), "=r"(r1), "=r"(r2), "=r"(r3) : "r"(addr));
}
__device__ __forceinline__ uint32_t smem_u32(const void* p) {
    uint32_t a;
    asm("{ .reg .u64 t; cvta.to.shared.u64 t, %1; cvt.u32.u64 %0, t; }" : "=r"(a) : "l"(p));
    return a;
}
__device__ __forceinline__ void cp16(uint32_t saddr, const void* gptr) {
    asm volatile("cp.async.cg.shared.global [%0], [%1], 16;" :: "r"(saddr), "l"(gptr));
}
__device__ __forceinline__ void cp_commit() {
    asm volatile("cp.async.commit_group;" ::: "memory");
}
__device__ __forceinline__ void cp_wait1() {
    asm volatile("cp.async.wait_group 1;" ::: "memory");
}
__device__ __forceinline__ void cp_wait0() {
    asm volatile("cp.async.wait_group 0;" ::: "memory");
}

// ============ split-fp16 tensor-core GEMM: C[M,N] = A[M,K] @ B[N,K]^T + bias ============
// CTA tile 128x128, 8 warps (2m x 4n), warp tile 64x32, k-chunk 32,
// cp.async 2-stage double buffer, 2 CTAs/SM. Row pitch 40 halves (80B).
// Main term f32-accum; corrections (Al*Bh + Ah*Bl) in f16-accum (2x rate).
#define PADE 40
#define OFF_AH 0
#define OFF_AL (128 * PADE)
#define OFF_BH (2 * 128 * PADE)
#define OFF_BL (3 * 128 * PADE)
#define BUFE (4 * 128 * PADE)
#define MMA_SMEM_BYTES (2 * BUFE * 2)

__global__ __launch_bounds__(256, 2) void mma_gemm_kernel(
    const __half* __restrict__ Ah, const __half* __restrict__ Al,
    const __half* __restrict__ Bh, const __half* __restrict__ Bl,
    const float* __restrict__ bias, float* __restrict__ C,
    __half* __restrict__ Ch, __half* __restrict__ Cl,
    int M, int N, int K, int act, int osplit) {
    extern __shared__ __half smb[];
    const uint32_t sbase = smem_u32(smb);
    const int tid = threadIdx.x;
    const int wid = tid >> 5, lane = tid & 31;
    const int r4 = lane >> 2, lq = lane & 3;
    const int m0 = blockIdx.y * 128, n0 = blockIdx.x * 128;
    const int wm = (wid & 1) * 64, wn = (wid >> 1) * 32;

    const int aro = lane & 15, ako = (lane >> 4) << 3;
    const int bro = (lane & 7) + ((lane >> 4) << 3), bko = ((lane >> 3) & 1) << 3;

    float acc[4][4][4] = {};
    uint32_t corr[4][4][2] = {};
    const int nch = K >> 5;

    // cp.async issue for chunk c into buffer c&1
    const int ld_r = tid >> 2, ld_q = tid & 3;
    const uint32_t ld_e = (uint32_t)(ld_r * PADE + ld_q * 8) * 2;

    {
        // chunk 0 + chunk 1
#pragma unroll
        for (int c = 0; c < 2; c++) {
            if (c >= nch) break;
            const int k0 = c << 5;
            const uint32_t bb = sbase + (uint32_t)((c & 1) * BUFE * 2);
#pragma unroll
            for (int q = 0; q < 2; q++) {
                int r = ld_r + 64 * q;
                uint32_t e = ld_e + (uint32_t)(64 * q * PADE) * 2;
                size_t goA = (size_t)(m0 + r) * K + k0 + ld_q * 8;
                size_t goB = (size_t)(n0 + r) * K + k0 + ld_q * 8;
                cp16(bb + OFF_AH * 2 + e, Ah + goA);
                cp16(bb + OFF_AL * 2 + e, Al + goA);
                cp16(bb + OFF_BH * 2 + e, Bh + goB);
                cp16(bb + OFF_BL * 2 + e, Bl + goB);
            }
            cp_commit();
        }
    }

    for (int c = 0; c < nch; c++) {
        if (c + 1 < nch) cp_wait1(); else cp_wait0();
        __syncthreads();

        const uint32_t bb = sbase + (uint32_t)((c & 1) * BUFE * 2);
#pragma unroll
        for (int ks = 0; ks < 2; ks++) {
            uint32_t ahf[4][4], alf[4][4], bhf[4][2], blf[4][2];
#pragma unroll
            for (int am = 0; am < 4; am++) {
                uint32_t ar = (uint32_t)((wm + am * 16 + aro) * PADE + ks * 16 + ako) * 2;
                ldsm4(ahf[am][0], ahf[am][1], ahf[am][2], ahf[am][3], bb + OFF_AH * 2 + ar);
                ldsm4(alf[am][0], alf[am][1], alf[am][2], alf[am][3], bb + OFF_AL * 2 + ar);
            }
#pragma unroll
            for (int nb = 0; nb < 2; nb++) {
                uint32_t br = (uint32_t)((wn + nb * 16 + bro) * PADE + ks * 16 + bko) * 2;
                ldsm4(bhf[nb * 2][0], bhf[nb * 2][1], bhf[nb * 2 + 1][0], bhf[nb * 2 + 1][1],
                      bb + OFF_BH * 2 + br);
                ldsm4(blf[nb * 2][0], blf[nb * 2][1], blf[nb * 2 + 1][0], blf[nb * 2 + 1][1],
                      bb + OFF_BL * 2 + br);
            }
#pragma unroll
            for (int am = 0; am < 4; am++)
#pragma unroll
                for (int bn = 0; bn < 4; bn++) {
                    mma16816(acc[am][bn], ahf[am], bhf[bn]);
                    mma16816h(corr[am][bn], alf[am], bhf[bn]);
                    mma16816h(corr[am][bn], ahf[am], blf[bn]);
                }
        }
        __syncthreads();  // all warps done reading buffer c&1 before refilling it

        if (c + 2 < nch) {
            const int k0 = (c + 2) << 5;
            const uint32_t nb = sbase + (uint32_t)(((c + 2) & 1) * BUFE * 2);
#pragma unroll
            for (int q = 0; q < 2; q++) {
                int r = ld_r + 64 * q;
                uint32_t e = ld_e + (uint32_t)(64 * q * PADE) * 2;
                size_t goA = (size_t)(m0 + r) * K + k0 + ld_q * 8;
                size_t goB = (size_t)(n0 + r) * K + k0 + ld_q * 8;
                cp16(nb + OFF_AH * 2 + e, Ah + goA);
                cp16(nb + OFF_AL * 2 + e, Al + goA);
                cp16(nb + OFF_BH * 2 + e, Bh + goB);
                cp16(nb + OFF_BL * 2 + e, Bl + goB);
            }
            cp_commit();
        }
    }

    // epilogue: main + correction + bias, optional mish; fp32 or fp16-split output
#pragma unroll
    for (int am = 0; am < 4; am++) {
        const int row = m0 + wm + am * 16 + r4;
#pragma unroll
        for (int bn = 0; bn < 4; bn++) {
            const int col = n0 + wn + bn * 8 + 2 * lq;
            const float b0 = bias[col], b1 = bias[col + 1];
            float2 c01 = __half22float2(*reinterpret_cast<__half2*>(&corr[am][bn][0]));
            float2 c23 = __half22float2(*reinterpret_cast<__half2*>(&corr[am][bn][1]));
            float v0 = acc[am][bn][0] + c01.x + b0, v1 = acc[am][bn][1] + c01.y + b1;
            float v2 = acc[am][bn][2] + c23.x + b0, v3 = acc[am][bn][3] + c23.y + b1;
            if (act) { v0 = mishf(v0); v1 = mishf(v1); v2 = mishf(v2); v3 = mishf(v3); }
            if (osplit) {
                __half2 h01, h23, l01, l23;
                h01.x = __float2half_rn(v0); h01.y = __float2half_rn(v1);
                h23.x = __float2half_rn(v2); h23.y = __float2half_rn(v3);
                l01.x = __float2half_rn(v0 - __half2float(h01.x));
                l01.y = __float2half_rn(v1 - __half2float(h01.y));
                l23.x = __float2half_rn(v2 - __half2float(h23.x));
                l23.y = __float2half_rn(v3 - __half2float(h23.y));
                *(uint32_t*)(Ch + (size_t)row * N + col) = h2u(h01);
                *(uint32_t*)(Cl + (size_t)row * N + col) = h2u(l01);
                *(uint32_t*)(Ch + (size_t)(row + 8) * N + col) = h2u(h23);
                *(uint32_t*)(Cl + (size_t)(row + 8) * N + col) = h2u(l23);
            } else {
                *(float2*)(C + (size_t)row * N + col) = make_float2(v0, v1);
                *(float2*)(C + (size_t)(row + 8) * N + col) = make_float2(v2, v3);
            }
        }
    }
}

// ---------------- small SGEMM (p3, N=16) ----------------
__global__ __launch_bounds__(256) void sgemm64_kernel(
    const float* __restrict__ A, const float* __restrict__ B,
    const float* __restrict__ bias, float* __restrict__ C,
    int M, int N, int K) {
    __shared__ float As[16][64];
    __shared__ float Bs[16][64];
    const int m0 = blockIdx.y * 64;
    const int n0 = blockIdx.x * 64;
    const int tid = threadIdx.x;
    const int tx = tid & 15, ty = tid >> 4;
    const int lr = tid >> 2, lq = tid & 3;
    float acc[4][4] = {};
    for (int k0 = 0; k0 < K; k0 += 16) {
        float4 a4 = *(const float4*)(A + (size_t)(m0 + lr) * K + k0 + lq * 4);
        As[lq * 4 + 0][lr] = a4.x; As[lq * 4 + 1][lr] = a4.y;
        As[lq * 4 + 2][lr] = a4.z; As[lq * 4 + 3][lr] = a4.w;
        float4 b4 = make_float4(0.f, 0.f, 0.f, 0.f);
        if (n0 + lr < N) b4 = *(const float4*)(B + (size_t)(n0 + lr) * K + k0 + lq * 4);
        Bs[lq * 4 + 0][lr] = b4.x; Bs[lq * 4 + 1][lr] = b4.y;
        Bs[lq * 4 + 2][lr] = b4.z; Bs[lq * 4 + 3][lr] = b4.w;
        __syncthreads();
#pragma unroll
        for (int k = 0; k < 16; k++) {
            float4 av = *(const float4*)(&As[k][ty * 4]);
            float4 bv = *(const float4*)(&Bs[k][tx * 4]);
            float avs[4] = {av.x, av.y, av.z, av.w};
            float bvs[4] = {bv.x, bv.y, bv.z, bv.w};
#pragma unroll
            for (int i = 0; i < 4; i++)
#pragma unroll
                for (int jj = 0; jj < 4; jj++)
                    acc[i][jj] = fmaf(avs[i], bvs[jj], acc[i][jj]);
        }
        __syncthreads();
    }
#pragma unroll
    for (int i = 0; i < 4; i++) {
        int m = m0 + ty * 4 + i;
#pragma unroll
        for (int jj = 0; jj < 4; jj++) {
            int n = n0 + tx * 4 + jj;
            if (n < N) C[(size_t)m * N + n] = acc[i][jj] + (bias ? bias[n] : 0.0f);
        }
    }
}

// ---------------- prep: bucket timesteps by age within reset-segment ----------------
__global__ __launch_bounds__(1024) void prep_kernel(const int* __restrict__ start) {
    __shared__ int sa[2048], sb_[2048], sc[2048];
    __shared__ int skmax;
    const int tid = threadIdx.x;
    const int t0 = tid, t1 = tid + 1024;
    if (tid == 0) { g_bar = 0u; skmax = 0; }
    sa[t0] = start[t0] ? t0 : -1;
    sa[t1] = start[t1] ? t1 : -1;
    __syncthreads();
    int* src = sa; int* dst = sb_;
    for (int d = 1; d < 2048; d <<= 1) {
        int v0 = src[t0]; if (t0 >= d) v0 = max(v0, src[t0 - d]);
        int v1 = src[t1]; if (t1 >= d) v1 = max(v1, src[t1 - d]);
        dst[t0] = v0; dst[t1] = v1;
        __syncthreads();
        int* tmp = src; src = dst; dst = tmp;
    }
    int r0v = src[t0], r1v = src[t1];
    int age0 = (r0v < 0) ? t0 : t0 - r0v;
    int age1 = (r1v < 0) ? t1 : t1 - r1v;
    __syncthreads();
    sc[t0] = 0; sc[t1] = 0;
    __syncthreads();
    atomicAdd(&sc[age0], 1);
    atomicAdd(&sc[age1], 1);
    atomicMax(&skmax, max(age0, age1) + 1);
    __syncthreads();
    sa[t0] = sc[t0]; sa[t1] = sc[t1];
    __syncthreads();
    src = sa; dst = sb_;
    for (int d = 1; d < 2048; d <<= 1) {
        int v0 = src[t0]; if (t0 >= d) v0 += src[t0 - d];
        int v1 = src[t1]; if (t1 >= d) v1 += src[t1 - d];
        dst[t0] = v0; dst[t1] = v1;
        __syncthreads();
        int* tmp = src; src = dst; dst = tmp;
    }
    if (tid == 0) { g_off[0] = 0; g_kmax = skmax; }
    g_off[t0 + 1] = src[t0];
    g_off[t1 + 1] = src[t1];
    sc[t0] = 0; sc[t1] = 0;
    __syncthreads();
    int base0 = (age0 == 0) ? 0 : src[age0 - 1];
    g_order[base0 + atomicAdd(&sc[age0], 1)] = t0;
    int base1 = (age1 == 0) ? 0 : src[age1 - 1];
    g_order[base1 + atomicAdd(&sc[age1], 1)] = t1;
}

// ---------------- grid barrier ----------------
__device__ inline void grid_bar(unsigned* barp, unsigned target) {
    __syncthreads();
    if (threadIdx.x == 0) {
        asm volatile("red.release.gpu.global.add.u32 [%0], %1;" :: "l"(barp), "r"(1u) : "memory");
        unsigned v;
        do {
            asm volatile("ld.acquire.gpu.global.u32 %0, [%1];" : "=r"(v) : "l"(barp) : "memory");
        } while (v < target);
    }
    __syncthreads();
}

__device__ __forceinline__ void store_state(int t, int j, float hnew, float* out) {
    g_states[(size_t)t * HD + j] = hnew;
    __half h = __float2half_rn(hnew);
    g_sth[(size_t)t * HD + j] = h;
    g_stl[(size_t)t * HD + j] = __float2half_rn(hnew - __half2float(h));
    if (t == T_STEPS - 1) out[(size_t)T_STEPS * ACTD + j] = hnew;
}

// ---------------- segment-parallel GRU scan, register-resident whh, 2 rows/iter ----------------
__global__ __launch_bounds__(256, 1) void scan_kernel(
    const float* __restrict__ whh, const float* __restrict__ gbn,
    const int* __restrict__ start, const float* __restrict__ state,
    float* __restrict__ out) {
    __shared__ float sH[2][HD];
    const int tid = threadIdx.x;
    const int w = tid >> 5, lane = tid & 31;
    const int j = blockIdx.x * 8 + w;

    const float4* w4 = (const float4*)whh;
    float4 wr[8], wz[8], wn[8];
#pragma unroll
    for (int q = 0; q < 8; q++) {
        wr[q] = w4[(size_t)(0 * HD + j) * 256 + lane + 32 * q];
        wz[q] = w4[(size_t)(1 * HD + j) * 256 + lane + 32 * q];
        wn[q] = w4[(size_t)(2 * HD + j) * 256 + lane + 32 * q];
    }
    const float bnj = gbn[j];
    float4* sH0s = (float4*)sH[0];
    float4* sH1s = (float4*)sH[1];
    const float4* sH0 = (const float4*)sH[0];
    const float4* sH1 = (const float4*)sH[1];
    unsigned* barp = &g_bar;
    const int kmax = g_kmax;
    const int s0 = start[0];
    unsigned epoch = 0;

    if (s0 == 0) {
        sH0s[tid] = ((const float4*)state)[tid];
        __syncthreads();
        float ir = 0.f, iz = 0.f, inn = 0.f;
        if (lane == 0) { ir = g_ig[j]; iz = g_ig[HD + j]; inn = g_ig[2 * HD + j]; }
        float aR = 0.f, aZ = 0.f, aN = 0.f;
#pragma unroll
        for (int q = 0; q < 8; q++) {
            float4 h4 = sH0[lane + 32 * q];
            aR = fmaf(h4.x, wr[q].x, fmaf(h4.y, wr[q].y, fmaf(h4.z, wr[q].z, fmaf(h4.w, wr[q].w, aR))));
            aZ = fmaf(h4.x, wz[q].x, fmaf(h4.y, wz[q].y, fmaf(h4.z, wz[q].z, fmaf(h4.w, wz[q].w, aZ))));
            aN = fmaf(h4.x, wn[q].x, fmaf(h4.y, wn[q].y, fmaf(h4.z, wn[q].z, fmaf(h4.w, wn[q].w, aN))));
        }
#pragma unroll
        for (int off = 16; off; off >>= 1) {
            aR += __shfl_xor_sync(0xffffffffu, aR, off);
            aZ += __shfl_xor_sync(0xffffffffu, aZ, off);
            aN += __shfl_xor_sync(0xffffffffu, aN, off);
        }
        if (lane == 0) {
            float rv = sigmoidf_(ir + aR);
            float uv = sigmoidf_(iz + aZ);
            float nv = tanhf(inn + rv * (aN + bnj));
            float hin = sH[0][j];
            store_state(0, j, nv + uv * (hin - nv), out);
        }
        __syncthreads();
    }
    {
        const int beg = g_off[0], end = g_off[1];
        for (int r = beg + lane; r < end; r += 32) {
            const int t = g_order[r];
            if (t == 0 && s0 == 0) continue;
            const float* igt = g_ig + (size_t)t * (3 * HD);
            float rv = sigmoidf_(igt[j]);
            float uv = sigmoidf_(igt[HD + j]);
            float nv = tanhf(igt[2 * HD + j] + rv * bnj);
            store_state(t, j, nv - uv * nv, out);
        }
    }
    grid_bar(barp, (++epoch) * SCAN_BLOCKS);

    for (int k = 1; k < kmax; k++) {
        const int beg = g_off[k], end = g_off[k + 1];
        int r = beg;
        int tA = g_order[r];
        float4 nxtA = __ldcg((const float4*)(g_states + (size_t)(tA - 1) * HD) + tid);
        int tB = (r + 1 < end) ? g_order[r + 1] : -1;
        float4 nxtB = make_float4(0.f, 0.f, 0.f, 0.f);
        if (tB >= 0) nxtB = __ldcg((const float4*)(g_states + (size_t)(tB - 1) * HD) + tid);

        while (r < end) {
            const int curA = tA, curB = tB;
            sH0s[tid] = nxtA;
            if (curB >= 0) sH1s[tid] = nxtB;
            __syncthreads();

            const int rn = r + 2;
            if (rn < end) {
                tA = g_order[rn];
                nxtA = __ldcg((const float4*)(g_states + (size_t)(tA - 1) * HD) + tid);
            }
            if (rn + 1 < end) {
                tB = g_order[rn + 1];
                nxtB = __ldcg((const float4*)(g_states + (size_t)(tB - 1) * HD) + tid);
            } else {
                tB = -1;
            }

            float irA = 0.f, izA = 0.f, inA = 0.f, irB = 0.f, izB = 0.f, inB = 0.f;
            if (lane == 0) {
                const float* iga = g_ig + (size_t)curA * (3 * HD);
                irA = iga[j]; izA = iga[HD + j]; inA = iga[2 * HD + j];
                if (curB >= 0) {
                    const float* igb = g_ig + (size_t)curB * (3 * HD);
                    irB = igb[j]; izB = igb[HD + j]; inB = igb[2 * HD + j];
                }
            }

            float aR = 0.f, aZ = 0.f, aN = 0.f, bR = 0.f, bZ = 0.f, bN = 0.f;
#pragma unroll
            for (int q = 0; q < 8; q++) {
                const int c = lane + 32 * q;
                float4 hA = sH0[c];
                float4 hB = sH1[c];
                float4 r4v = wr[q], z4v = wz[q], n4v = wn[q];
                aR = fmaf(hA.x, r4v.x, fmaf(hA.y, r4v.y, fmaf(hA.z, r4v.z, fmaf(hA.w, r4v.w, aR))));
                bR = fmaf(hB.x, r4v.x, fmaf(hB.y, r4v.y, fmaf(hB.z, r4v.z, fmaf(hB.w, r4v.w, bR))));
                aZ = fmaf(hA.x, z4v.x, fmaf(hA.y, z4v.y, fmaf(hA.z, z4v.z, fmaf(hA.w, z4v.w, aZ))));
                bZ = fmaf(hB.x, z4v.x, fmaf(hB.y, z4v.y, fmaf(hB.z, z4v.z, fmaf(hB.w, z4v.w, bZ))));
                aN = fmaf(hA.x, n4v.x, fmaf(hA.y, n4v.y, fmaf(hA.z, n4v.z, fmaf(hA.w, n4v.w, aN))));
                bN = fmaf(hB.x, n4v.x, fmaf(hB.y, n4v.y, fmaf(hB.z, n4v.z, fmaf(hB.w, n4v.w, bN))));
            }
#pragma unroll
            for (int off = 16; off; off >>= 1) {
                aR += __shfl_xor_sync(0xffffffffu, aR, off);
                aZ += __shfl_xor_sync(0xffffffffu, aZ, off);
                aN += __shfl_xor_sync(0xffffffffu, aN, off);
                bR += __shfl_xor_sync(0xffffffffu, bR, off);
                bZ += __shfl_xor_sync(0xffffffffu, bZ, off);
                bN += __shfl_xor_sync(0xffffffffu, bN, off);
            }
            if (lane == 0) {
                {
                    float rv = sigmoidf_(irA + aR);
                    float uv = sigmoidf_(izA + aZ);
                    float nv = tanhf(inA + rv * (aN + bnj));
                    float hin = sH[0][j];
                    store_state(curA, j, nv + uv * (hin - nv), out);
                }
                if (curB >= 0) {
                    float rv = sigmoidf_(irB + bR);
                    float uv = sigmoidf_(izB + bZ);
                    float nv = tanhf(inB + rv * (bN + bnj));
                    float hin = sH[1][j];
                    store_state(curB, j, nv + uv * (hin - nv), out);
                }
            }
            __syncthreads();
            r = rn;
        }
        grid_bar(barp, (++epoch) * SCAN_BLOCKS);
    }
}

// ---------------- launch ----------------
extern "C" void kernel_launch(void* const* d_in, const int* in_sizes, int n_in,
                              void* d_out, int out_size) {
    (void)in_sizes; (void)n_in;
    const float* x      = (const float*)d_in[0];
    const float* state  = (const float*)d_in[1];
    const int*   start  = (const int*)d_in[2];
    const float* pre_wm = (const float*)d_in[4];
    const float* pre_ws = (const float*)d_in[5];
    const float* pre_bm = (const float*)d_in[6];
    const float* pre_bs = (const float*)d_in[7];
    const float* wih    = (const float*)d_in[8];
    const float* whh    = (const float*)d_in[9];
    const float* gru_b  = (const float*)d_in[10];
    const float* gru_bn = (const float*)d_in[11];
    const float* p1_wm  = (const float*)d_in[12];
    const float* p1_ws  = (const float*)d_in[13];
    const float* p1_bm  = (const float*)d_in[14];
    const float* p1_bs  = (const float*)d_in[15];
    const float* p2_wm  = (const float*)d_in[16];
    const float* p2_ws  = (const float*)d_in[17];
    const float* p2_bm  = (const float*)d_in[18];
    const float* p2_bs  = (const float*)d_in[19];
    const float* p3_wm  = (const float*)d_in[20];
    const float* p3_ws  = (const float*)d_in[21];
    const float* p3_bm  = (const float*)d_in[22];
    const float* p3_bs  = (const float*)d_in[23];
    float* out = (float*)d_out;
    (void)out_size;

    unsigned nk[8][2];
    for (int i = 0; i < 8; i++) {
        unsigned a = 0u, b = (unsigned)i;
        tf_block(0u, 7u, a, b);
        nk[i][0] = a; nk[i][1] = b;
    }

    float *preB, *p1B, *p2B, *p3W, *p3B, *ig, *states, *y2;
    __half *xh, *xl, *preWh, *preWl, *wihh, *wihl, *p1Wh, *p1Wl, *p2Wh, *p2Wl;
    __half *zh, *zl, *sth, *stl, *y1h, *y1l;
    cudaGetSymbolAddress((void**)&preB, g_preB);
    cudaGetSymbolAddress((void**)&p1B, g_p1B);
    cudaGetSymbolAddress((void**)&p2B, g_p2B);
    cudaGetSymbolAddress((void**)&p3W, g_p3W);
    cudaGetSymbolAddress((void**)&p3B, g_p3B);
    cudaGetSymbolAddress((void**)&ig, g_ig);
    cudaGetSymbolAddress((void**)&states, g_states);
    cudaGetSymbolAddress((void**)&y2, g_y2);
    cudaGetSymbolAddress((void**)&xh, g_xh);
    cudaGetSymbolAddress((void**)&xl, g_xl);
    cudaGetSymbolAddress((void**)&preWh, g_preWh);
    cudaGetSymbolAddress((void**)&preWl, g_preWl);
    cudaGetSymbolAddress((void**)&wihh, g_wihh);
    cudaGetSymbolAddress((void**)&wihl, g_wihl);
    cudaGetSymbolAddress((void**)&p1Wh, g_p1Wh);
    cudaGetSymbolAddress((void**)&p1Wl, g_p1Wl);
    cudaGetSymbolAddress((void**)&p2Wh, g_p2Wh);
    cudaGetSymbolAddress((void**)&p2Wl, g_p2Wl);
    cudaGetSymbolAddress((void**)&zh, g_zh);
    cudaGetSymbolAddress((void**)&zl, g_zl);
    cudaGetSymbolAddress((void**)&sth, g_sth);
    cudaGetSymbolAddress((void**)&stl, g_stl);
    cudaGetSymbolAddress((void**)&y1h, g_y1h);
    cudaGetSymbolAddress((void**)&y1l, g_y1l);

    cudaFuncSetAttribute(mma_gemm_kernel, cudaFuncAttributeMaxDynamicSharedMemorySize,
                         MMA_SMEM_BYTES);

    // Launch order arranged so launch #6 (ncu -s 5 -c 1) is GEMM2, the largest kernel.
    // 1: wih split
    conv_split_kernel<<<(3 * HD * MLPD / 4 + 255) / 256, 256>>>(wih, wihh, wihl, 3 * HD * MLPD / 4);
    // 2: preW noise->split, 3: preB noise
    { int n = MLPD * OBS; gen_noisy_w_kernel<<<(n + 255) / 256, 256>>>(pre_wm, pre_ws, preWh, preWl, n, nk[0][0], nk[0][1]); }
    { int n = MLPD;       gen_noisy_kernel<<<(n + 255) / 256, 256>>>(pre_bm, pre_bs, preB, n, nk[1][0], nk[1][1]); }
    // 4: x split
    conv_split_kernel<<<(T_STEPS * OBS / 4 + 255) / 256, 256>>>(x, xh, xl, T_STEPS * OBS / 4);
    // 5: GEMM1: z = mish(x @ preW^T + preB) -> zh/zl   [2048,1024], K=512
    mma_gemm_kernel<<<dim3(MLPD / 128, T_STEPS / 128), 256, MMA_SMEM_BYTES>>>(
        xh, xl, preWh, preWl, preB, nullptr, zh, zl, T_STEPS, MLPD, OBS, 1, 1);
    // 6: GEMM2: igates = z @ wih^T + gru_b -> fp32     [2048,3072], K=1024  (PROFILED)
    mma_gemm_kernel<<<dim3(3 * HD / 128, T_STEPS / 128), 256, MMA_SMEM_BYTES>>>(
        zh, zl, wihh, wihl, gru_b, ig, nullptr, nullptr, T_STEPS, 3 * HD, MLPD, 0, 0);
    // 7: prep, 8: scan
    prep_kernel<<<1, 1024>>>(start);
    scan_kernel<<<SCAN_BLOCKS, 256>>>(whh, gru_bn, start, state, out);
    // 9-14: remaining noise
    { int n = MLPD * HD;   gen_noisy_w_kernel<<<(n + 255) / 256, 256>>>(p1_wm, p1_ws, p1Wh, p1Wl, n, nk[2][0], nk[2][1]); }
    { int n = MLPD;        gen_noisy_kernel<<<(n + 255) / 256, 256>>>(p1_bm, p1_bs, p1B, n, nk[3][0], nk[3][1]); }
    { int n = MLPD * MLPD; gen_noisy_w_kernel<<<(n + 255) / 256, 256>>>(p2_wm, p2_ws, p2Wh, p2Wl, n, nk[4][0], nk[4][1]); }
    { int n = MLPD;        gen_noisy_kernel<<<(n + 255) / 256, 256>>>(p2_bm, p2_bs, p2B, n, nk[5][0], nk[5][1]); }
    { int n = ACTD * MLPD; gen_noisy_kernel<<<(n + 255) / 256, 256>>>(p3_wm, p3_ws, p3W, n, nk[6][0], nk[6][1]); }
    { int n = ACTD;        gen_noisy_kernel<<<(n + 255) / 256, 256>>>(p3_bm, p3_bs, p3B, n, nk[7][0], nk[7][1]); }
    // 15: GEMM3: y1 = mish(states @ p1W^T + p1B) -> y1h/y1l
    mma_gemm_kernel<<<dim3(MLPD / 128, T_STEPS / 128), 256, MMA_SMEM_BYTES>>>(
        sth, stl, p1Wh, p1Wl, p1B, nullptr, y1h, y1l, T_STEPS, MLPD, HD, 1, 1);
    // 16: GEMM4: y2 = mish(y1 @ p2W^T + p2B) -> fp32
    mma_gemm_kernel<<<dim3(MLPD / 128, T_STEPS / 128), 256, MMA_SMEM_BYTES>>>(
        y1h, y1l, p2Wh, p2Wl, p2B, y2, nullptr, nullptr, T_STEPS, MLPD, MLPD, 1, 0);
    // 17: final layer -> d_out[0 : 2048*16]
    sgemm64_kernel<<<dim3(1, T_STEPS / 64), 256>>>(y2, p3W, p3B, out, T_STEPS, ACTD, MLPD);
}

// round 11
// speedup vs baseline: 7.4684x; 1.0059x over previous
#include <cuda_runtime.h>
#include <cuda_fp16.h>
#include <cstdint>

#define T_STEPS 2048
#define OBS 512
#define MLPD 1024
#define HD 1024
#define ACTD 16
#define SCAN_BLOCKS 128

// ---------------- device scratch (no allocations allowed) ----------------
__device__ float g_preB[MLPD];
__device__ float g_p1B[MLPD];
__device__ float g_p2B[MLPD];
__device__ float g_p3W[ACTD * MLPD];
__device__ float g_p3B[ACTD];
__device__ float g_ig[(size_t)T_STEPS * 3 * HD];
__device__ float g_states[(size_t)T_STEPS * HD];
__device__ float g_y2[T_STEPS * MLPD];
__device__ __half g_xh[T_STEPS * OBS],  g_xl[T_STEPS * OBS];
__device__ __half g_preWh[MLPD * OBS],  g_preWl[MLPD * OBS];
__device__ __half g_wihh[3 * HD * MLPD], g_wihl[3 * HD * MLPD];
__device__ __half g_p1Wh[MLPD * HD],    g_p1Wl[MLPD * HD];
__device__ __half g_p2Wh[MLPD * MLPD],  g_p2Wl[MLPD * MLPD];
__device__ __half g_zh[T_STEPS * MLPD], g_zl[T_STEPS * MLPD];
__device__ __half g_sth[(size_t)T_STEPS * HD], g_stl[(size_t)T_STEPS * HD];
__device__ __half g_y1h[T_STEPS * MLPD], g_y1l[T_STEPS * MLPD];
__device__ unsigned g_bar;
__device__ int g_order[T_STEPS];
__device__ int g_off[T_STEPS + 1];
__device__ int g_kmax;

// ---------------- threefry2x32 (matches JAX) ----------------
#define TF_ROUND(x0, x1, R) { x0 += x1; x1 = (x1 << R) | (x1 >> (32 - R)); x1 ^= x0; }

__host__ __device__ inline void tf_block(unsigned k0, unsigned k1, unsigned &x0, unsigned &x1) {
    unsigned ks2 = k0 ^ k1 ^ 0x1BD11BDAu;
    x0 += k0; x1 += k1;
    TF_ROUND(x0, x1, 13) TF_ROUND(x0, x1, 15) TF_ROUND(x0, x1, 26) TF_ROUND(x0, x1, 6)
    x0 += k1; x1 += ks2 + 1u;
    TF_ROUND(x0, x1, 17) TF_ROUND(x0, x1, 29) TF_ROUND(x0, x1, 16) TF_ROUND(x0, x1, 24)
    x0 += ks2; x1 += k0 + 2u;
    TF_ROUND(x0, x1, 13) TF_ROUND(x0, x1, 15) TF_ROUND(x0, x1, 26) TF_ROUND(x0, x1, 6)
    x0 += k0; x1 += k1 + 3u;
    TF_ROUND(x0, x1, 17) TF_ROUND(x0, x1, 29) TF_ROUND(x0, x1, 16) TF_ROUND(x0, x1, 24)
    x0 += k1; x1 += ks2 + 4u;
    TF_ROUND(x0, x1, 13) TF_ROUND(x0, x1, 15) TF_ROUND(x0, x1, 26) TF_ROUND(x0, x1, 6)
    x0 += ks2; x1 += k0 + 5u;
}

// XLA f32 erf_inv (Giles)
__device__ inline float xla_erfinv(float x) {
    float w = -log1pf(-x * x);
    float p;
    if (w < 5.0f) {
        w -= 2.5f;
        p = 2.81022636e-08f;
        p = fmaf(p, w, 3.43273939e-07f);
        p = fmaf(p, w, -3.5233877e-06f);
        p = fmaf(p, w, -4.39150654e-06f);
        p = fmaf(p, w, 0.00021858087f);
        p = fmaf(p, w, -0.00125372503f);
        p = fmaf(p, w, -0.00417768164f);
        p = fmaf(p, w, 0.246640727f);
        p = fmaf(p, w, 1.50140941f);
    } else {
        w = sqrtf(w) - 3.0f;
        p = -0.000200214257f;
        p = fmaf(p, w, 0.000100950558f);
        p = fmaf(p, w, 0.00134934322f);
        p = fmaf(p, w, -0.00367342844f);
        p = fmaf(p, w, 0.00573950773f);
        p = fmaf(p, w, -0.0076224613f);
        p = fmaf(p, w, 0.00943887047f);
        p = fmaf(p, w, 1.00167406f);
        p = fmaf(p, w, 2.83297682f);
    }
    return p * x;
}

__device__ inline float bits_to_normal(unsigned b) {
    float u1 = __uint_as_float((b >> 9) | 0x3f800000u) - 1.0f;
    float v = fmaf(u1, 1.99999994f, -0.99999994f);
    v = fmaxf(v, -0.99999994f);
    return 1.41421356f * xla_erfinv(v);
}

// Partitionable threefry: bits[i] = x0^x1 of block with counter (0, i)
__global__ void gen_noisy_kernel(const float* __restrict__ wm, const float* __restrict__ ws,
                                 float* __restrict__ dst, int n, unsigned k0, unsigned k1) {
    int i = blockIdx.x * blockDim.x + threadIdx.x;
    if (i >= n) return;
    unsigned x0 = 0u, x1 = (unsigned)i;
    tf_block(k0, k1, x0, x1);
    dst[i] = fmaf(ws[i], bits_to_normal(x0 ^ x1), wm[i]);
}

// noisy weights straight to fp16 hi/lo
__global__ void gen_noisy_w_kernel(const float* __restrict__ wm, const float* __restrict__ ws,
                                   __half* __restrict__ hi, __half* __restrict__ lo,
                                   int n, unsigned k0, unsigned k1) {
    int i = blockIdx.x * blockDim.x + threadIdx.x;
    if (i >= n) return;
    unsigned x0 = 0u, x1 = (unsigned)i;
    tf_block(k0, k1, x0, x1);
    float v = fmaf(ws[i], bits_to_normal(x0 ^ x1), wm[i]);
    __half h = __float2half_rn(v);
    hi[i] = h;
    lo[i] = __float2half_rn(v - __half2float(h));
}

// ---------------- activations ----------------
__device__ inline float mishf(float x) {
    float sp = fmaxf(x, 0.0f) + log1pf(expf(-fabsf(x)));
    return x * tanhf(sp);
}
__device__ inline float sigmoidf_(float x) { return 1.0f / (1.0f + expf(-x)); }

__device__ __forceinline__ uint32_t h2u(__half2 v) {
    return *reinterpret_cast<uint32_t*>(&v);
}

// ---------------- fp32 -> fp16 hi/lo split (n4 = n/4) ----------------
__global__ void conv_split_kernel(const float* __restrict__ src,
                                  __half* __restrict__ hi,
                                  __half* __restrict__ lo, int n4) {
    int i = blockIdx.x * blockDim.x + threadIdx.x;
    if (i >= n4) return;
    float4 v = ((const float4*)src)[i];
    __half2 h0, h1, l0, l1;
    h0.x = __float2half_rn(v.x); h0.y = __float2half_rn(v.y);
    h1.x = __float2half_rn(v.z); h1.y = __float2half_rn(v.w);
    l0.x = __float2half_rn(v.x - __half2float(h0.x));
    l0.y = __float2half_rn(v.y - __half2float(h0.y));
    l1.x = __float2half_rn(v.z - __half2float(h1.x));
    l1.y = __float2half_rn(v.w - __half2float(h1.y));
    ((uint2*)hi)[i] = make_uint2(h2u(h0), h2u(h1));
    ((uint2*)lo)[i] = make_uint2(h2u(l0), h2u(l1));
}

// ---------------- mma / ldmatrix / cp.async wrappers ----------------
__device__ __forceinline__ void mma16816(float* c, const uint32_t* a, const uint32_t* b) {
    asm volatile(
        "mma.sync.aligned.m16n8k16.row.col.f32.f16.f16.f32 "
        "{%0,%1,%2,%3}, {%4,%5,%6,%7}, {%8,%9}, {%0,%1,%2,%3};\n"
        : "+f"(c[0]), "+f"(c[1]), "+f"(c[2]), "+f"(c[3])
        : "r"(a[0]), "r"(a[1]), "r"(a[2]), "r"(a[3]), "r"(b[0]), "r"(b[1]));
}
__device__ __forceinline__ void mma16816h(uint32_t* c, const uint32_t* a, const uint32_t* b) {
    asm volatile(
        "mma.sync.aligned.m16n8k16.row.col.f16.f16.f16.f16 "
        "{%0,%1}, {%2,%3,%4,%5}, {%6,%7}, {%0,%1};\n"
        : "+r"(c[0]), "+r"(c[1])
        : "r"(a[0]), "r"(a[1]), "r"(a[2]), "r"(a[3]), "r"(b[0]), "r"(b[1]));
}
__device__ __forceinline__ void ldsm4(uint32_t& r0, uint32_t& r1, uint32_t& r2, uint32_t& r3,
                                      uint32_t addr) {
    asm volatile("ldmatrix.sync.aligned.m8n8.x4.shared.b16 {%0,%1,%2,%3}, [%4];"
                 : "=r"(r0), "=r"(r1), "=r"(r2), "=r"(r3) : "r"(addr));
}
__device__ __forceinline__ uint32_t smem_u32(const void* p) {
    uint32_t a;
    asm("{ .reg .u64 t; cvta.to.shared.u64 t, %1; cvt.u32.u64 %0, t; }" : "=r"(a) : "l"(p));
    return a;
}
__device__ __forceinline__ void cp16(uint32_t saddr, const void* gptr) {
    asm volatile("cp.async.cg.shared.global [%0], [%1], 16;" :: "r"(saddr), "l"(gptr));
}
__device__ __forceinline__ void cp_commit() {
    asm volatile("cp.async.commit_group;" ::: "memory");
}
__device__ __forceinline__ void cp_wait1() {
    asm volatile("cp.async.wait_group 1;" ::: "memory");
}
__device__ __forceinline__ void cp_wait0() {
    asm volatile("cp.async.wait_group 0;" ::: "memory");
}

// ============ split-fp16 tensor-core GEMM: C[M,N] = A[M,K] @ B[N,K]^T + bias ============
// CTA tile 128x128, 8 warps (2m x 4n), warp tile 64x32, k-chunk 32,
// cp.async 2-stage double buffer, 2 CTAs/SM. Row pitch 40 halves (80B).
// Main term f32-accum; corrections (Al*Bh + Ah*Bl) in f16-accum (2x rate).
#define PADE 40
#define OFF_AH 0
#define OFF_AL (128 * PADE)
#define OFF_BH (2 * 128 * PADE)
#define OFF_BL (3 * 128 * PADE)
#define BUFE (4 * 128 * PADE)
#define MMA_SMEM_BYTES (2 * BUFE * 2)

__global__ __launch_bounds__(256, 2) void mma_gemm_kernel(
    const __half* __restrict__ Ah, const __half* __restrict__ Al,
    const __half* __restrict__ Bh, const __half* __restrict__ Bl,
    const float* __restrict__ bias, float* __restrict__ C,
    __half* __restrict__ Ch, __half* __restrict__ Cl,
    int M, int N, int K, int act, int osplit) {
    extern __shared__ __half smb[];
    const uint32_t sbase = smem_u32(smb);
    const int tid = threadIdx.x;
    const int wid = tid >> 5, lane = tid & 31;
    const int r4 = lane >> 2, lq = lane & 3;
    const int m0 = blockIdx.y * 128, n0 = blockIdx.x * 128;
    const int wm = (wid & 1) * 64, wn = (wid >> 1) * 32;

    const int aro = lane & 15, ako = (lane >> 4) << 3;
    const int bro = (lane & 7) + ((lane >> 4) << 3), bko = ((lane >> 3) & 1) << 3;

    float acc[4][4][4] = {};
    uint32_t corr[4][4][2] = {};
    const int nch = K >> 5;

    const int ld_r = tid >> 2, ld_q = tid & 3;
    const uint32_t ld_e = (uint32_t)(ld_r * PADE + ld_q * 8) * 2;

    {
#pragma unroll
        for (int c = 0; c < 2; c++) {
            if (c >= nch) break;
            const int k0 = c << 5;
            const uint32_t bb = sbase + (uint32_t)((c & 1) * BUFE * 2);
#pragma unroll
            for (int q = 0; q < 2; q++) {
                int r = ld_r + 64 * q;
                uint32_t e = ld_e + (uint32_t)(64 * q * PADE) * 2;
                size_t goA = (size_t)(m0 + r) * K + k0 + ld_q * 8;
                size_t goB = (size_t)(n0 + r) * K + k0 + ld_q * 8;
                cp16(bb + OFF_AH * 2 + e, Ah + goA);
                cp16(bb + OFF_AL * 2 + e, Al + goA);
                cp16(bb + OFF_BH * 2 + e, Bh + goB);
                cp16(bb + OFF_BL * 2 + e, Bl + goB);
            }
            cp_commit();
        }
    }

    for (int c = 0; c < nch; c++) {
        if (c + 1 < nch) cp_wait1(); else cp_wait0();
        __syncthreads();

        const uint32_t bb = sbase + (uint32_t)((c & 1) * BUFE * 2);
#pragma unroll
        for (int ks = 0; ks < 2; ks++) {
            uint32_t ahf[4][4], alf[4][4], bhf[4][2], blf[4][2];
#pragma unroll
            for (int am = 0; am < 4; am++) {
                uint32_t ar = (uint32_t)((wm + am * 16 + aro) * PADE + ks * 16 + ako) * 2;
                ldsm4(ahf[am][0], ahf[am][1], ahf[am][2], ahf[am][3], bb + OFF_AH * 2 + ar);
                ldsm4(alf[am][0], alf[am][1], alf[am][2], alf[am][3], bb + OFF_AL * 2 + ar);
            }
#pragma unroll
            for (int nb = 0; nb < 2; nb++) {
                uint32_t br = (uint32_t)((wn + nb * 16 + bro) * PADE + ks * 16 + bko) * 2;
                ldsm4(bhf[nb * 2][0], bhf[nb * 2][1], bhf[nb * 2 + 1][0], bhf[nb * 2 + 1][1],
                      bb + OFF_BH * 2 + br);
                ldsm4(blf[nb * 2][0], blf[nb * 2][1], blf[nb * 2 + 1][0], blf[nb * 2 + 1][1],
                      bb + OFF_BL * 2 + br);
            }
#pragma unroll
            for (int am = 0; am < 4; am++)
#pragma unroll
                for (int bn = 0; bn < 4; bn++) {
                    mma16816(acc[am][bn], ahf[am], bhf[bn]);
                    mma16816h(corr[am][bn], alf[am], bhf[bn]);
                    mma16816h(corr[am][bn], ahf[am], blf[bn]);
                }
        }
        __syncthreads();

        if (c + 2 < nch) {
            const int k0 = (c + 2) << 5;
            const uint32_t nb = sbase + (uint32_t)(((c + 2) & 1) * BUFE * 2);
#pragma unroll
            for (int q = 0; q < 2; q++) {
                int r = ld_r + 64 * q;
                uint32_t e = ld_e + (uint32_t)(64 * q * PADE) * 2;
                size_t goA = (size_t)(m0 + r) * K + k0 + ld_q * 8;
                size_t goB = (size_t)(n0 + r) * K + k0 + ld_q * 8;
                cp16(nb + OFF_AH * 2 + e, Ah + goA);
                cp16(nb + OFF_AL * 2 + e, Al + goA);
                cp16(nb + OFF_BH * 2 + e, Bh + goB);
                cp16(nb + OFF_BL * 2 + e, Bl + goB);
            }
            cp_commit();
        }
    }

#pragma unroll
    for (int am = 0; am < 4; am++) {
        const int row = m0 + wm + am * 16 + r4;
#pragma unroll
        for (int bn = 0; bn < 4; bn++) {
            const int col = n0 + wn + bn * 8 + 2 * lq;
            const float b0 = bias[col], b1 = bias[col + 1];
            float2 c01 = __half22float2(*reinterpret_cast<__half2*>(&corr[am][bn][0]));
            float2 c23 = __half22float2(*reinterpret_cast<__half2*>(&corr[am][bn][1]));
            float v0 = acc[am][bn][0] + c01.x + b0, v1 = acc[am][bn][1] + c01.y + b1;
            float v2 = acc[am][bn][2] + c23.x + b0, v3 = acc[am][bn][3] + c23.y + b1;
            if (act) { v0 = mishf(v0); v1 = mishf(v1); v2 = mishf(v2); v3 = mishf(v3); }
            if (osplit) {
                __half2 h01, h23, l01, l23;
                h01.x = __float2half_rn(v0); h01.y = __float2half_rn(v1);
                h23.x = __float2half_rn(v2); h23.y = __float2half_rn(v3);
                l01.x = __float2half_rn(v0 - __half2float(h01.x));
                l01.y = __float2half_rn(v1 - __half2float(h01.y));
                l23.x = __float2half_rn(v2 - __half2float(h23.x));
                l23.y = __float2half_rn(v3 - __half2float(h23.y));
                *(uint32_t*)(Ch + (size_t)row * N + col) = h2u(h01);
                *(uint32_t*)(Cl + (size_t)row * N + col) = h2u(l01);
                *(uint32_t*)(Ch + (size_t)(row + 8) * N + col) = h2u(h23);
                *(uint32_t*)(Cl + (size_t)(row + 8) * N + col) = h2u(l23);
            } else {
                *(float2*)(C + (size_t)row * N + col) = make_float2(v0, v1);
                *(float2*)(C + (size_t)(row + 8) * N + col) = make_float2(v2, v3);
            }
        }
    }
}

// ---------------- small SGEMM (p3, N=16) ----------------
__global__ __launch_bounds__(256) void sgemm64_kernel(
    const float* __restrict__ A, const float* __restrict__ B,
    const float* __restrict__ bias, float* __restrict__ C,
    int M, int N, int K) {
    __shared__ float As[16][64];
    __shared__ float Bs[16][64];
    const int m0 = blockIdx.y * 64;
    const int n0 = blockIdx.x * 64;
    const int tid = threadIdx.x;
    const int tx = tid & 15, ty = tid >> 4;
    const int lr = tid >> 2, lq = tid & 3;
    float acc[4][4] = {};
    for (int k0 = 0; k0 < K; k0 += 16) {
        float4 a4 = *(const float4*)(A + (size_t)(m0 + lr) * K + k0 + lq * 4);
        As[lq * 4 + 0][lr] = a4.x; As[lq * 4 + 1][lr] = a4.y;
        As[lq * 4 + 2][lr] = a4.z; As[lq * 4 + 3][lr] = a4.w;
        float4 b4 = make_float4(0.f, 0.f, 0.f, 0.f);
        if (n0 + lr < N) b4 = *(const float4*)(B + (size_t)(n0 + lr) * K + k0 + lq * 4);
        Bs[lq * 4 + 0][lr] = b4.x; Bs[lq * 4 + 1][lr] = b4.y;
        Bs[lq * 4 + 2][lr] = b4.z; Bs[lq * 4 + 3][lr] = b4.w;
        __syncthreads();
#pragma unroll
        for (int k = 0; k < 16; k++) {
            float4 av = *(const float4*)(&As[k][ty * 4]);
            float4 bv = *(const float4*)(&Bs[k][tx * 4]);
            float avs[4] = {av.x, av.y, av.z, av.w};
            float bvs[4] = {bv.x, bv.y, bv.z, bv.w};
#pragma unroll
            for (int i = 0; i < 4; i++)
#pragma unroll
                for (int jj = 0; jj < 4; jj++)
                    acc[i][jj] = fmaf(avs[i], bvs[jj], acc[i][jj]);
        }
        __syncthreads();
    }
#pragma unroll
    for (int i = 0; i < 4; i++) {
        int m = m0 + ty * 4 + i;
#pragma unroll
        for (int jj = 0; jj < 4; jj++) {
            int n = n0 + tx * 4 + jj;
            if (n < N) C[(size_t)m * N + n] = acc[i][jj] + (bias ? bias[n] : 0.0f);
        }
    }
}

// ---------------- prep: bucket timesteps by age within reset-segment ----------------
__global__ __launch_bounds__(1024) void prep_kernel(const int* __restrict__ start) {
    __shared__ int sa[2048], sb_[2048], sc[2048];
    __shared__ int skmax;
    const int tid = threadIdx.x;
    const int t0 = tid, t1 = tid + 1024;
    if (tid == 0) { g_bar = 0u; skmax = 0; }
    sa[t0] = start[t0] ? t0 : -1;
    sa[t1] = start[t1] ? t1 : -1;
    __syncthreads();
    int* src = sa; int* dst = sb_;
    for (int d = 1; d < 2048; d <<= 1) {
        int v0 = src[t0]; if (t0 >= d) v0 = max(v0, src[t0 - d]);
        int v1 = src[t1]; if (t1 >= d) v1 = max(v1, src[t1 - d]);
        dst[t0] = v0; dst[t1] = v1;
        __syncthreads();
        int* tmp = src; src = dst; dst = tmp;
    }
    int r0v = src[t0], r1v = src[t1];
    int age0 = (r0v < 0) ? t0 : t0 - r0v;
    int age1 = (r1v < 0) ? t1 : t1 - r1v;
    __syncthreads();
    sc[t0] = 0; sc[t1] = 0;
    __syncthreads();
    atomicAdd(&sc[age0], 1);
    atomicAdd(&sc[age1], 1);
    atomicMax(&skmax, max(age0, age1) + 1);
    __syncthreads();
    sa[t0] = sc[t0]; sa[t1] = sc[t1];
    __syncthreads();
    src = sa; dst = sb_;
    for (int d = 1; d < 2048; d <<= 1) {
        int v0 = src[t0]; if (t0 >= d) v0 += src[t0 - d];
        int v1 = src[t1]; if (t1 >= d) v1 += src[t1 - d];
        dst[t0] = v0; dst[t1] = v1;
        __syncthreads();
        int* tmp = src; src = dst; dst = tmp;
    }
    if (tid == 0) { g_off[0] = 0; g_kmax = skmax; }
    g_off[t0 + 1] = src[t0];
    g_off[t1 + 1] = src[t1];
    sc[t0] = 0; sc[t1] = 0;
    __syncthreads();
    int base0 = (age0 == 0) ? 0 : src[age0 - 1];
    g_order[base0 + atomicAdd(&sc[age0], 1)] = t0;
    int base1 = (age1 == 0) ? 0 : src[age1 - 1];
    g_order[base1 + atomicAdd(&sc[age1], 1)] = t1;
}

// ---------------- grid barrier ----------------
__device__ inline void grid_bar(unsigned* barp, unsigned target) {
    __syncthreads();
    if (threadIdx.x == 0) {
        asm volatile("red.release.gpu.global.add.u32 [%0], %1;" :: "l"(barp), "r"(1u) : "memory");
        unsigned v;
        do {
            asm volatile("ld.acquire.gpu.global.u32 %0, [%1];" : "=r"(v) : "l"(barp) : "memory");
        } while (v < target);
    }
    __syncthreads();
}

__device__ __forceinline__ void store_state(int t, int j, float hnew, float* out) {
    g_states[(size_t)t * HD + j] = hnew;
    __half h = __float2half_rn(hnew);
    g_sth[(size_t)t * HD + j] = h;
    g_stl[(size_t)t * HD + j] = __float2half_rn(hnew - __half2float(h));
    if (t == T_STEPS - 1) out[(size_t)T_STEPS * ACTD + j] = hnew;
}

// ---------------- segment-parallel GRU scan, register-resident whh, 2 rows/iter ----------------
__global__ __launch_bounds__(256, 1) void scan_kernel(
    const float* __restrict__ whh, const float* __restrict__ gbn,
    const int* __restrict__ start, const float* __restrict__ state,
    float* __restrict__ out) {
    __shared__ float sH[2][HD];
    const int tid = threadIdx.x;
    const int w = tid >> 5, lane = tid & 31;
    const int j = blockIdx.x * 8 + w;

    const float4* w4 = (const float4*)whh;
    float4 wr[8], wz[8], wn[8];
#pragma unroll
    for (int q = 0; q < 8; q++) {
        wr[q] = w4[(size_t)(0 * HD + j) * 256 + lane + 32 * q];
        wz[q] = w4[(size_t)(1 * HD + j) * 256 + lane + 32 * q];
        wn[q] = w4[(size_t)(2 * HD + j) * 256 + lane + 32 * q];
    }
    const float bnj = gbn[j];
    float4* sH0s = (float4*)sH[0];
    float4* sH1s = (float4*)sH[1];
    const float4* sH0 = (const float4*)sH[0];
    const float4* sH1 = (const float4*)sH[1];
    unsigned* barp = &g_bar;
    const int kmax = g_kmax;
    const int s0 = start[0];
    unsigned epoch = 0;

    if (s0 == 0) {
        sH0s[tid] = ((const float4*)state)[tid];
        __syncthreads();
        float ir = 0.f, iz = 0.f, inn = 0.f;
        if (lane == 0) { ir = g_ig[j]; iz = g_ig[HD + j]; inn = g_ig[2 * HD + j]; }
        float aR = 0.f, aZ = 0.f, aN = 0.f;
#pragma unroll
        for (int q = 0; q < 8; q++) {
            float4 h4 = sH0[lane + 32 * q];
            aR = fmaf(h4.x, wr[q].x, fmaf(h4.y, wr[q].y, fmaf(h4.z, wr[q].z, fmaf(h4.w, wr[q].w, aR))));
            aZ = fmaf(h4.x, wz[q].x, fmaf(h4.y, wz[q].y, fmaf(h4.z, wz[q].z, fmaf(h4.w, wz[q].w, aZ))));
            aN = fmaf(h4.x, wn[q].x, fmaf(h4.y, wn[q].y, fmaf(h4.z, wn[q].z, fmaf(h4.w, wn[q].w, aN))));
        }
#pragma unroll
        for (int off = 16; off; off >>= 1) {
            aR += __shfl_xor_sync(0xffffffffu, aR, off);
            aZ += __shfl_xor_sync(0xffffffffu, aZ, off);
            aN += __shfl_xor_sync(0xffffffffu, aN, off);
        }
        if (lane == 0) {
            float rv = sigmoidf_(ir + aR);
            float uv = sigmoidf_(iz + aZ);
            float nv = tanhf(inn + rv * (aN + bnj));
            float hin = sH[0][j];
            store_state(0, j, nv + uv * (hin - nv), out);
        }
        __syncthreads();
    }
    {
        const int beg = g_off[0], end = g_off[1];
        for (int r = beg + lane; r < end; r += 32) {
            const int t = g_order[r];
            if (t == 0 && s0 == 0) continue;
            const float* igt = g_ig + (size_t)t * (3 * HD);
            float rv = sigmoidf_(igt[j]);
            float uv = sigmoidf_(igt[HD + j]);
            float nv = tanhf(igt[2 * HD + j] + rv * bnj);
            store_state(t, j, nv - uv * nv, out);
        }
    }
    grid_bar(barp, (++epoch) * SCAN_BLOCKS);

    for (int k = 1; k < kmax; k++) {
        const int beg = g_off[k], end = g_off[k + 1];
        int r = beg;
        int tA = g_order[r];
        float4 nxtA = __ldcg((const float4*)(g_states + (size_t)(tA - 1) * HD) + tid);
        int tB = (r + 1 < end) ? g_order[r + 1] : -1;
        float4 nxtB = make_float4(0.f, 0.f, 0.f, 0.f);
        if (tB >= 0) nxtB = __ldcg((const float4*)(g_states + (size_t)(tB - 1) * HD) + tid);

        while (r < end) {
            const int curA = tA, curB = tB;
            sH0s[tid] = nxtA;
            if (curB >= 0) sH1s[tid] = nxtB;
            __syncthreads();

            const int rn = r + 2;
            if (rn < end) {
                tA = g_order[rn];
                nxtA = __ldcg((const float4*)(g_states + (size_t)(tA - 1) * HD) + tid);
            }
            if (rn + 1 < end) {
                tB = g_order[rn + 1];
                nxtB = __ldcg((const float4*)(g_states + (size_t)(tB - 1) * HD) + tid);
            } else {
                tB = -1;
            }

            float irA = 0.f, izA = 0.f, inA = 0.f, irB = 0.f, izB = 0.f, inB = 0.f;
            if (lane == 0) {
                const float* iga = g_ig + (size_t)curA * (3 * HD);
                irA = iga[j]; izA = iga[HD + j]; inA = iga[2 * HD + j];
                if (curB >= 0) {
                    const float* igb = g_ig + (size_t)curB * (3 * HD);
                    irB = igb[j]; izB = igb[HD + j]; inB = igb[2 * HD + j];
                }
            }

            float aR = 0.f, aZ = 0.f, aN = 0.f, bR = 0.f, bZ = 0.f, bN = 0.f;
#pragma unroll
            for (int q = 0; q < 8; q++) {
                const int c = lane + 32 * q;
                float4 hA = sH0[c];
                float4 hB = sH1[c];
                float4 r4v = wr[q], z4v = wz[q], n4v = wn[q];
                aR = fmaf(hA.x, r4v.x, fmaf(hA.y, r4v.y, fmaf(hA.z, r4v.z, fmaf(hA.w, r4v.w, aR))));
                bR = fmaf(hB.x, r4v.x, fmaf(hB.y, r4v.y, fmaf(hB.z, r4v.z, fmaf(hB.w, r4v.w, bR))));
                aZ = fmaf(hA.x, z4v.x, fmaf(hA.y, z4v.y, fmaf(hA.z, z4v.z, fmaf(hA.w, z4v.w, aZ))));
                bZ = fmaf(hB.x, z4v.x, fmaf(hB.y, z4v.y, fmaf(hB.z, z4v.z, fmaf(hB.w, z4v.w, bZ))));
                aN = fmaf(hA.x, n4v.x, fmaf(hA.y, n4v.y, fmaf(hA.z, n4v.z, fmaf(hA.w, n4v.w, aN))));
                bN = fmaf(hB.x, n4v.x, fmaf(hB.y, n4v.y, fmaf(hB.z, n4v.z, fmaf(hB.w, n4v.w, bN))));
            }
#pragma unroll
            for (int off = 16; off; off >>= 1) {
                aR += __shfl_xor_sync(0xffffffffu, aR, off);
                aZ += __shfl_xor_sync(0xffffffffu, aZ, off);
                aN += __shfl_xor_sync(0xffffffffu, aN, off);
                bR += __shfl_xor_sync(0xffffffffu, bR, off);
                bZ += __shfl_xor_sync(0xffffffffu, bZ, off);
                bN += __shfl_xor_sync(0xffffffffu, bN, off);
            }
            if (lane == 0) {
                {
                    float rv = sigmoidf_(irA + aR);
                    float uv = sigmoidf_(izA + aZ);
                    float nv = tanhf(inA + rv * (aN + bnj));
                    float hin = sH[0][j];
                    store_state(curA, j, nv + uv * (hin - nv), out);
                }
                if (curB >= 0) {
                    float rv = sigmoidf_(irB + bR);
                    float uv = sigmoidf_(izB + bZ);
                    float nv = tanhf(inB + rv * (bN + bnj));
                    float hin = sH[1][j];
                    store_state(curB, j, nv + uv * (hin - nv), out);
                }
            }
            __syncthreads();
            r = rn;
        }
        grid_bar(barp, (++epoch) * SCAN_BLOCKS);
    }
}

// ---------------- launch ----------------
extern "C" void kernel_launch(void* const* d_in, const int* in_sizes, int n_in,
                              void* d_out, int out_size) {
    (void)in_sizes; (void)n_in;
    const float* x      = (const float*)d_in[0];
    const float* state  = (const float*)d_in[1];
    const int*   start  = (const int*)d_in[2];
    const float* pre_wm = (const float*)d_in[4];
    const float* pre_ws = (const float*)d_in[5];
    const float* pre_bm = (const float*)d_in[6];
    const float* pre_bs = (const float*)d_in[7];
    const float* wih    = (const float*)d_in[8];
    const float* whh    = (const float*)d_in[9];
    const float* gru_b  = (const float*)d_in[10];
    const float* gru_bn = (const float*)d_in[11];
    const float* p1_wm  = (const float*)d_in[12];
    const float* p1_ws  = (const float*)d_in[13];
    const float* p1_bm  = (const float*)d_in[14];
    const float* p1_bs  = (const float*)d_in[15];
    const float* p2_wm  = (const float*)d_in[16];
    const float* p2_ws  = (const float*)d_in[17];
    const float* p2_bm  = (const float*)d_in[18];
    const float* p2_bs  = (const float*)d_in[19];
    const float* p3_wm  = (const float*)d_in[20];
    const float* p3_ws  = (const float*)d_in[21];
    const float* p3_bm  = (const float*)d_in[22];
    const float* p3_bs  = (const float*)d_in[23];
    float* out = (float*)d_out;
    (void)out_size;

    unsigned nk[8][2];
    for (int i = 0; i < 8; i++) {
        unsigned a = 0u, b = (unsigned)i;
        tf_block(0u, 7u, a, b);
        nk[i][0] = a; nk[i][1] = b;
    }

    float *preB, *p1B, *p2B, *p3W, *p3B, *ig, *states, *y2;
    __half *xh, *xl, *preWh, *preWl, *wihh, *wihl, *p1Wh, *p1Wl, *p2Wh, *p2Wl;
    __half *zh, *zl, *sth, *stl, *y1h, *y1l;
    cudaGetSymbolAddress((void**)&preB, g_preB);
    cudaGetSymbolAddress((void**)&p1B, g_p1B);
    cudaGetSymbolAddress((void**)&p2B, g_p2B);
    cudaGetSymbolAddress((void**)&p3W, g_p3W);
    cudaGetSymbolAddress((void**)&p3B, g_p3B);
    cudaGetSymbolAddress((void**)&ig, g_ig);
    cudaGetSymbolAddress((void**)&states, g_states);
    cudaGetSymbolAddress((void**)&y2, g_y2);
    cudaGetSymbolAddress((void**)&xh, g_xh);
    cudaGetSymbolAddress((void**)&xl, g_xl);
    cudaGetSymbolAddress((void**)&preWh, g_preWh);
    cudaGetSymbolAddress((void**)&preWl, g_preWl);
    cudaGetSymbolAddress((void**)&wihh, g_wihh);
    cudaGetSymbolAddress((void**)&wihl, g_wihl);
    cudaGetSymbolAddress((void**)&p1Wh, g_p1Wh);
    cudaGetSymbolAddress((void**)&p1Wl, g_p1Wl);
    cudaGetSymbolAddress((void**)&p2Wh, g_p2Wh);
    cudaGetSymbolAddress((void**)&p2Wl, g_p2Wl);
    cudaGetSymbolAddress((void**)&zh, g_zh);
    cudaGetSymbolAddress((void**)&zl, g_zl);
    cudaGetSymbolAddress((void**)&sth, g_sth);
    cudaGetSymbolAddress((void**)&stl, g_stl);
    cudaGetSymbolAddress((void**)&y1h, g_y1h);
    cudaGetSymbolAddress((void**)&y1l, g_y1l);

    cudaFuncSetAttribute(mma_gemm_kernel, cudaFuncAttributeMaxDynamicSharedMemorySize,
                         MMA_SMEM_BYTES);

    // persistent side stream + events (created once; graph capture bakes dependencies)
    static cudaStream_t sB = nullptr;
    static cudaEvent_t evFork, evPre, evWih, evPrep, evP1, evP2, evP3;
    if (sB == nullptr) {
        cudaStreamCreateWithFlags(&sB, cudaStreamNonBlocking);
        cudaEventCreateWithFlags(&evFork, cudaEventDisableTiming);
        cudaEventCreateWithFlags(&evPre, cudaEventDisableTiming);
        cudaEventCreateWithFlags(&evWih, cudaEventDisableTiming);
        cudaEventCreateWithFlags(&evPrep, cudaEventDisableTiming);
        cudaEventCreateWithFlags(&evP1, cudaEventDisableTiming);
        cudaEventCreateWithFlags(&evP2, cudaEventDisableTiming);
        cudaEventCreateWithFlags(&evP3, cudaEventDisableTiming);
    }

    // fork side stream from main stream
    cudaEventRecord(evFork, 0);
    cudaStreamWaitEvent(sB, evFork, 0);

    // main #1: x split
    conv_split_kernel<<<(T_STEPS * OBS / 4 + 255) / 256, 256>>>(x, xh, xl, T_STEPS * OBS / 4);
    // side #2,#3: pre noise
    { int n = MLPD * OBS; gen_noisy_w_kernel<<<(n + 255) / 256, 256, 0, sB>>>(pre_wm, pre_ws, preWh, preWl, n, nk[0][0], nk[0][1]); }
    { int n = MLPD;       gen_noisy_kernel<<<(n + 255) / 256, 256, 0, sB>>>(pre_bm, pre_bs, preB, n, nk[1][0], nk[1][1]); }
    cudaEventRecord(evPre, sB);

    // main #4: GEMM1 (PROFILED by ncu -s 5 -c 1, empirically my launch #4)
    cudaStreamWaitEvent(0, evPre, 0);
    mma_gemm_kernel<<<dim3(MLPD / 128, T_STEPS / 128), 256, MMA_SMEM_BYTES>>>(
        xh, xl, preWh, preWl, preB, nullptr, zh, zl, T_STEPS, MLPD, OBS, 1, 1);

    // side: wih split (overlaps GEMM1)
    conv_split_kernel<<<(3 * HD * MLPD / 4 + 255) / 256, 256, 0, sB>>>(wih, wihh, wihl, 3 * HD * MLPD / 4);
    cudaEventRecord(evWih, sB);
    // side: prep (overlaps GEMM1/2)
    prep_kernel<<<1, 1024, 0, sB>>>(start);
    cudaEventRecord(evPrep, sB);

    // main: GEMM2
    cudaStreamWaitEvent(0, evWih, 0);
    mma_gemm_kernel<<<dim3(3 * HD / 128, T_STEPS / 128), 256, MMA_SMEM_BYTES>>>(
        zh, zl, wihh, wihl, gru_b, ig, nullptr, nullptr, T_STEPS, 3 * HD, MLPD, 0, 0);

    // side: p1/p2/p3 noise (overlaps GEMM2 + scan)
    { int n = MLPD * HD;   gen_noisy_w_kernel<<<(n + 255) / 256, 256, 0, sB>>>(p1_wm, p1_ws, p1Wh, p1Wl, n, nk[2][0], nk[2][1]); }
    { int n = MLPD;        gen_noisy_kernel<<<(n + 255) / 256, 256, 0, sB>>>(p1_bm, p1_bs, p1B, n, nk[3][0], nk[3][1]); }
    cudaEventRecord(evP1, sB);
    { int n = MLPD * MLPD; gen_noisy_w_kernel<<<(n + 255) / 256, 256, 0, sB>>>(p2_wm, p2_ws, p2Wh, p2Wl, n, nk[4][0], nk[4][1]); }
    { int n = MLPD;        gen_noisy_kernel<<<(n + 255) / 256, 256, 0, sB>>>(p2_bm, p2_bs, p2B, n, nk[5][0], nk[5][1]); }
    cudaEventRecord(evP2, sB);
    { int n = ACTD * MLPD; gen_noisy_kernel<<<(n + 255) / 256, 256, 0, sB>>>(p3_wm, p3_ws, p3W, n, nk[6][0], nk[6][1]); }
    { int n = ACTD;        gen_noisy_kernel<<<(n + 255) / 256, 256, 0, sB>>>(p3_bm, p3_bs, p3B, n, nk[7][0], nk[7][1]); }
    cudaEventRecord(evP3, sB);

    // main: scan
    cudaStreamWaitEvent(0, evPrep, 0);
    scan_kernel<<<SCAN_BLOCKS, 256>>>(whh, gru_bn, start, state, out);

    // main: GEMM3
    cudaStreamWaitEvent(0, evP1, 0);
    mma_gemm_kernel<<<dim3(MLPD / 128, T_STEPS / 128), 256, MMA_SMEM_BYTES>>>(
        sth, stl, p1Wh, p1Wl, p1B, nullptr, y1h, y1l, T_STEPS, MLPD, HD, 1, 1);

    // main: GEMM4
    cudaStreamWaitEvent(0, evP2, 0);
    mma_gemm_kernel<<<dim3(MLPD / 128, T_STEPS / 128), 256, MMA_SMEM_BYTES>>>(
        y1h, y1l, p2Wh, p2Wl, p2B, y2, nullptr, nullptr, T_STEPS, MLPD, MLPD, 1, 0);

    // main: final layer -> d_out[0 : 2048*16]  (joins side stream via evP3)
    cudaStreamWaitEvent(0, evP3, 0);
    sgemm64_kernel<<<dim3(1, T_STEPS / 64), 256>>>(y2, p3W, p3B, out, T_STEPS, ACTD, MLPD);
}